// round 7
// baseline (speedup 1.0000x reference)
#include <cuda_runtime.h>
#include <cuda_bf16.h>
#include <cstdint>

// Problem constants
#define BB 2
#define SS 2048
#define HH 16
#define HD 128
#define HID 2048
#define FF 8192
#define NTOK 4096

typedef __nv_bfloat16 bf16;

// ---------------- scratch (device globals; no allocation allowed) ----------
__device__ float g_att[(size_t)NTOK * HID];
__device__ float g_rope[SS * 16 * 2];
__device__ bf16 g_ln1h[(size_t)NTOK * HID];
__device__ bf16 g_ln1l[(size_t)NTOK * HID];
__device__ bf16 g_ln2h[(size_t)NTOK * HID];
__device__ bf16 g_ln2l[(size_t)NTOK * HID];
__device__ bf16 g_ctxh[(size_t)NTOK * HID];
__device__ bf16 g_ctxl[(size_t)NTOK * HID];
__device__ bf16 g_fch[(size_t)NTOK * FF];
__device__ bf16 g_fcl[(size_t)NTOK * FF];
__device__ bf16 g_Qh[(size_t)NTOK * HID];
__device__ bf16 g_Ql[(size_t)NTOK * HID];
__device__ bf16 g_Kh[(size_t)NTOK * HID];
__device__ bf16 g_Kl[(size_t)NTOK * HID];
__device__ bf16 g_Vh[(size_t)NTOK * HID];
__device__ bf16 g_Vl[(size_t)NTOK * HID];
__device__ bf16 g_wqkvh[(size_t)3 * HID * HID];
__device__ bf16 g_wqkvl[(size_t)3 * HID * HID];
__device__ bf16 g_woh[(size_t)HID * HID];
__device__ bf16 g_wol[(size_t)HID * HID];
__device__ bf16 g_wfch[(size_t)FF * HID];
__device__ bf16 g_wfcl[(size_t)FF * HID];
__device__ bf16 g_wprojh[(size_t)HID * FF];
__device__ bf16 g_wprojl[(size_t)HID * FF];

// ---------------- helpers ----------------
__device__ __forceinline__ uint32_t smem_u32(const void* p) {
    uint32_t a;
    asm("{ .reg .u64 t; cvta.to.shared.u64 t, %1; cvt.u32.u64 %0, t; }" : "=r"(a) : "l"(p));
    return a;
}
#define CP16(dst, src) \
    asm volatile("cp.async.cg.shared.global [%0], [%1], 16;" :: "r"(dst), "l"(src) : "memory")
#define CP_COMMIT() asm volatile("cp.async.commit_group;" ::: "memory")
#define CP_WAIT1()  asm volatile("cp.async.wait_group 1;" ::: "memory")
#define CP_WAIT0()  asm volatile("cp.async.wait_group 0;" ::: "memory")

__device__ __forceinline__ void ldm_x4(uint32_t* r, uint32_t addr) {
    asm volatile("ldmatrix.sync.aligned.m8n8.x4.shared.b16 {%0,%1,%2,%3}, [%4];"
                 : "=r"(r[0]), "=r"(r[1]), "=r"(r[2]), "=r"(r[3]) : "r"(addr));
}
__device__ __forceinline__ void ldm_x4_t(uint32_t* r, uint32_t addr) {
    asm volatile("ldmatrix.sync.aligned.m8n8.x4.trans.shared.b16 {%0,%1,%2,%3}, [%4];"
                 : "=r"(r[0]), "=r"(r[1]), "=r"(r[2]), "=r"(r[3]) : "r"(addr));
}
__device__ __forceinline__ void mma_bf16(float* c, const uint32_t* a, const uint32_t* b) {
    asm volatile("mma.sync.aligned.m16n8k16.row.col.f32.bf16.bf16.f32 "
                 "{%0,%1,%2,%3},{%4,%5,%6,%7},{%8,%9},{%0,%1,%2,%3};"
                 : "+f"(c[0]), "+f"(c[1]), "+f"(c[2]), "+f"(c[3])
                 : "r"(a[0]), "r"(a[1]), "r"(a[2]), "r"(a[3]), "r"(b[0]), "r"(b[1]));
}
__device__ __forceinline__ void split_bf16(float v, bf16& h, bf16& l) {
    h = __float2bfloat16(v);
    l = __float2bfloat16(v - __bfloat162float(h));
}
__device__ __forceinline__ void packhl(float a, float b, uint32_t& hi, uint32_t& lo) {
    __nv_bfloat162 hv, lv;
    split_bf16(a, hv.x, lv.x);
    split_bf16(b, hv.y, lv.y);
    hi = *(uint32_t*)&hv;
    lo = *(uint32_t*)&lv;
}
__device__ __forceinline__ float gelu_exact(float v) {
    return 0.5f * v * (1.0f + erff(v * 0.70710678118654752f));
}

// ------- fused double layernorm -> bf16 hi/lo (+ RoPE table, blocks<128) ---
__global__ void ln_kernel(const float* __restrict__ x,
                          const float* __restrict__ g1, const float* __restrict__ b1,
                          const float* __restrict__ g2, const float* __restrict__ b2,
                          bf16* __restrict__ o1h, bf16* __restrict__ o1l,
                          bf16* __restrict__ o2h, bf16* __restrict__ o2l,
                          float* __restrict__ rtab) {
    __shared__ float redS[8];
    __shared__ float redQ[8];
    const int row = blockIdx.x;
    const int t = threadIdx.x;

    if (row < 128) {                       // fill rope table: 256 entries/block
        const int i = row * 256 + t;       // 32768 entries total
        const int s = i >> 4, fi = i & 15;
        const float inv = powf(10000.0f, -(float)fi * (1.0f / 16.0f));
        float sn, cs;
        sincosf((float)s * inv, &sn, &cs);
        rtab[i * 2]     = cs;
        rtab[i * 2 + 1] = sn;
    }

    const float* xr = x + (size_t)row * HID;
    float4 a = *(const float4*)(xr + t * 8);
    float4 b = *(const float4*)(xr + t * 8 + 4);
    float s  = a.x + a.y + a.z + a.w + b.x + b.y + b.z + b.w;
    float ss = a.x*a.x + a.y*a.y + a.z*a.z + a.w*a.w
             + b.x*b.x + b.y*b.y + b.z*b.z + b.w*b.w;
    #pragma unroll
    for (int o = 16; o; o >>= 1) {
        s  += __shfl_xor_sync(0xffffffffu, s,  o);
        ss += __shfl_xor_sync(0xffffffffu, ss, o);
    }
    if ((t & 31) == 0) { redS[t >> 5] = s; redQ[t >> 5] = ss; }
    __syncthreads();
    s = 0.f; ss = 0.f;
    #pragma unroll
    for (int i = 0; i < 8; i++) { s += redS[i]; ss += redQ[i]; }
    const float mu  = s * (1.0f / HID);
    const float var = ss * (1.0f / HID) - mu * mu;
    const float rs  = rsqrtf(var + 1e-5f);

    float vals[8] = {a.x,a.y,a.z,a.w,b.x,b.y,b.z,b.w};
    __align__(16) bf16 h1[8], l1[8], h2[8], l2[8];
    #pragma unroll
    for (int q = 0; q < 8; q++) {
        const int col = t * 8 + q;
        const float xn = (vals[q] - mu) * rs;
        split_bf16(xn * g1[col] + b1[col], h1[q], l1[q]);
        split_bf16(xn * g2[col] + b2[col], h2[q], l2[q]);
    }
    const size_t off = (size_t)row * HID + t * 8;
    *(uint4*)(o1h + off) = *(uint4*)h1;
    *(uint4*)(o1l + off) = *(uint4*)l1;
    *(uint4*)(o2h + off) = *(uint4*)h2;
    *(uint4*)(o2l + off) = *(uint4*)l2;
}

// ---------------- weight convert + transpose: W[K][N] -> T{h,l}[N][K] ------
__global__ void wconv_kernel(const float* __restrict__ W, bf16* __restrict__ Th,
                             bf16* __restrict__ Tl, int K, int N) {
    __shared__ float tile[32][33];
    const int n0 = blockIdx.x * 32, k0 = blockIdx.y * 32;
    const int tx = threadIdx.x, ty = threadIdx.y;  // 32 x 8
    #pragma unroll
    for (int i = 0; i < 4; i++)
        tile[ty + 8 * i][tx] = W[(size_t)(k0 + ty + 8 * i) * N + n0 + tx];
    __syncthreads();
    #pragma unroll
    for (int i = 0; i < 4; i++) {
        const float v = tile[tx][ty + 8 * i];
        const size_t idx = (size_t)(n0 + ty + 8 * i) * K + k0 + tx;
        bf16 h, l;
        split_bf16(v, h, l);
        Th[idx] = h; Tl[idx] = l;
    }
}

// ---------------- mma.sync bf16-split GEMM, CTA 256x128, BK=64 -------------
// 1-D grid, GROUP_M=8 swizzle for L2 locality.  M is always NTOK (Mt=16).
#define ROWP   72
#define A_ARR  36864u
#define B_ARR  18432u
#define STG_B  110592u
#define G_SMEM (2u * STG_B)

// EPI: 0 +bias->f32 | 1 gelu(+bias)->bf16 h/l | 2 +bias+add1+add2->f32
//      3 qkv: +bias, RoPE, q-scale, head-transpose -> 6 bf16 h/l arrays
template <int EPI>
__global__ void __launch_bounds__(256, 1) mma_gemm(
    const bf16* __restrict__ Ah, const bf16* __restrict__ Al,
    const bf16* __restrict__ Bh, const bf16* __restrict__ Bl,
    const float* __restrict__ bias,
    const float* __restrict__ add1, const float* __restrict__ add2,
    const float* __restrict__ rtab,
    float* __restrict__ Cf, bf16* __restrict__ Ch, bf16* __restrict__ Cl,
    bf16* __restrict__ o2h, bf16* __restrict__ o2l,
    bf16* __restrict__ o3h, bf16* __restrict__ o3l,
    int N, int K) {
    extern __shared__ char sm[];
    const uint32_t smb = smem_u32(sm);
    const int tid = threadIdx.x;
    const int lane = tid & 31;
    const int wm = (tid >> 5) & 3;     // 4 warps along M (64 rows each)
    const int wn = (tid >> 7);         // 2 warps along N (64 cols each)

    // GROUP_M=8 swizzle (Mt = 16 always, divisible by 8)
    const int Nt = N >> 7;
    const int pid = blockIdx.x;
    const int mt = (pid / (8 * Nt)) * 8 + (pid & 7);
    const int nt = (pid % (8 * Nt)) >> 3;

    const size_t arow0 = (size_t)mt * 256;
    const size_t brow0 = (size_t)nt * 128;
    const bf16* pa_h = Ah + arow0 * K;
    const bf16* pa_l = Al + arow0 * K;
    const bf16* pb_h = Bh + brow0 * K;
    const bf16* pb_l = Bl + brow0 * K;
    const int nch = K >> 6;

    const uint32_t aoff = ((wm * 64 + (lane & 15)) * ROWP + (lane >> 4) * 8) * 2;
    const uint32_t boff = ((wn * 64 + (lane & 7) + ((lane >> 4) & 1) * 8) * ROWP
                           + ((lane >> 3) & 1) * 8) * 2;

    float acc[4][8][4];
    #pragma unroll
    for (int m = 0; m < 4; m++)
        #pragma unroll
        for (int n = 0; n < 8; n++)
            #pragma unroll
            for (int q = 0; q < 4; q++) acc[m][n][q] = 0.f;

    auto load_stage = [&](int stg, int k0) {
        const uint32_t sb = smb + (uint32_t)stg * STG_B;
        #pragma unroll
        for (int i = 0; i < 8; ++i) {          // A: 2048 chunks per array
            const int id = tid + i * 256;
            const int row = id >> 3, cc = id & 7;
            const uint32_t so = (uint32_t)(row * ROWP + cc * 8) * 2;
            const size_t go = (size_t)row * K + k0 + cc * 8;
            CP16(sb + so,         pa_h + go);
            CP16(sb + A_ARR + so, pa_l + go);
        }
        #pragma unroll
        for (int i = 0; i < 4; ++i) {          // B: 1024 chunks per array
            const int id = tid + i * 256;
            const int row = id >> 3, cc = id & 7;
            const uint32_t so = (uint32_t)(row * ROWP + cc * 8) * 2;
            const size_t go = (size_t)row * K + k0 + cc * 8;
            CP16(sb + 2 * A_ARR + so,         pb_h + go);
            CP16(sb + 2 * A_ARR + B_ARR + so, pb_l + go);
        }
    };

    load_stage(0, 0);
    CP_COMMIT();

    for (int c = 0; c < nch; ++c) {
        CP_WAIT0();
        __syncthreads();
        if (c + 1 < nch) {
            load_stage((c + 1) & 1, (c + 1) << 6);
            CP_COMMIT();
        }
        const uint32_t sb = smb + (uint32_t)(c & 1) * STG_B;
        #pragma unroll
        for (int ks = 0; ks < 4; ++ks) {
            const uint32_t kb = ks * 32;       // 16 elems * 2B
            uint32_t ah[4][4], bh[4][4];
            #pragma unroll
            for (int i = 0; i < 4; ++i)
                ldm_x4(ah[i], sb + aoff + kb + i * 16 * ROWP * 2);
            #pragma unroll
            for (int t2 = 0; t2 < 4; ++t2)
                ldm_x4(bh[t2], sb + 2 * A_ARR + boff + kb + t2 * 16 * ROWP * 2);
            #pragma unroll
            for (int m = 0; m < 4; ++m)
                #pragma unroll
                for (int n = 0; n < 8; ++n)
                    mma_bf16(acc[m][n], ah[m], &bh[n >> 1][(n & 1) * 2]);
            {
                uint32_t al[4][4];
                #pragma unroll
                for (int i = 0; i < 4; ++i)
                    ldm_x4(al[i], sb + A_ARR + aoff + kb + i * 16 * ROWP * 2);
                #pragma unroll
                for (int m = 0; m < 4; ++m)
                    #pragma unroll
                    for (int n = 0; n < 8; ++n)
                        mma_bf16(acc[m][n], al[m], &bh[n >> 1][(n & 1) * 2]);
            }
            {
                uint32_t bl[4][4];
                #pragma unroll
                for (int t2 = 0; t2 < 4; ++t2)
                    ldm_x4(bl[t2], sb + 2 * A_ARR + B_ARR + boff + kb + t2 * 16 * ROWP * 2);
                #pragma unroll
                for (int m = 0; m < 4; ++m)
                    #pragma unroll
                    for (int n = 0; n < 8; ++n)
                        mma_bf16(acc[m][n], ah[m], &bl[n >> 1][(n & 1) * 2]);
            }
        }
    }

    // ---------------- epilogue ----------------
    const int row_base = mt * 256 + wm * 64;
    const int col_base = nt * 128 + wn * 64;

    if (EPI == 3) {
        const int hh2 = col_base / 384;
        const int sub0 = col_base % 384;
        const int sect = sub0 >> 7;            // 0=q 1=k 2=v
        const int dbase = sub0 & 127;
        const bool ropeW = (dbase == 0) && (sect < 2);
        const float qsc = (sect == 0) ? 0.08838834764831845f : 1.0f;
        bf16* Oh = (sect == 0) ? Ch : (sect == 1) ? o2h : o3h;
        bf16* Ol = (sect == 0) ? Cl : (sect == 1) ? o2l : o3l;
        #pragma unroll
        for (int m = 0; m < 4; ++m) {
            const int r0 = row_base + m * 16 + (lane >> 2);
            const int r1 = r0 + 8;
            const int bb2 = r0 >> 11;
            const int s0 = r0 & (SS - 1), s1 = r1 & (SS - 1);
            float v[8][4];
            #pragma unroll
            for (int n = 0; n < 8; ++n) {
                const int cc = col_base + n * 8 + (lane & 3) * 2;
                const float b0 = bias[cc], b1 = bias[cc + 1];
                v[n][0] = acc[m][n][0] + b0; v[n][1] = acc[m][n][1] + b1;
                v[n][2] = acc[m][n][2] + b0; v[n][3] = acc[m][n][3] + b1;
            }
            if (ropeW) {
                float rp[4][4];
                #pragma unroll
                for (int n = 0; n < 4; ++n) {
                    const int dl = n * 8 + (lane & 3) * 2;   // 0..30 even
                    const bool first = dl < 16;
                    const int np = first ? n + 2 : n - 2;
                    const float sign = first ? -1.0f : 1.0f;
                    const int fi0 = dl & 15, fi1 = (dl + 1) & 15;
                    const float2 c00 = *(const float2*)(rtab + (s0 * 16 + fi0) * 2);
                    const float2 c01 = *(const float2*)(rtab + (s0 * 16 + fi1) * 2);
                    const float2 c10 = *(const float2*)(rtab + (s1 * 16 + fi0) * 2);
                    const float2 c11 = *(const float2*)(rtab + (s1 * 16 + fi1) * 2);
                    rp[n][0] = v[n][0] * c00.x + sign * v[np][0] * c00.y;
                    rp[n][1] = v[n][1] * c01.x + sign * v[np][1] * c01.y;
                    rp[n][2] = v[n][2] * c10.x + sign * v[np][2] * c10.y;
                    rp[n][3] = v[n][3] * c11.x + sign * v[np][3] * c11.y;
                }
                #pragma unroll
                for (int n = 0; n < 4; ++n)
                    #pragma unroll
                    for (int q = 0; q < 4; ++q) v[n][q] = rp[n][q];
            }
            const size_t base0 = (((size_t)bb2 * HH + hh2) * SS + s0) * HD;
            const size_t base1 = (((size_t)bb2 * HH + hh2) * SS + s1) * HD;
            #pragma unroll
            for (int n = 0; n < 8; ++n) {
                const int d = dbase + n * 8 + (lane & 3) * 2;
                uint32_t hi, lo;
                packhl(v[n][0] * qsc, v[n][1] * qsc, hi, lo);
                *(uint32_t*)(Oh + base0 + d) = hi;
                *(uint32_t*)(Ol + base0 + d) = lo;
                packhl(v[n][2] * qsc, v[n][3] * qsc, hi, lo);
                *(uint32_t*)(Oh + base1 + d) = hi;
                *(uint32_t*)(Ol + base1 + d) = lo;
            }
        }
        return;
    }

    #pragma unroll
    for (int m = 0; m < 4; ++m) {
        const int r0 = row_base + m * 16 + (lane >> 2);
        #pragma unroll
        for (int n = 0; n < 8; ++n) {
            const int cc = col_base + n * 8 + (lane & 3) * 2;
            const float b0 = bias[cc], b1 = bias[cc + 1];
            float v0 = acc[m][n][0] + b0, v1 = acc[m][n][1] + b1;
            float v2 = acc[m][n][2] + b0, v3 = acc[m][n][3] + b1;
            const size_t off0 = (size_t)r0 * N + cc;
            const size_t off1 = (size_t)(r0 + 8) * N + cc;
            if (EPI == 1) {
                uint32_t hi, lo;
                packhl(gelu_exact(v0), gelu_exact(v1), hi, lo);
                *(uint32_t*)(Ch + off0) = hi;
                *(uint32_t*)(Cl + off0) = lo;
                packhl(gelu_exact(v2), gelu_exact(v3), hi, lo);
                *(uint32_t*)(Ch + off1) = hi;
                *(uint32_t*)(Cl + off1) = lo;
            } else {
                if (EPI == 2) {
                    const float2 x0 = *(const float2*)(add1 + off0);
                    const float2 y0 = *(const float2*)(add2 + off0);
                    const float2 x1 = *(const float2*)(add1 + off1);
                    const float2 y1 = *(const float2*)(add2 + off1);
                    v0 += x0.x + y0.x; v1 += x0.y + y0.y;
                    v2 += x1.x + y1.x; v3 += x1.y + y1.y;
                }
                *(float2*)(Cf + off0) = make_float2(v0, v1);
                *(float2*)(Cf + off1) = make_float2(v2, v3);
            }
        }
    }
}

// ---------------- causal flash attention via mma.sync, BQ=128 --------------
#define AST   136
#define ATILE (64 * AST * 2)
#define AQ_H  0
#define AQ_L  (2 * ATILE)
#define ASTAGE0 (4 * ATILE)
#define ASTG_B  (4 * ATILE)
#define A_SMEM  (4 * ATILE + 2 * ASTG_B)

__global__ void __launch_bounds__(256, 1) attn_mma_kernel(
    const bf16* __restrict__ Qh, const bf16* __restrict__ Ql,
    const bf16* __restrict__ Kh, const bf16* __restrict__ Kl,
    const bf16* __restrict__ Vh, const bf16* __restrict__ Vl,
    bf16* __restrict__ ctxh, bf16* __restrict__ ctxl) {
    extern __shared__ char sm[];
    const uint32_t smb = smem_u32(sm);
    const int qt = gridDim.x - 1 - blockIdx.x;
    const int bhid = blockIdx.y;
    const int b = bhid >> 4, h = bhid & 15;
    const int tid = threadIdx.x;
    const int lane = tid & 31;
    const int w = tid >> 5;

    const size_t headbase = (size_t)bhid * SS * HD;

    auto ldq = [&]() {
        const size_t gb = headbase + (size_t)qt * 128 * HD;
        #pragma unroll
        for (int i = 0; i < 8; i++) {
            const int c = tid + i * 256;
            const int row = c >> 4, ch = c & 15;
            const uint32_t so = row * (AST * 2) + ch * 16;
            const size_t go = gb + (size_t)row * HD + ch * 8;
            CP16(smb + AQ_H + so, Qh + go);
            CP16(smb + AQ_L + so, Ql + go);
        }
    };
    auto ldkv = [&](int kt, int stg) {
        const uint32_t sb = smb + ASTAGE0 + (uint32_t)stg * ASTG_B;
        const size_t gb = headbase + (size_t)kt * 64 * HD;
        #pragma unroll
        for (int i = 0; i < 4; i++) {
            const int c = tid + i * 256;
            const int row = c >> 4, ch = c & 15;
            const uint32_t so = row * (AST * 2) + ch * 16;
            const size_t go = gb + (size_t)row * HD + ch * 8;
            CP16(sb + so,             Kh + go);
            CP16(sb + ATILE + so,     Kl + go);
            CP16(sb + 2 * ATILE + so, Vh + go);
            CP16(sb + 3 * ATILE + so, Vl + go);
        }
    };

    const uint32_t qa_off = ((w * 16 + (lane & 15)) * AST + (lane >> 4) * 8) * 2;
    const int lm = lane >> 3, li = lane & 7;
    const uint32_t kb_off = (((lm >> 1) * 8 + li) * AST + (lm & 1) * 8) * 2;
    const uint32_t vb_off = (((lm & 1) * 8 + li) * AST + (lm >> 1) * 8) * 2;

    float oacc[16][4];
    #pragma unroll
    for (int t = 0; t < 16; t++)
        #pragma unroll
        for (int q = 0; q < 4; q++) oacc[t][q] = 0.f;
    float m0 = -1e30f, m1 = -1e30f, l0 = 0.f, l1 = 0.f;
    const int qrow0 = qt * 128 + w * 16 + (lane >> 2);
    const int qrow1 = qrow0 + 8;
    const int nkt = 2 * qt + 2;

    ldq();
    ldkv(0, 0);
    CP_COMMIT();

    for (int kt = 0; kt < nkt; ++kt) {
        if (kt + 1 < nkt) {
            ldkv(kt + 1, (kt + 1) & 1);
            CP_COMMIT();
            CP_WAIT1();
        } else {
            CP_WAIT0();
        }
        __syncthreads();
        const uint32_t sb = smb + ASTAGE0 + (uint32_t)(kt & 1) * ASTG_B;

        float sacc[8][4];
        #pragma unroll
        for (int j = 0; j < 8; j++)
            #pragma unroll
            for (int q = 0; q < 4; q++) sacc[j][q] = 0.f;

        #pragma unroll
        for (int ks = 0; ks < 8; ++ks) {
            uint32_t ah[4], al[4], kfh[8][2], kfl[8][2];
            ldm_x4(ah, smb + AQ_H + qa_off + ks * 32);
            ldm_x4(al, smb + AQ_L + qa_off + ks * 32);
            #pragma unroll
            for (int jp = 0; jp < 4; ++jp) {
                uint32_t r[4];
                ldm_x4(r, sb + kb_off + (jp * 16 * AST + ks * 16) * 2);
                kfh[2*jp][0] = r[0]; kfh[2*jp][1] = r[1];
                kfh[2*jp+1][0] = r[2]; kfh[2*jp+1][1] = r[3];
                ldm_x4(r, sb + ATILE + kb_off + (jp * 16 * AST + ks * 16) * 2);
                kfl[2*jp][0] = r[0]; kfl[2*jp][1] = r[1];
                kfl[2*jp+1][0] = r[2]; kfl[2*jp+1][1] = r[3];
            }
            #pragma unroll
            for (int j = 0; j < 8; ++j) mma_bf16(sacc[j], ah, kfh[j]);
            #pragma unroll
            for (int j = 0; j < 8; ++j) mma_bf16(sacc[j], al, kfh[j]);
            #pragma unroll
            for (int j = 0; j < 8; ++j) mma_bf16(sacc[j], ah, kfl[j]);
        }

        if (kt >= 2 * qt) {
            #pragma unroll
            for (int j = 0; j < 8; ++j) {
                const int c0 = kt * 64 + j * 8 + (lane & 3) * 2;
                if (c0     > qrow0) sacc[j][0] = -1e30f;
                if (c0 + 1 > qrow0) sacc[j][1] = -1e30f;
                if (c0     > qrow1) sacc[j][2] = -1e30f;
                if (c0 + 1 > qrow1) sacc[j][3] = -1e30f;
            }
        }

        float mx0 = -1e30f, mx1 = -1e30f;
        #pragma unroll
        for (int j = 0; j < 8; ++j) {
            mx0 = fmaxf(mx0, fmaxf(sacc[j][0], sacc[j][1]));
            mx1 = fmaxf(mx1, fmaxf(sacc[j][2], sacc[j][3]));
        }
        #pragma unroll
        for (int o = 1; o < 4; o <<= 1) {
            mx0 = fmaxf(mx0, __shfl_xor_sync(0xffffffffu, mx0, o));
            mx1 = fmaxf(mx1, __shfl_xor_sync(0xffffffffu, mx1, o));
        }
        const float mn0 = fmaxf(m0, mx0), mn1 = fmaxf(m1, mx1);
        const float e0 = __expf(m0 - mn0), e1 = __expf(m1 - mn1);
        m0 = mn0; m1 = mn1;
        float rs0 = 0.f, rs1 = 0.f;
        #pragma unroll
        for (int j = 0; j < 8; ++j) {
            sacc[j][0] = __expf(sacc[j][0] - mn0); rs0 += sacc[j][0];
            sacc[j][1] = __expf(sacc[j][1] - mn0); rs0 += sacc[j][1];
            sacc[j][2] = __expf(sacc[j][2] - mn1); rs1 += sacc[j][2];
            sacc[j][3] = __expf(sacc[j][3] - mn1); rs1 += sacc[j][3];
        }
        #pragma unroll
        for (int o = 1; o < 4; o <<= 1) {
            rs0 += __shfl_xor_sync(0xffffffffu, rs0, o);
            rs1 += __shfl_xor_sync(0xffffffffu, rs1, o);
        }
        l0 = l0 * e0 + rs0;
        l1 = l1 * e1 + rs1;
        #pragma unroll
        for (int t = 0; t < 16; t++) {
            oacc[t][0] *= e0; oacc[t][1] *= e0;
            oacc[t][2] *= e1; oacc[t][3] *= e1;
        }

        #pragma unroll
        for (int c = 0; c < 4; ++c) {
            uint32_t pah[4], pal[4];
            packhl(sacc[2*c][0],   sacc[2*c][1],   pah[0], pal[0]);
            packhl(sacc[2*c][2],   sacc[2*c][3],   pah[1], pal[1]);
            packhl(sacc[2*c+1][0], sacc[2*c+1][1], pah[2], pal[2]);
            packhl(sacc[2*c+1][2], sacc[2*c+1][3], pah[3], pal[3]);
            #pragma unroll
            for (int tp = 0; tp < 8; ++tp) {
                uint32_t rvh[4], rvl[4];
                ldm_x4_t(rvh, sb + 2 * ATILE + vb_off + (c * 16 * AST + tp * 16) * 2);
                ldm_x4_t(rvl, sb + 3 * ATILE + vb_off + (c * 16 * AST + tp * 16) * 2);
                mma_bf16(oacc[2*tp],   pah, &rvh[0]);
                mma_bf16(oacc[2*tp],   pal, &rvh[0]);
                mma_bf16(oacc[2*tp],   pah, &rvl[0]);
                mma_bf16(oacc[2*tp+1], pah, &rvh[2]);
                mma_bf16(oacc[2*tp+1], pal, &rvh[2]);
                mma_bf16(oacc[2*tp+1], pah, &rvl[2]);
            }
        }
        __syncthreads();
    }

    const float inv0 = 1.0f / l0, inv1 = 1.0f / l1;
    const size_t ob0 = ((size_t)b * SS + qrow0) * HID + h * HD;
    const size_t ob1 = ((size_t)b * SS + qrow1) * HID + h * HD;
    #pragma unroll
    for (int t = 0; t < 16; ++t) {
        const int d = t * 8 + (lane & 3) * 2;
        uint32_t hi, lo;
        packhl(oacc[t][0] * inv0, oacc[t][1] * inv0, hi, lo);
        *(uint32_t*)(ctxh + ob0 + d) = hi;
        *(uint32_t*)(ctxl + ob0 + d) = lo;
        packhl(oacc[t][2] * inv1, oacc[t][3] * inv1, hi, lo);
        *(uint32_t*)(ctxh + ob1 + d) = hi;
        *(uint32_t*)(ctxl + ob1 + d) = lo;
    }
}

// ---------------- launch ----------------
extern "C" void kernel_launch(void* const* d_in, const int* in_sizes, int n_in,
                              void* d_out, int out_size) {
    const float* hid   = (const float*)d_in[0];
    const float* ln1g  = (const float*)d_in[1];
    const float* ln1b  = (const float*)d_in[2];
    const float* ln2g  = (const float*)d_in[3];
    const float* ln2b  = (const float*)d_in[4];
    const float* Wqkv  = (const float*)d_in[5];
    const float* bqkv  = (const float*)d_in[6];
    const float* Wo    = (const float*)d_in[7];
    const float* bo    = (const float*)d_in[8];
    const float* Wfc   = (const float*)d_in[9];
    const float* bfc   = (const float*)d_in[10];
    const float* Wproj = (const float*)d_in[11];
    const float* bproj = (const float*)d_in[12];
    float* out = (float*)d_out;

    float *att, *rope;
    bf16 *ln1h, *ln1l, *ln2h, *ln2l, *ctxh, *ctxl, *fch, *fcl;
    bf16 *Qh, *Ql, *Kh, *Kl, *Vh, *Vl;
    bf16 *wqkvh, *wqkvl, *woh, *wol, *wfch, *wfcl, *wprojh, *wprojl;
    cudaGetSymbolAddress((void**)&att, g_att);
    cudaGetSymbolAddress((void**)&rope, g_rope);
    cudaGetSymbolAddress((void**)&ln1h, g_ln1h);
    cudaGetSymbolAddress((void**)&ln1l, g_ln1l);
    cudaGetSymbolAddress((void**)&ln2h, g_ln2h);
    cudaGetSymbolAddress((void**)&ln2l, g_ln2l);
    cudaGetSymbolAddress((void**)&ctxh, g_ctxh);
    cudaGetSymbolAddress((void**)&ctxl, g_ctxl);
    cudaGetSymbolAddress((void**)&fch, g_fch);
    cudaGetSymbolAddress((void**)&fcl, g_fcl);
    cudaGetSymbolAddress((void**)&Qh, g_Qh);
    cudaGetSymbolAddress((void**)&Ql, g_Ql);
    cudaGetSymbolAddress((void**)&Kh, g_Kh);
    cudaGetSymbolAddress((void**)&Kl, g_Kl);
    cudaGetSymbolAddress((void**)&Vh, g_Vh);
    cudaGetSymbolAddress((void**)&Vl, g_Vl);
    cudaGetSymbolAddress((void**)&wqkvh, g_wqkvh);
    cudaGetSymbolAddress((void**)&wqkvl, g_wqkvl);
    cudaGetSymbolAddress((void**)&woh, g_woh);
    cudaGetSymbolAddress((void**)&wol, g_wol);
    cudaGetSymbolAddress((void**)&wfch, g_wfch);
    cudaGetSymbolAddress((void**)&wfcl, g_wfcl);
    cudaGetSymbolAddress((void**)&wprojh, g_wprojh);
    cudaGetSymbolAddress((void**)&wprojl, g_wprojl);

    cudaFuncSetAttribute(mma_gemm<0>, cudaFuncAttributeMaxDynamicSharedMemorySize, G_SMEM);
    cudaFuncSetAttribute(mma_gemm<1>, cudaFuncAttributeMaxDynamicSharedMemorySize, G_SMEM);
    cudaFuncSetAttribute(mma_gemm<2>, cudaFuncAttributeMaxDynamicSharedMemorySize, G_SMEM);
    cudaFuncSetAttribute(mma_gemm<3>, cudaFuncAttributeMaxDynamicSharedMemorySize, G_SMEM);
    cudaFuncSetAttribute(attn_mma_kernel, cudaFuncAttributeMaxDynamicSharedMemorySize, A_SMEM);

    // [0-3] weight conversions
    wconv_kernel<<<dim3(3 * HID / 32, HID / 32), dim3(32, 8)>>>(Wqkv, wqkvh, wqkvl, HID, 3 * HID);
    wconv_kernel<<<dim3(HID / 32, HID / 32),     dim3(32, 8)>>>(Wo,   woh,   wol,   HID, HID);
    wconv_kernel<<<dim3(FF / 32, HID / 32),      dim3(32, 8)>>>(Wfc,  wfch,  wfcl,  HID, FF);
    wconv_kernel<<<dim3(HID / 32, FF / 32),      dim3(32, 8)>>>(Wproj, wprojh, wprojl, FF, HID);

    // [4] LN1 + LN2 fused + rope table
    ln_kernel<<<NTOK, 256>>>(hid, ln1g, ln1b, ln2g, ln2b, ln1h, ln1l, ln2h, ln2l, rope);

    // [5] QKV gemm + fused bias/RoPE/scale/head-transpose  (ncu captures this)
    mma_gemm<3><<<16 * (3 * HID / 128), 256, G_SMEM>>>(
        ln1h, ln1l, wqkvh, wqkvl, bqkv, nullptr, nullptr, rope,
        nullptr, Qh, Ql, Kh, Kl, Vh, Vl, 3 * HID, HID);

    // [6] causal attention (mma.sync, BQ=128) -> ctx bf16 hi/lo
    attn_mma_kernel<<<dim3(SS / 128, BB * HH), 256, A_SMEM>>>(
        Qh, Ql, Kh, Kl, Vh, Vl, ctxh, ctxl);

    // [7] attn_out = ctx @ W_o + b_o -> fp32
    mma_gemm<0><<<16 * (HID / 128), 256, G_SMEM>>>(
        ctxh, ctxl, woh, wol, bo, nullptr, nullptr, nullptr,
        att, nullptr, nullptr, nullptr, nullptr, nullptr, nullptr, HID, HID);

    // [8] fc = gelu(ln2 @ W_fc + b_fc) -> bf16 hi/lo
    mma_gemm<1><<<16 * (FF / 128), 256, G_SMEM>>>(
        ln2h, ln2l, wfch, wfcl, bfc, nullptr, nullptr, nullptr,
        nullptr, fch, fcl, nullptr, nullptr, nullptr, nullptr, FF, HID);

    // [9] out = fc @ W_proj + b_proj + attn_out + hidden
    mma_gemm<2><<<16 * (HID / 128), 256, G_SMEM>>>(
        fch, fcl, wprojh, wprojl, bproj, att, hid, nullptr,
        out, nullptr, nullptr, nullptr, nullptr, nullptr, nullptr, HID, FF);
}

// round 8
// speedup vs baseline: 1.0181x; 1.0181x over previous
#include <cuda_runtime.h>
#include <cuda_bf16.h>
#include <cstdint>

// Problem constants
#define BB 2
#define SS 2048
#define HH 16
#define HD 128
#define HID 2048
#define FF 8192
#define NTOK 4096

typedef __nv_bfloat16 bf16;

// ---------------- scratch (device globals; no allocation allowed) ----------
__device__ float g_att[(size_t)NTOK * HID];
__device__ float g_rope[SS * 16 * 2];
__device__ bf16 g_ln1h[(size_t)NTOK * HID];
__device__ bf16 g_ln1l[(size_t)NTOK * HID];
__device__ bf16 g_ln2h[(size_t)NTOK * HID];
__device__ bf16 g_ln2l[(size_t)NTOK * HID];
__device__ bf16 g_ctxh[(size_t)NTOK * HID];
__device__ bf16 g_ctxl[(size_t)NTOK * HID];
__device__ bf16 g_fch[(size_t)NTOK * FF];
__device__ bf16 g_fcl[(size_t)NTOK * FF];
__device__ bf16 g_Qh[(size_t)NTOK * HID];
__device__ bf16 g_Ql[(size_t)NTOK * HID];
__device__ bf16 g_Kh[(size_t)NTOK * HID];
__device__ bf16 g_Kl[(size_t)NTOK * HID];
__device__ bf16 g_Vh[(size_t)NTOK * HID];
__device__ bf16 g_Vl[(size_t)NTOK * HID];
__device__ bf16 g_wqkvh[(size_t)3 * HID * HID];
__device__ bf16 g_wqkvl[(size_t)3 * HID * HID];
__device__ bf16 g_woh[(size_t)HID * HID];
__device__ bf16 g_wol[(size_t)HID * HID];
__device__ bf16 g_wfch[(size_t)FF * HID];
__device__ bf16 g_wfcl[(size_t)FF * HID];
__device__ bf16 g_wprojh[(size_t)HID * FF];
__device__ bf16 g_wprojl[(size_t)HID * FF];

// ---------------- helpers ----------------
__device__ __forceinline__ uint32_t smem_u32(const void* p) {
    uint32_t a;
    asm("{ .reg .u64 t; cvta.to.shared.u64 t, %1; cvt.u32.u64 %0, t; }" : "=r"(a) : "l"(p));
    return a;
}
#define CP16(dst, src) \
    asm volatile("cp.async.cg.shared.global [%0], [%1], 16;" :: "r"(dst), "l"(src) : "memory")
#define CP_COMMIT() asm volatile("cp.async.commit_group;" ::: "memory")
#define CP_WAIT1()  asm volatile("cp.async.wait_group 1;" ::: "memory")
#define CP_WAIT0()  asm volatile("cp.async.wait_group 0;" ::: "memory")

__device__ __forceinline__ void ldm_x4(uint32_t* r, uint32_t addr) {
    asm volatile("ldmatrix.sync.aligned.m8n8.x4.shared.b16 {%0,%1,%2,%3}, [%4];"
                 : "=r"(r[0]), "=r"(r[1]), "=r"(r[2]), "=r"(r[3]) : "r"(addr));
}
__device__ __forceinline__ void ldm_x4_t(uint32_t* r, uint32_t addr) {
    asm volatile("ldmatrix.sync.aligned.m8n8.x4.trans.shared.b16 {%0,%1,%2,%3}, [%4];"
                 : "=r"(r[0]), "=r"(r[1]), "=r"(r[2]), "=r"(r[3]) : "r"(addr));
}
__device__ __forceinline__ void mma_bf16(float* c, const uint32_t* a, const uint32_t* b) {
    asm volatile("mma.sync.aligned.m16n8k16.row.col.f32.bf16.bf16.f32 "
                 "{%0,%1,%2,%3},{%4,%5,%6,%7},{%8,%9},{%0,%1,%2,%3};"
                 : "+f"(c[0]), "+f"(c[1]), "+f"(c[2]), "+f"(c[3])
                 : "r"(a[0]), "r"(a[1]), "r"(a[2]), "r"(a[3]), "r"(b[0]), "r"(b[1]));
}
__device__ __forceinline__ void split_bf16(float v, bf16& h, bf16& l) {
    h = __float2bfloat16(v);
    l = __float2bfloat16(v - __bfloat162float(h));
}
__device__ __forceinline__ void packhl(float a, float b, uint32_t& hi, uint32_t& lo) {
    __nv_bfloat162 hv, lv;
    split_bf16(a, hv.x, lv.x);
    split_bf16(b, hv.y, lv.y);
    hi = *(uint32_t*)&hv;
    lo = *(uint32_t*)&lv;
}
__device__ __forceinline__ float gelu_exact(float v) {
    return 0.5f * v * (1.0f + erff(v * 0.70710678118654752f));
}

// ------- fused double layernorm -> bf16 hi/lo (+ RoPE table, blocks<128) ---
__global__ void ln_kernel(const float* __restrict__ x,
                          const float* __restrict__ g1, const float* __restrict__ b1,
                          const float* __restrict__ g2, const float* __restrict__ b2,
                          bf16* __restrict__ o1h, bf16* __restrict__ o1l,
                          bf16* __restrict__ o2h, bf16* __restrict__ o2l,
                          float* __restrict__ rtab) {
    __shared__ float redS[8];
    __shared__ float redQ[8];
    const int row = blockIdx.x;
    const int t = threadIdx.x;

    if (row < 128) {                       // fill rope table: 256 entries/block
        const int i = row * 256 + t;       // 32768 entries total
        const int s = i >> 4, fi = i & 15;
        const float inv = powf(10000.0f, -(float)fi * (1.0f / 16.0f));
        float sn, cs;
        sincosf((float)s * inv, &sn, &cs);
        rtab[i * 2]     = cs;
        rtab[i * 2 + 1] = sn;
    }

    const float* xr = x + (size_t)row * HID;
    float4 a = *(const float4*)(xr + t * 8);
    float4 b = *(const float4*)(xr + t * 8 + 4);
    float s  = a.x + a.y + a.z + a.w + b.x + b.y + b.z + b.w;
    float ss = a.x*a.x + a.y*a.y + a.z*a.z + a.w*a.w
             + b.x*b.x + b.y*b.y + b.z*b.z + b.w*b.w;
    #pragma unroll
    for (int o = 16; o; o >>= 1) {
        s  += __shfl_xor_sync(0xffffffffu, s,  o);
        ss += __shfl_xor_sync(0xffffffffu, ss, o);
    }
    if ((t & 31) == 0) { redS[t >> 5] = s; redQ[t >> 5] = ss; }
    __syncthreads();
    s = 0.f; ss = 0.f;
    #pragma unroll
    for (int i = 0; i < 8; i++) { s += redS[i]; ss += redQ[i]; }
    const float mu  = s * (1.0f / HID);
    const float var = ss * (1.0f / HID) - mu * mu;
    const float rs  = rsqrtf(var + 1e-5f);

    float vals[8] = {a.x,a.y,a.z,a.w,b.x,b.y,b.z,b.w};
    __align__(16) bf16 h1[8], l1[8], h2[8], l2[8];
    #pragma unroll
    for (int q = 0; q < 8; q++) {
        const int col = t * 8 + q;
        const float xn = (vals[q] - mu) * rs;
        split_bf16(xn * g1[col] + b1[col], h1[q], l1[q]);
        split_bf16(xn * g2[col] + b2[col], h2[q], l2[q]);
    }
    const size_t off = (size_t)row * HID + t * 8;
    *(uint4*)(o1h + off) = *(uint4*)h1;
    *(uint4*)(o1l + off) = *(uint4*)l1;
    *(uint4*)(o2h + off) = *(uint4*)h2;
    *(uint4*)(o2l + off) = *(uint4*)l2;
}

// ---------------- weight convert + transpose: W[K][N] -> T{h,l}[N][K] ------
__global__ void wconv_kernel(const float* __restrict__ W, bf16* __restrict__ Th,
                             bf16* __restrict__ Tl, int K, int N) {
    __shared__ float tile[32][33];
    const int n0 = blockIdx.x * 32, k0 = blockIdx.y * 32;
    const int tx = threadIdx.x, ty = threadIdx.y;  // 32 x 8
    #pragma unroll
    for (int i = 0; i < 4; i++)
        tile[ty + 8 * i][tx] = W[(size_t)(k0 + ty + 8 * i) * N + n0 + tx];
    __syncthreads();
    #pragma unroll
    for (int i = 0; i < 4; i++) {
        const float v = tile[tx][ty + 8 * i];
        const size_t idx = (size_t)(n0 + ty + 8 * i) * K + k0 + tx;
        bf16 h, l;
        split_bf16(v, h, l);
        Th[idx] = h; Tl[idx] = l;
    }
}

// ------------ mma.sync bf16-split GEMM, CTA 256x128, BK=64, 512 thr --------
// 16 warps (4 M x 4 N), warp tile 64x32.  1-D grid, GROUP_M=8 swizzle.
#define ROWP   72
#define A_ARR  36864u
#define B_ARR  18432u
#define STG_B  110592u
#define G_SMEM (2u * STG_B)

// EPI: 0 +bias->f32 | 1 gelu(+bias)->bf16 h/l | 2 +bias+add1+add2->f32
//      3 qkv: +bias, RoPE, q-scale, head-transpose -> 6 bf16 h/l arrays
template <int EPI>
__global__ void __launch_bounds__(512, 1) mma_gemm(
    const bf16* __restrict__ Ah, const bf16* __restrict__ Al,
    const bf16* __restrict__ Bh, const bf16* __restrict__ Bl,
    const float* __restrict__ bias,
    const float* __restrict__ add1, const float* __restrict__ add2,
    const float* __restrict__ rtab,
    float* __restrict__ Cf, bf16* __restrict__ Ch, bf16* __restrict__ Cl,
    bf16* __restrict__ o2h, bf16* __restrict__ o2l,
    bf16* __restrict__ o3h, bf16* __restrict__ o3l,
    int N, int K) {
    extern __shared__ char sm[];
    const uint32_t smb = smem_u32(sm);
    const int tid = threadIdx.x;
    const int lane = tid & 31;
    const int warp = tid >> 5;
    const int wm = warp >> 2;          // 4 warps along M (64 rows each)
    const int wn = warp & 3;           // 4 warps along N (32 cols each)

    // GROUP_M=8 swizzle (Mt = 16 always, divisible by 8)
    const int Nt = N >> 7;
    const int pid = blockIdx.x;
    const int mt = (pid / (8 * Nt)) * 8 + (pid & 7);
    const int nt = (pid % (8 * Nt)) >> 3;

    const size_t arow0 = (size_t)mt * 256;
    const size_t brow0 = (size_t)nt * 128;
    const bf16* pa_h = Ah + arow0 * K;
    const bf16* pa_l = Al + arow0 * K;
    const bf16* pb_h = Bh + brow0 * K;
    const bf16* pb_l = Bl + brow0 * K;
    const int nch = K >> 6;

    const uint32_t aoff = ((wm * 64 + (lane & 15)) * ROWP + (lane >> 4) * 8) * 2;
    const uint32_t boff = ((wn * 32 + (lane & 7) + ((lane >> 4) & 1) * 8) * ROWP
                           + ((lane >> 3) & 1) * 8) * 2;

    float acc[4][4][4];
    #pragma unroll
    for (int m = 0; m < 4; m++)
        #pragma unroll
        for (int n = 0; n < 4; n++)
            #pragma unroll
            for (int q = 0; q < 4; q++) acc[m][n][q] = 0.f;

    auto load_stage = [&](int stg, int k0) {
        const uint32_t sb = smb + (uint32_t)stg * STG_B;
        #pragma unroll
        for (int i = 0; i < 4; ++i) {          // A: 2048 chunks per array
            const int id = tid + i * 512;
            const int row = id >> 3, cc = id & 7;
            const uint32_t so = (uint32_t)(row * ROWP + cc * 8) * 2;
            const size_t go = (size_t)row * K + k0 + cc * 8;
            CP16(sb + so,         pa_h + go);
            CP16(sb + A_ARR + so, pa_l + go);
        }
        #pragma unroll
        for (int i = 0; i < 2; ++i) {          // B: 1024 chunks per array
            const int id = tid + i * 512;
            const int row = id >> 3, cc = id & 7;
            const uint32_t so = (uint32_t)(row * ROWP + cc * 8) * 2;
            const size_t go = (size_t)row * K + k0 + cc * 8;
            CP16(sb + 2 * A_ARR + so,         pb_h + go);
            CP16(sb + 2 * A_ARR + B_ARR + so, pb_l + go);
        }
    };

    load_stage(0, 0);
    CP_COMMIT();

    for (int c = 0; c < nch; ++c) {
        CP_WAIT0();
        __syncthreads();
        if (c + 1 < nch) {
            load_stage((c + 1) & 1, (c + 1) << 6);
            CP_COMMIT();
        }
        const uint32_t sb = smb + (uint32_t)(c & 1) * STG_B;
        #pragma unroll
        for (int ks = 0; ks < 4; ++ks) {
            const uint32_t kb = ks * 32;       // 16 elems * 2B
            uint32_t ah[4][4], bh[2][4];
            #pragma unroll
            for (int i = 0; i < 4; ++i)
                ldm_x4(ah[i], sb + aoff + kb + i * 16 * ROWP * 2);
            #pragma unroll
            for (int t2 = 0; t2 < 2; ++t2)
                ldm_x4(bh[t2], sb + 2 * A_ARR + boff + kb + t2 * 16 * ROWP * 2);
            #pragma unroll
            for (int m = 0; m < 4; ++m)
                #pragma unroll
                for (int n = 0; n < 4; ++n)
                    mma_bf16(acc[m][n], ah[m], &bh[n >> 1][(n & 1) * 2]);
            {
                uint32_t al[4][4];
                #pragma unroll
                for (int i = 0; i < 4; ++i)
                    ldm_x4(al[i], sb + A_ARR + aoff + kb + i * 16 * ROWP * 2);
                #pragma unroll
                for (int m = 0; m < 4; ++m)
                    #pragma unroll
                    for (int n = 0; n < 4; ++n)
                        mma_bf16(acc[m][n], al[m], &bh[n >> 1][(n & 1) * 2]);
            }
            {
                uint32_t bl[2][4];
                #pragma unroll
                for (int t2 = 0; t2 < 2; ++t2)
                    ldm_x4(bl[t2], sb + 2 * A_ARR + B_ARR + boff + kb + t2 * 16 * ROWP * 2);
                #pragma unroll
                for (int m = 0; m < 4; ++m)
                    #pragma unroll
                    for (int n = 0; n < 4; ++n)
                        mma_bf16(acc[m][n], ah[m], &bl[n >> 1][(n & 1) * 2]);
            }
        }
    }

    // ---------------- epilogue ----------------
    const int row_base = mt * 256 + wm * 64;
    const int col_base = nt * 128 + wn * 32;

    if (EPI == 3) {
        const int hh2 = col_base / 384;
        const int sub0 = col_base % 384;
        const int sect = sub0 >> 7;            // 0=q 1=k 2=v
        const int dbase = sub0 & 127;
        const bool ropeW = (dbase == 0) && (sect < 2);
        const float qsc = (sect == 0) ? 0.08838834764831845f : 1.0f;
        bf16* Oh = (sect == 0) ? Ch : (sect == 1) ? o2h : o3h;
        bf16* Ol = (sect == 0) ? Cl : (sect == 1) ? o2l : o3l;
        #pragma unroll
        for (int m = 0; m < 4; ++m) {
            const int r0 = row_base + m * 16 + (lane >> 2);
            const int r1 = r0 + 8;
            const int bb2 = r0 >> 11;
            const int s0 = r0 & (SS - 1), s1 = r1 & (SS - 1);
            float v[4][4];
            #pragma unroll
            for (int n = 0; n < 4; ++n) {
                const int cc = col_base + n * 8 + (lane & 3) * 2;
                const float b0 = bias[cc], b1 = bias[cc + 1];
                v[n][0] = acc[m][n][0] + b0; v[n][1] = acc[m][n][1] + b1;
                v[n][2] = acc[m][n][2] + b0; v[n][3] = acc[m][n][3] + b1;
            }
            if (ropeW) {
                float rp[4][4];
                #pragma unroll
                for (int n = 0; n < 4; ++n) {
                    const int dl = n * 8 + (lane & 3) * 2;   // 0..30 even
                    const bool first = dl < 16;
                    const int np = first ? n + 2 : n - 2;
                    const float sign = first ? -1.0f : 1.0f;
                    const int fi0 = dl & 15, fi1 = (dl + 1) & 15;
                    const float2 c00 = *(const float2*)(rtab + (s0 * 16 + fi0) * 2);
                    const float2 c01 = *(const float2*)(rtab + (s0 * 16 + fi1) * 2);
                    const float2 c10 = *(const float2*)(rtab + (s1 * 16 + fi0) * 2);
                    const float2 c11 = *(const float2*)(rtab + (s1 * 16 + fi1) * 2);
                    rp[n][0] = v[n][0] * c00.x + sign * v[np][0] * c00.y;
                    rp[n][1] = v[n][1] * c01.x + sign * v[np][1] * c01.y;
                    rp[n][2] = v[n][2] * c10.x + sign * v[np][2] * c10.y;
                    rp[n][3] = v[n][3] * c11.x + sign * v[np][3] * c11.y;
                }
                #pragma unroll
                for (int n = 0; n < 4; ++n)
                    #pragma unroll
                    for (int q = 0; q < 4; ++q) v[n][q] = rp[n][q];
            }
            const size_t base0 = (((size_t)bb2 * HH + hh2) * SS + s0) * HD;
            const size_t base1 = (((size_t)bb2 * HH + hh2) * SS + s1) * HD;
            #pragma unroll
            for (int n = 0; n < 4; ++n) {
                const int d = dbase + n * 8 + (lane & 3) * 2;
                uint32_t hi, lo;
                packhl(v[n][0] * qsc, v[n][1] * qsc, hi, lo);
                *(uint32_t*)(Oh + base0 + d) = hi;
                *(uint32_t*)(Ol + base0 + d) = lo;
                packhl(v[n][2] * qsc, v[n][3] * qsc, hi, lo);
                *(uint32_t*)(Oh + base1 + d) = hi;
                *(uint32_t*)(Ol + base1 + d) = lo;
            }
        }
        return;
    }

    #pragma unroll
    for (int m = 0; m < 4; ++m) {
        const int r0 = row_base + m * 16 + (lane >> 2);
        #pragma unroll
        for (int n = 0; n < 4; ++n) {
            const int cc = col_base + n * 8 + (lane & 3) * 2;
            const float b0 = bias[cc], b1 = bias[cc + 1];
            float v0 = acc[m][n][0] + b0, v1 = acc[m][n][1] + b1;
            float v2 = acc[m][n][2] + b0, v3 = acc[m][n][3] + b1;
            const size_t off0 = (size_t)r0 * N + cc;
            const size_t off1 = (size_t)(r0 + 8) * N + cc;
            if (EPI == 1) {
                uint32_t hi, lo;
                packhl(gelu_exact(v0), gelu_exact(v1), hi, lo);
                *(uint32_t*)(Ch + off0) = hi;
                *(uint32_t*)(Cl + off0) = lo;
                packhl(gelu_exact(v2), gelu_exact(v3), hi, lo);
                *(uint32_t*)(Ch + off1) = hi;
                *(uint32_t*)(Cl + off1) = lo;
            } else {
                if (EPI == 2) {
                    const float2 x0 = *(const float2*)(add1 + off0);
                    const float2 y0 = *(const float2*)(add2 + off0);
                    const float2 x1 = *(const float2*)(add1 + off1);
                    const float2 y1 = *(const float2*)(add2 + off1);
                    v0 += x0.x + y0.x; v1 += x0.y + y0.y;
                    v2 += x1.x + y1.x; v3 += x1.y + y1.y;
                }
                *(float2*)(Cf + off0) = make_float2(v0, v1);
                *(float2*)(Cf + off1) = make_float2(v2, v3);
            }
        }
    }
}

// ---------------- causal flash attention via mma.sync, BQ=128 --------------
#define AST   136
#define ATILE (64 * AST * 2)
#define AQ_H  0
#define AQ_L  (2 * ATILE)
#define ASTAGE0 (4 * ATILE)
#define ASTG_B  (4 * ATILE)
#define A_SMEM  (4 * ATILE + 2 * ASTG_B)

__global__ void __launch_bounds__(256, 1) attn_mma_kernel(
    const bf16* __restrict__ Qh, const bf16* __restrict__ Ql,
    const bf16* __restrict__ Kh, const bf16* __restrict__ Kl,
    const bf16* __restrict__ Vh, const bf16* __restrict__ Vl,
    bf16* __restrict__ ctxh, bf16* __restrict__ ctxl) {
    extern __shared__ char sm[];
    const uint32_t smb = smem_u32(sm);
    const int qt = gridDim.x - 1 - blockIdx.x;
    const int bhid = blockIdx.y;
    const int b = bhid >> 4, h = bhid & 15;
    const int tid = threadIdx.x;
    const int lane = tid & 31;
    const int w = tid >> 5;

    const size_t headbase = (size_t)bhid * SS * HD;

    auto ldq = [&]() {
        const size_t gb = headbase + (size_t)qt * 128 * HD;
        #pragma unroll
        for (int i = 0; i < 8; i++) {
            const int c = tid + i * 256;
            const int row = c >> 4, ch = c & 15;
            const uint32_t so = row * (AST * 2) + ch * 16;
            const size_t go = gb + (size_t)row * HD + ch * 8;
            CP16(smb + AQ_H + so, Qh + go);
            CP16(smb + AQ_L + so, Ql + go);
        }
    };
    auto ldkv = [&](int kt, int stg) {
        const uint32_t sb = smb + ASTAGE0 + (uint32_t)stg * ASTG_B;
        const size_t gb = headbase + (size_t)kt * 64 * HD;
        #pragma unroll
        for (int i = 0; i < 4; i++) {
            const int c = tid + i * 256;
            const int row = c >> 4, ch = c & 15;
            const uint32_t so = row * (AST * 2) + ch * 16;
            const size_t go = gb + (size_t)row * HD + ch * 8;
            CP16(sb + so,             Kh + go);
            CP16(sb + ATILE + so,     Kl + go);
            CP16(sb + 2 * ATILE + so, Vh + go);
            CP16(sb + 3 * ATILE + so, Vl + go);
        }
    };

    const uint32_t qa_off = ((w * 16 + (lane & 15)) * AST + (lane >> 4) * 8) * 2;
    const int lm = lane >> 3, li = lane & 7;
    const uint32_t kb_off = (((lm >> 1) * 8 + li) * AST + (lm & 1) * 8) * 2;
    const uint32_t vb_off = (((lm & 1) * 8 + li) * AST + (lm >> 1) * 8) * 2;

    float oacc[16][4];
    #pragma unroll
    for (int t = 0; t < 16; t++)
        #pragma unroll
        for (int q = 0; q < 4; q++) oacc[t][q] = 0.f;
    float m0 = -1e30f, m1 = -1e30f, l0 = 0.f, l1 = 0.f;
    const int qrow0 = qt * 128 + w * 16 + (lane >> 2);
    const int qrow1 = qrow0 + 8;
    const int nkt = 2 * qt + 2;

    ldq();
    ldkv(0, 0);
    CP_COMMIT();

    for (int kt = 0; kt < nkt; ++kt) {
        if (kt + 1 < nkt) {
            ldkv(kt + 1, (kt + 1) & 1);
            CP_COMMIT();
            CP_WAIT1();
        } else {
            CP_WAIT0();
        }
        __syncthreads();
        const uint32_t sb = smb + ASTAGE0 + (uint32_t)(kt & 1) * ASTG_B;

        float sacc[8][4];
        #pragma unroll
        for (int j = 0; j < 8; j++)
            #pragma unroll
            for (int q = 0; q < 4; q++) sacc[j][q] = 0.f;

        #pragma unroll
        for (int ks = 0; ks < 8; ++ks) {
            uint32_t ah[4], al[4], kfh[8][2], kfl[8][2];
            ldm_x4(ah, smb + AQ_H + qa_off + ks * 32);
            ldm_x4(al, smb + AQ_L + qa_off + ks * 32);
            #pragma unroll
            for (int jp = 0; jp < 4; ++jp) {
                uint32_t r[4];
                ldm_x4(r, sb + kb_off + (jp * 16 * AST + ks * 16) * 2);
                kfh[2*jp][0] = r[0]; kfh[2*jp][1] = r[1];
                kfh[2*jp+1][0] = r[2]; kfh[2*jp+1][1] = r[3];
                ldm_x4(r, sb + ATILE + kb_off + (jp * 16 * AST + ks * 16) * 2);
                kfl[2*jp][0] = r[0]; kfl[2*jp][1] = r[1];
                kfl[2*jp+1][0] = r[2]; kfl[2*jp+1][1] = r[3];
            }
            #pragma unroll
            for (int j = 0; j < 8; ++j) mma_bf16(sacc[j], ah, kfh[j]);
            #pragma unroll
            for (int j = 0; j < 8; ++j) mma_bf16(sacc[j], al, kfh[j]);
            #pragma unroll
            for (int j = 0; j < 8; ++j) mma_bf16(sacc[j], ah, kfl[j]);
        }

        if (kt >= 2 * qt) {
            #pragma unroll
            for (int j = 0; j < 8; ++j) {
                const int c0 = kt * 64 + j * 8 + (lane & 3) * 2;
                if (c0     > qrow0) sacc[j][0] = -1e30f;
                if (c0 + 1 > qrow0) sacc[j][1] = -1e30f;
                if (c0     > qrow1) sacc[j][2] = -1e30f;
                if (c0 + 1 > qrow1) sacc[j][3] = -1e30f;
            }
        }

        float mx0 = -1e30f, mx1 = -1e30f;
        #pragma unroll
        for (int j = 0; j < 8; ++j) {
            mx0 = fmaxf(mx0, fmaxf(sacc[j][0], sacc[j][1]));
            mx1 = fmaxf(mx1, fmaxf(sacc[j][2], sacc[j][3]));
        }
        #pragma unroll
        for (int o = 1; o < 4; o <<= 1) {
            mx0 = fmaxf(mx0, __shfl_xor_sync(0xffffffffu, mx0, o));
            mx1 = fmaxf(mx1, __shfl_xor_sync(0xffffffffu, mx1, o));
        }
        const float mn0 = fmaxf(m0, mx0), mn1 = fmaxf(m1, mx1);
        const float e0 = __expf(m0 - mn0), e1 = __expf(m1 - mn1);
        m0 = mn0; m1 = mn1;
        float rs0 = 0.f, rs1 = 0.f;
        #pragma unroll
        for (int j = 0; j < 8; ++j) {
            sacc[j][0] = __expf(sacc[j][0] - mn0); rs0 += sacc[j][0];
            sacc[j][1] = __expf(sacc[j][1] - mn0); rs0 += sacc[j][1];
            sacc[j][2] = __expf(sacc[j][2] - mn1); rs1 += sacc[j][2];
            sacc[j][3] = __expf(sacc[j][3] - mn1); rs1 += sacc[j][3];
        }
        #pragma unroll
        for (int o = 1; o < 4; o <<= 1) {
            rs0 += __shfl_xor_sync(0xffffffffu, rs0, o);
            rs1 += __shfl_xor_sync(0xffffffffu, rs1, o);
        }
        l0 = l0 * e0 + rs0;
        l1 = l1 * e1 + rs1;
        #pragma unroll
        for (int t = 0; t < 16; t++) {
            oacc[t][0] *= e0; oacc[t][1] *= e0;
            oacc[t][2] *= e1; oacc[t][3] *= e1;
        }

        #pragma unroll
        for (int c = 0; c < 4; ++c) {
            uint32_t pah[4], pal[4];
            packhl(sacc[2*c][0],   sacc[2*c][1],   pah[0], pal[0]);
            packhl(sacc[2*c][2],   sacc[2*c][3],   pah[1], pal[1]);
            packhl(sacc[2*c+1][0], sacc[2*c+1][1], pah[2], pal[2]);
            packhl(sacc[2*c+1][2], sacc[2*c+1][3], pah[3], pal[3]);
            #pragma unroll
            for (int tp = 0; tp < 8; ++tp) {
                uint32_t rvh[4], rvl[4];
                ldm_x4_t(rvh, sb + 2 * ATILE + vb_off + (c * 16 * AST + tp * 16) * 2);
                ldm_x4_t(rvl, sb + 3 * ATILE + vb_off + (c * 16 * AST + tp * 16) * 2);
                mma_bf16(oacc[2*tp],   pah, &rvh[0]);
                mma_bf16(oacc[2*tp],   pal, &rvh[0]);
                mma_bf16(oacc[2*tp],   pah, &rvl[0]);
                mma_bf16(oacc[2*tp+1], pah, &rvh[2]);
                mma_bf16(oacc[2*tp+1], pal, &rvh[2]);
                mma_bf16(oacc[2*tp+1], pah, &rvl[2]);
            }
        }
        __syncthreads();
    }

    const float inv0 = 1.0f / l0, inv1 = 1.0f / l1;
    const size_t ob0 = ((size_t)b * SS + qrow0) * HID + h * HD;
    const size_t ob1 = ((size_t)b * SS + qrow1) * HID + h * HD;
    #pragma unroll
    for (int t = 0; t < 16; ++t) {
        const int d = t * 8 + (lane & 3) * 2;
        uint32_t hi, lo;
        packhl(oacc[t][0] * inv0, oacc[t][1] * inv0, hi, lo);
        *(uint32_t*)(ctxh + ob0 + d) = hi;
        *(uint32_t*)(ctxl + ob0 + d) = lo;
        packhl(oacc[t][2] * inv1, oacc[t][3] * inv1, hi, lo);
        *(uint32_t*)(ctxh + ob1 + d) = hi;
        *(uint32_t*)(ctxl + ob1 + d) = lo;
    }
}

// ---------------- launch ----------------
extern "C" void kernel_launch(void* const* d_in, const int* in_sizes, int n_in,
                              void* d_out, int out_size) {
    const float* hid   = (const float*)d_in[0];
    const float* ln1g  = (const float*)d_in[1];
    const float* ln1b  = (const float*)d_in[2];
    const float* ln2g  = (const float*)d_in[3];
    const float* ln2b  = (const float*)d_in[4];
    const float* Wqkv  = (const float*)d_in[5];
    const float* bqkv  = (const float*)d_in[6];
    const float* Wo    = (const float*)d_in[7];
    const float* bo    = (const float*)d_in[8];
    const float* Wfc   = (const float*)d_in[9];
    const float* bfc   = (const float*)d_in[10];
    const float* Wproj = (const float*)d_in[11];
    const float* bproj = (const float*)d_in[12];
    float* out = (float*)d_out;

    float *att, *rope;
    bf16 *ln1h, *ln1l, *ln2h, *ln2l, *ctxh, *ctxl, *fch, *fcl;
    bf16 *Qh, *Ql, *Kh, *Kl, *Vh, *Vl;
    bf16 *wqkvh, *wqkvl, *woh, *wol, *wfch, *wfcl, *wprojh, *wprojl;
    cudaGetSymbolAddress((void**)&att, g_att);
    cudaGetSymbolAddress((void**)&rope, g_rope);
    cudaGetSymbolAddress((void**)&ln1h, g_ln1h);
    cudaGetSymbolAddress((void**)&ln1l, g_ln1l);
    cudaGetSymbolAddress((void**)&ln2h, g_ln2h);
    cudaGetSymbolAddress((void**)&ln2l, g_ln2l);
    cudaGetSymbolAddress((void**)&ctxh, g_ctxh);
    cudaGetSymbolAddress((void**)&ctxl, g_ctxl);
    cudaGetSymbolAddress((void**)&fch, g_fch);
    cudaGetSymbolAddress((void**)&fcl, g_fcl);
    cudaGetSymbolAddress((void**)&Qh, g_Qh);
    cudaGetSymbolAddress((void**)&Ql, g_Ql);
    cudaGetSymbolAddress((void**)&Kh, g_Kh);
    cudaGetSymbolAddress((void**)&Kl, g_Kl);
    cudaGetSymbolAddress((void**)&Vh, g_Vh);
    cudaGetSymbolAddress((void**)&Vl, g_Vl);
    cudaGetSymbolAddress((void**)&wqkvh, g_wqkvh);
    cudaGetSymbolAddress((void**)&wqkvl, g_wqkvl);
    cudaGetSymbolAddress((void**)&woh, g_woh);
    cudaGetSymbolAddress((void**)&wol, g_wol);
    cudaGetSymbolAddress((void**)&wfch, g_wfch);
    cudaGetSymbolAddress((void**)&wfcl, g_wfcl);
    cudaGetSymbolAddress((void**)&wprojh, g_wprojh);
    cudaGetSymbolAddress((void**)&wprojl, g_wprojl);

    cudaFuncSetAttribute(mma_gemm<0>, cudaFuncAttributeMaxDynamicSharedMemorySize, G_SMEM);
    cudaFuncSetAttribute(mma_gemm<1>, cudaFuncAttributeMaxDynamicSharedMemorySize, G_SMEM);
    cudaFuncSetAttribute(mma_gemm<2>, cudaFuncAttributeMaxDynamicSharedMemorySize, G_SMEM);
    cudaFuncSetAttribute(mma_gemm<3>, cudaFuncAttributeMaxDynamicSharedMemorySize, G_SMEM);
    cudaFuncSetAttribute(attn_mma_kernel, cudaFuncAttributeMaxDynamicSharedMemorySize, A_SMEM);

    // [0-3] weight conversions
    wconv_kernel<<<dim3(3 * HID / 32, HID / 32), dim3(32, 8)>>>(Wqkv, wqkvh, wqkvl, HID, 3 * HID);
    wconv_kernel<<<dim3(HID / 32, HID / 32),     dim3(32, 8)>>>(Wo,   woh,   wol,   HID, HID);
    wconv_kernel<<<dim3(FF / 32, HID / 32),      dim3(32, 8)>>>(Wfc,  wfch,  wfcl,  HID, FF);
    wconv_kernel<<<dim3(HID / 32, FF / 32),      dim3(32, 8)>>>(Wproj, wprojh, wprojl, FF, HID);

    // [4] LN1 + LN2 fused + rope table
    ln_kernel<<<NTOK, 256>>>(hid, ln1g, ln1b, ln2g, ln2b, ln1h, ln1l, ln2h, ln2l, rope);

    // [5] QKV gemm + fused bias/RoPE/scale/head-transpose
    mma_gemm<3><<<16 * (3 * HID / 128), 512, G_SMEM>>>(
        ln1h, ln1l, wqkvh, wqkvl, bqkv, nullptr, nullptr, rope,
        nullptr, Qh, Ql, Kh, Kl, Vh, Vl, 3 * HID, HID);

    // [6] causal attention (mma.sync, BQ=128) -> ctx bf16 hi/lo
    attn_mma_kernel<<<dim3(SS / 128, BB * HH), 256, A_SMEM>>>(
        Qh, Ql, Kh, Kl, Vh, Vl, ctxh, ctxl);

    // [7] attn_out = ctx @ W_o + b_o -> fp32
    mma_gemm<0><<<16 * (HID / 128), 512, G_SMEM>>>(
        ctxh, ctxl, woh, wol, bo, nullptr, nullptr, nullptr,
        att, nullptr, nullptr, nullptr, nullptr, nullptr, nullptr, HID, HID);

    // [8] fc = gelu(ln2 @ W_fc + b_fc) -> bf16 hi/lo
    mma_gemm<1><<<16 * (FF / 128), 512, G_SMEM>>>(
        ln2h, ln2l, wfch, wfcl, bfc, nullptr, nullptr, nullptr,
        nullptr, fch, fcl, nullptr, nullptr, nullptr, nullptr, FF, HID);

    // [9] out = fc @ W_proj + b_proj + attn_out + hidden
    mma_gemm<2><<<16 * (HID / 128), 512, G_SMEM>>>(
        fch, fcl, wprojh, wprojl, bproj, att, hid, nullptr,
        out, nullptr, nullptr, nullptr, nullptr, nullptr, nullptr, HID, FF);
}

// round 9
// speedup vs baseline: 1.0612x; 1.0424x over previous
#include <cuda_runtime.h>
#include <cuda_bf16.h>
#include <cstdint>

// Problem constants
#define BB 2
#define SS 2048
#define HH 16
#define HD 128
#define HID 2048
#define FF 8192
#define NTOK 4096

typedef __nv_bfloat16 bf16;

// ---------------- scratch (device globals; no allocation allowed) ----------
__device__ float g_att[(size_t)NTOK * HID];
__device__ float g_rope[SS * 16 * 2];
__device__ bf16 g_ln1h[(size_t)NTOK * HID];
__device__ bf16 g_ln1l[(size_t)NTOK * HID];
__device__ bf16 g_ln2h[(size_t)NTOK * HID];
__device__ bf16 g_ln2l[(size_t)NTOK * HID];
__device__ bf16 g_ctxh[(size_t)NTOK * HID];
__device__ bf16 g_ctxl[(size_t)NTOK * HID];
__device__ bf16 g_fch[(size_t)NTOK * FF];
__device__ bf16 g_fcl[(size_t)NTOK * FF];
__device__ bf16 g_Qh[(size_t)NTOK * HID];
__device__ bf16 g_Ql[(size_t)NTOK * HID];
__device__ bf16 g_Kh[(size_t)NTOK * HID];
__device__ bf16 g_Kl[(size_t)NTOK * HID];
__device__ bf16 g_Vh[(size_t)NTOK * HID];
__device__ bf16 g_Vl[(size_t)NTOK * HID];
__device__ bf16 g_wqkvh[(size_t)3 * HID * HID];
__device__ bf16 g_wqkvl[(size_t)3 * HID * HID];
__device__ bf16 g_woh[(size_t)HID * HID];
__device__ bf16 g_wol[(size_t)HID * HID];
__device__ bf16 g_wfch[(size_t)FF * HID];
__device__ bf16 g_wfcl[(size_t)FF * HID];
__device__ bf16 g_wprojh[(size_t)HID * FF];
__device__ bf16 g_wprojl[(size_t)HID * FF];

// ---------------- helpers ----------------
__device__ __forceinline__ uint32_t smem_u32(const void* p) {
    uint32_t a;
    asm("{ .reg .u64 t; cvta.to.shared.u64 t, %1; cvt.u32.u64 %0, t; }" : "=r"(a) : "l"(p));
    return a;
}
#define CP16(dst, src) \
    asm volatile("cp.async.cg.shared.global [%0], [%1], 16;" :: "r"(dst), "l"(src) : "memory")
#define CP_COMMIT() asm volatile("cp.async.commit_group;" ::: "memory")
#define CP_WAIT1()  asm volatile("cp.async.wait_group 1;" ::: "memory")
#define CP_WAIT0()  asm volatile("cp.async.wait_group 0;" ::: "memory")

__device__ __forceinline__ void ldm_x4(uint32_t* r, uint32_t addr) {
    asm volatile("ldmatrix.sync.aligned.m8n8.x4.shared.b16 {%0,%1,%2,%3}, [%4];"
                 : "=r"(r[0]), "=r"(r[1]), "=r"(r[2]), "=r"(r[3]) : "r"(addr));
}
__device__ __forceinline__ void ldm_x4_t(uint32_t* r, uint32_t addr) {
    asm volatile("ldmatrix.sync.aligned.m8n8.x4.trans.shared.b16 {%0,%1,%2,%3}, [%4];"
                 : "=r"(r[0]), "=r"(r[1]), "=r"(r[2]), "=r"(r[3]) : "r"(addr));
}
__device__ __forceinline__ void mma_bf16(float* c, const uint32_t* a, const uint32_t* b) {
    asm volatile("mma.sync.aligned.m16n8k16.row.col.f32.bf16.bf16.f32 "
                 "{%0,%1,%2,%3},{%4,%5,%6,%7},{%8,%9},{%0,%1,%2,%3};"
                 : "+f"(c[0]), "+f"(c[1]), "+f"(c[2]), "+f"(c[3])
                 : "r"(a[0]), "r"(a[1]), "r"(a[2]), "r"(a[3]), "r"(b[0]), "r"(b[1]));
}
__device__ __forceinline__ void split_bf16(float v, bf16& h, bf16& l) {
    h = __float2bfloat16(v);
    l = __float2bfloat16(v - __bfloat162float(h));
}
__device__ __forceinline__ void packhl(float a, float b, uint32_t& hi, uint32_t& lo) {
    __nv_bfloat162 hv, lv;
    split_bf16(a, hv.x, lv.x);
    split_bf16(b, hv.y, lv.y);
    hi = *(uint32_t*)&hv;
    lo = *(uint32_t*)&lv;
}
__device__ __forceinline__ float gelu_exact(float v) {
    return 0.5f * v * (1.0f + erff(v * 0.70710678118654752f));
}

// ------- fused double layernorm -> bf16 hi/lo (+ RoPE table, blocks<128) ---
__global__ void ln_kernel(const float* __restrict__ x,
                          const float* __restrict__ g1, const float* __restrict__ b1,
                          const float* __restrict__ g2, const float* __restrict__ b2,
                          bf16* __restrict__ o1h, bf16* __restrict__ o1l,
                          bf16* __restrict__ o2h, bf16* __restrict__ o2l,
                          float* __restrict__ rtab) {
    __shared__ float redS[8];
    __shared__ float redQ[8];
    const int row = blockIdx.x;
    const int t = threadIdx.x;

    if (row < 128) {                       // fill rope table: 256 entries/block
        const int i = row * 256 + t;       // 32768 entries total
        const int s = i >> 4, fi = i & 15;
        const float inv = powf(10000.0f, -(float)fi * (1.0f / 16.0f));
        float sn, cs;
        sincosf((float)s * inv, &sn, &cs);
        rtab[i * 2]     = cs;
        rtab[i * 2 + 1] = sn;
    }

    const float* xr = x + (size_t)row * HID;
    float4 a = *(const float4*)(xr + t * 8);
    float4 b = *(const float4*)(xr + t * 8 + 4);
    float s  = a.x + a.y + a.z + a.w + b.x + b.y + b.z + b.w;
    float ss = a.x*a.x + a.y*a.y + a.z*a.z + a.w*a.w
             + b.x*b.x + b.y*b.y + b.z*b.z + b.w*b.w;
    #pragma unroll
    for (int o = 16; o; o >>= 1) {
        s  += __shfl_xor_sync(0xffffffffu, s,  o);
        ss += __shfl_xor_sync(0xffffffffu, ss, o);
    }
    if ((t & 31) == 0) { redS[t >> 5] = s; redQ[t >> 5] = ss; }
    __syncthreads();
    s = 0.f; ss = 0.f;
    #pragma unroll
    for (int i = 0; i < 8; i++) { s += redS[i]; ss += redQ[i]; }
    const float mu  = s * (1.0f / HID);
    const float var = ss * (1.0f / HID) - mu * mu;
    const float rs  = rsqrtf(var + 1e-5f);

    float vals[8] = {a.x,a.y,a.z,a.w,b.x,b.y,b.z,b.w};
    __align__(16) bf16 h1[8], l1[8], h2[8], l2[8];
    #pragma unroll
    for (int q = 0; q < 8; q++) {
        const int col = t * 8 + q;
        const float xn = (vals[q] - mu) * rs;
        split_bf16(xn * g1[col] + b1[col], h1[q], l1[q]);
        split_bf16(xn * g2[col] + b2[col], h2[q], l2[q]);
    }
    const size_t off = (size_t)row * HID + t * 8;
    *(uint4*)(o1h + off) = *(uint4*)h1;
    *(uint4*)(o1l + off) = *(uint4*)l1;
    *(uint4*)(o2h + off) = *(uint4*)h2;
    *(uint4*)(o2l + off) = *(uint4*)l2;
}

// ---------------- weight convert + transpose: W[K][N] -> T{h,l}[N][K] ------
__global__ void wconv_kernel(const float* __restrict__ W, bf16* __restrict__ Th,
                             bf16* __restrict__ Tl, int K, int N) {
    __shared__ float tile[32][33];
    const int n0 = blockIdx.x * 32, k0 = blockIdx.y * 32;
    const int tx = threadIdx.x, ty = threadIdx.y;  // 32 x 8
    #pragma unroll
    for (int i = 0; i < 4; i++)
        tile[ty + 8 * i][tx] = W[(size_t)(k0 + ty + 8 * i) * N + n0 + tx];
    __syncthreads();
    #pragma unroll
    for (int i = 0; i < 4; i++) {
        const float v = tile[tx][ty + 8 * i];
        const size_t idx = (size_t)(n0 + ty + 8 * i) * K + k0 + tx;
        bf16 h, l;
        split_bf16(v, h, l);
        Th[idx] = h; Tl[idx] = l;
    }
}

// ------------ mma.sync bf16-split GEMM, CTA 256x128, BK=64, 512 thr --------
#define ROWP   72
#define A_ARR  36864u
#define B_ARR  18432u
#define STG_B  110592u
#define G_SMEM (2u * STG_B)

// EPI: 0 +bias->f32 | 1 gelu(+bias)->bf16 h/l | 2 +bias+add1+add2->f32
//      3 qkv: +bias, RoPE, q-scale, head-transpose -> 6 bf16 h/l arrays
template <int EPI>
__global__ void __launch_bounds__(512, 1) mma_gemm(
    const bf16* __restrict__ Ah, const bf16* __restrict__ Al,
    const bf16* __restrict__ Bh, const bf16* __restrict__ Bl,
    const float* __restrict__ bias,
    const float* __restrict__ add1, const float* __restrict__ add2,
    const float* __restrict__ rtab,
    float* __restrict__ Cf, bf16* __restrict__ Ch, bf16* __restrict__ Cl,
    bf16* __restrict__ o2h, bf16* __restrict__ o2l,
    bf16* __restrict__ o3h, bf16* __restrict__ o3l,
    int N, int K) {
    extern __shared__ char sm[];
    const uint32_t smb = smem_u32(sm);
    const int tid = threadIdx.x;
    const int lane = tid & 31;
    const int warp = tid >> 5;
    const int wm = warp >> 2;
    const int wn = warp & 3;

    const int Nt = N >> 7;
    const int pid = blockIdx.x;
    const int mt = (pid / (8 * Nt)) * 8 + (pid & 7);
    const int nt = (pid % (8 * Nt)) >> 3;

    const size_t arow0 = (size_t)mt * 256;
    const size_t brow0 = (size_t)nt * 128;
    const bf16* pa_h = Ah + arow0 * K;
    const bf16* pa_l = Al + arow0 * K;
    const bf16* pb_h = Bh + brow0 * K;
    const bf16* pb_l = Bl + brow0 * K;
    const int nch = K >> 6;

    const uint32_t aoff = ((wm * 64 + (lane & 15)) * ROWP + (lane >> 4) * 8) * 2;
    const uint32_t boff = ((wn * 32 + (lane & 7) + ((lane >> 4) & 1) * 8) * ROWP
                           + ((lane >> 3) & 1) * 8) * 2;

    float acc[4][4][4];
    #pragma unroll
    for (int m = 0; m < 4; m++)
        #pragma unroll
        for (int n = 0; n < 4; n++)
            #pragma unroll
            for (int q = 0; q < 4; q++) acc[m][n][q] = 0.f;

    auto load_stage = [&](int stg, int k0) {
        const uint32_t sb = smb + (uint32_t)stg * STG_B;
        #pragma unroll
        for (int i = 0; i < 4; ++i) {
            const int id = tid + i * 512;
            const int row = id >> 3, cc = id & 7;
            const uint32_t so = (uint32_t)(row * ROWP + cc * 8) * 2;
            const size_t go = (size_t)row * K + k0 + cc * 8;
            CP16(sb + so,         pa_h + go);
            CP16(sb + A_ARR + so, pa_l + go);
        }
        #pragma unroll
        for (int i = 0; i < 2; ++i) {
            const int id = tid + i * 512;
            const int row = id >> 3, cc = id & 7;
            const uint32_t so = (uint32_t)(row * ROWP + cc * 8) * 2;
            const size_t go = (size_t)row * K + k0 + cc * 8;
            CP16(sb + 2 * A_ARR + so,         pb_h + go);
            CP16(sb + 2 * A_ARR + B_ARR + so, pb_l + go);
        }
    };

    load_stage(0, 0);
    CP_COMMIT();

    for (int c = 0; c < nch; ++c) {
        CP_WAIT0();
        __syncthreads();
        if (c + 1 < nch) {
            load_stage((c + 1) & 1, (c + 1) << 6);
            CP_COMMIT();
        }
        const uint32_t sb = smb + (uint32_t)(c & 1) * STG_B;
        #pragma unroll
        for (int ks = 0; ks < 4; ++ks) {
            const uint32_t kb = ks * 32;
            uint32_t ah[4][4], bh[2][4];
            #pragma unroll
            for (int i = 0; i < 4; ++i)
                ldm_x4(ah[i], sb + aoff + kb + i * 16 * ROWP * 2);
            #pragma unroll
            for (int t2 = 0; t2 < 2; ++t2)
                ldm_x4(bh[t2], sb + 2 * A_ARR + boff + kb + t2 * 16 * ROWP * 2);
            #pragma unroll
            for (int m = 0; m < 4; ++m)
                #pragma unroll
                for (int n = 0; n < 4; ++n)
                    mma_bf16(acc[m][n], ah[m], &bh[n >> 1][(n & 1) * 2]);
            {
                uint32_t al[4][4];
                #pragma unroll
                for (int i = 0; i < 4; ++i)
                    ldm_x4(al[i], sb + A_ARR + aoff + kb + i * 16 * ROWP * 2);
                #pragma unroll
                for (int m = 0; m < 4; ++m)
                    #pragma unroll
                    for (int n = 0; n < 4; ++n)
                        mma_bf16(acc[m][n], al[m], &bh[n >> 1][(n & 1) * 2]);
            }
            {
                uint32_t bl[2][4];
                #pragma unroll
                for (int t2 = 0; t2 < 2; ++t2)
                    ldm_x4(bl[t2], sb + 2 * A_ARR + B_ARR + boff + kb + t2 * 16 * ROWP * 2);
                #pragma unroll
                for (int m = 0; m < 4; ++m)
                    #pragma unroll
                    for (int n = 0; n < 4; ++n)
                        mma_bf16(acc[m][n], ah[m], &bl[n >> 1][(n & 1) * 2]);
            }
        }
    }

    // ---------------- epilogue ----------------
    const int row_base = mt * 256 + wm * 64;
    const int col_base = nt * 128 + wn * 32;

    if (EPI == 3) {
        const int hh2 = col_base / 384;
        const int sub0 = col_base % 384;
        const int sect = sub0 >> 7;
        const int dbase = sub0 & 127;
        const bool ropeW = (dbase == 0) && (sect < 2);
        const float qsc = (sect == 0) ? 0.08838834764831845f : 1.0f;
        bf16* Oh = (sect == 0) ? Ch : (sect == 1) ? o2h : o3h;
        bf16* Ol = (sect == 0) ? Cl : (sect == 1) ? o2l : o3l;
        #pragma unroll
        for (int m = 0; m < 4; ++m) {
            const int r0 = row_base + m * 16 + (lane >> 2);
            const int r1 = r0 + 8;
            const int bb2 = r0 >> 11;
            const int s0 = r0 & (SS - 1), s1 = r1 & (SS - 1);
            float v[4][4];
            #pragma unroll
            for (int n = 0; n < 4; ++n) {
                const int cc = col_base + n * 8 + (lane & 3) * 2;
                const float b0 = bias[cc], b1 = bias[cc + 1];
                v[n][0] = acc[m][n][0] + b0; v[n][1] = acc[m][n][1] + b1;
                v[n][2] = acc[m][n][2] + b0; v[n][3] = acc[m][n][3] + b1;
            }
            if (ropeW) {
                float rp[4][4];
                #pragma unroll
                for (int n = 0; n < 4; ++n) {
                    const int dl = n * 8 + (lane & 3) * 2;
                    const bool first = dl < 16;
                    const int np = first ? n + 2 : n - 2;
                    const float sign = first ? -1.0f : 1.0f;
                    const int fi0 = dl & 15, fi1 = (dl + 1) & 15;
                    const float2 c00 = *(const float2*)(rtab + (s0 * 16 + fi0) * 2);
                    const float2 c01 = *(const float2*)(rtab + (s0 * 16 + fi1) * 2);
                    const float2 c10 = *(const float2*)(rtab + (s1 * 16 + fi0) * 2);
                    const float2 c11 = *(const float2*)(rtab + (s1 * 16 + fi1) * 2);
                    rp[n][0] = v[n][0] * c00.x + sign * v[np][0] * c00.y;
                    rp[n][1] = v[n][1] * c01.x + sign * v[np][1] * c01.y;
                    rp[n][2] = v[n][2] * c10.x + sign * v[np][2] * c10.y;
                    rp[n][3] = v[n][3] * c11.x + sign * v[np][3] * c11.y;
                }
                #pragma unroll
                for (int n = 0; n < 4; ++n)
                    #pragma unroll
                    for (int q = 0; q < 4; ++q) v[n][q] = rp[n][q];
            }
            const size_t base0 = (((size_t)bb2 * HH + hh2) * SS + s0) * HD;
            const size_t base1 = (((size_t)bb2 * HH + hh2) * SS + s1) * HD;
            #pragma unroll
            for (int n = 0; n < 4; ++n) {
                const int d = dbase + n * 8 + (lane & 3) * 2;
                uint32_t hi, lo;
                packhl(v[n][0] * qsc, v[n][1] * qsc, hi, lo);
                *(uint32_t*)(Oh + base0 + d) = hi;
                *(uint32_t*)(Ol + base0 + d) = lo;
                packhl(v[n][2] * qsc, v[n][3] * qsc, hi, lo);
                *(uint32_t*)(Oh + base1 + d) = hi;
                *(uint32_t*)(Ol + base1 + d) = lo;
            }
        }
        return;
    }

    #pragma unroll
    for (int m = 0; m < 4; ++m) {
        const int r0 = row_base + m * 16 + (lane >> 2);
        #pragma unroll
        for (int n = 0; n < 4; ++n) {
            const int cc = col_base + n * 8 + (lane & 3) * 2;
            const float b0 = bias[cc], b1 = bias[cc + 1];
            float v0 = acc[m][n][0] + b0, v1 = acc[m][n][1] + b1;
            float v2 = acc[m][n][2] + b0, v3 = acc[m][n][3] + b1;
            const size_t off0 = (size_t)r0 * N + cc;
            const size_t off1 = (size_t)(r0 + 8) * N + cc;
            if (EPI == 1) {
                uint32_t hi, lo;
                packhl(gelu_exact(v0), gelu_exact(v1), hi, lo);
                *(uint32_t*)(Ch + off0) = hi;
                *(uint32_t*)(Cl + off0) = lo;
                packhl(gelu_exact(v2), gelu_exact(v3), hi, lo);
                *(uint32_t*)(Ch + off1) = hi;
                *(uint32_t*)(Cl + off1) = lo;
            } else {
                if (EPI == 2) {
                    const float2 x0 = *(const float2*)(add1 + off0);
                    const float2 y0 = *(const float2*)(add2 + off0);
                    const float2 x1 = *(const float2*)(add1 + off1);
                    const float2 y1 = *(const float2*)(add2 + off1);
                    v0 += x0.x + y0.x; v1 += x0.y + y0.y;
                    v2 += x1.x + y1.x; v3 += x1.y + y1.y;
                }
                *(float2*)(Cf + off0) = make_float2(v0, v1);
                *(float2*)(Cf + off1) = make_float2(v2, v3);
            }
        }
    }
}

// ---------------- causal flash attention via mma.sync, BQ=128 --------------
#define AST   136
#define ATILE (64 * AST * 2)
#define AQ_H  0
#define AQ_L  (2 * ATILE)
#define ASTAGE0 (4 * ATILE)
#define ASTG_B  (4 * ATILE)
#define A_SMEM  (4 * ATILE + 2 * ASTG_B)

__global__ void __launch_bounds__(256, 1) attn_mma_kernel(
    const bf16* __restrict__ Qh, const bf16* __restrict__ Ql,
    const bf16* __restrict__ Kh, const bf16* __restrict__ Kl,
    const bf16* __restrict__ Vh, const bf16* __restrict__ Vl,
    bf16* __restrict__ ctxh, bf16* __restrict__ ctxl) {
    extern __shared__ char sm[];
    const uint32_t smb = smem_u32(sm);
    const int qt = gridDim.x - 1 - blockIdx.x;
    const int bhid = blockIdx.y;
    const int b = bhid >> 4, h = bhid & 15;
    const int tid = threadIdx.x;
    const int lane = tid & 31;
    const int w = tid >> 5;

    const size_t headbase = (size_t)bhid * SS * HD;

    auto ldq = [&]() {
        const size_t gb = headbase + (size_t)qt * 128 * HD;
        #pragma unroll
        for (int i = 0; i < 8; i++) {
            const int c = tid + i * 256;
            const int row = c >> 4, ch = c & 15;
            const uint32_t so = row * (AST * 2) + ch * 16;
            const size_t go = gb + (size_t)row * HD + ch * 8;
            CP16(smb + AQ_H + so, Qh + go);
            CP16(smb + AQ_L + so, Ql + go);
        }
    };
    auto ldkv = [&](int kt, int stg) {
        const uint32_t sb = smb + ASTAGE0 + (uint32_t)stg * ASTG_B;
        const size_t gb = headbase + (size_t)kt * 64 * HD;
        #pragma unroll
        for (int i = 0; i < 4; i++) {
            const int c = tid + i * 256;
            const int row = c >> 4, ch = c & 15;
            const uint32_t so = row * (AST * 2) + ch * 16;
            const size_t go = gb + (size_t)row * HD + ch * 8;
            CP16(sb + so,             Kh + go);
            CP16(sb + ATILE + so,     Kl + go);
            CP16(sb + 2 * ATILE + so, Vh + go);
            CP16(sb + 3 * ATILE + so, Vl + go);
        }
    };

    const uint32_t qa_off = ((w * 16 + (lane & 15)) * AST + (lane >> 4) * 8) * 2;
    const int lm = lane >> 3, li = lane & 7;
    const uint32_t kb_off = (((lm >> 1) * 8 + li) * AST + (lm & 1) * 8) * 2;
    const uint32_t vb_off = (((lm & 1) * 8 + li) * AST + (lm >> 1) * 8) * 2;

    float oacc[16][4];
    #pragma unroll
    for (int t = 0; t < 16; t++)
        #pragma unroll
        for (int q = 0; q < 4; q++) oacc[t][q] = 0.f;
    float m0 = -1e30f, m1 = -1e30f, l0 = 0.f, l1 = 0.f;
    const int qrow0 = qt * 128 + w * 16 + (lane >> 2);
    const int qrow1 = qrow0 + 8;
    const int nkt = 2 * qt + 2;

    ldq();
    ldkv(0, 0);
    CP_COMMIT();

    for (int kt = 0; kt < nkt; ++kt) {
        if (kt + 1 < nkt) {
            ldkv(kt + 1, (kt + 1) & 1);
            CP_COMMIT();
            CP_WAIT1();
        } else {
            CP_WAIT0();
        }
        __syncthreads();
        const uint32_t sb = smb + ASTAGE0 + (uint32_t)(kt & 1) * ASTG_B;

        float sacc[8][4];
        #pragma unroll
        for (int j = 0; j < 8; j++)
            #pragma unroll
            for (int q = 0; q < 4; q++) sacc[j][q] = 0.f;

        #pragma unroll
        for (int ks = 0; ks < 8; ++ks) {
            uint32_t ah[4], al[4], kfh[8][2], kfl[8][2];
            ldm_x4(ah, smb + AQ_H + qa_off + ks * 32);
            ldm_x4(al, smb + AQ_L + qa_off + ks * 32);
            #pragma unroll
            for (int jp = 0; jp < 4; ++jp) {
                uint32_t r[4];
                ldm_x4(r, sb + kb_off + (jp * 16 * AST + ks * 16) * 2);
                kfh[2*jp][0] = r[0]; kfh[2*jp][1] = r[1];
                kfh[2*jp+1][0] = r[2]; kfh[2*jp+1][1] = r[3];
                ldm_x4(r, sb + ATILE + kb_off + (jp * 16 * AST + ks * 16) * 2);
                kfl[2*jp][0] = r[0]; kfl[2*jp][1] = r[1];
                kfl[2*jp+1][0] = r[2]; kfl[2*jp+1][1] = r[3];
            }
            #pragma unroll
            for (int j = 0; j < 8; ++j) mma_bf16(sacc[j], ah, kfh[j]);
            #pragma unroll
            for (int j = 0; j < 8; ++j) mma_bf16(sacc[j], al, kfh[j]);
            #pragma unroll
            for (int j = 0; j < 8; ++j) mma_bf16(sacc[j], ah, kfl[j]);
        }

        if (kt >= 2 * qt) {
            #pragma unroll
            for (int j = 0; j < 8; ++j) {
                const int c0 = kt * 64 + j * 8 + (lane & 3) * 2;
                if (c0     > qrow0) sacc[j][0] = -1e30f;
                if (c0 + 1 > qrow0) sacc[j][1] = -1e30f;
                if (c0     > qrow1) sacc[j][2] = -1e30f;
                if (c0 + 1 > qrow1) sacc[j][3] = -1e30f;
            }
        }

        float mx0 = -1e30f, mx1 = -1e30f;
        #pragma unroll
        for (int j = 0; j < 8; ++j) {
            mx0 = fmaxf(mx0, fmaxf(sacc[j][0], sacc[j][1]));
            mx1 = fmaxf(mx1, fmaxf(sacc[j][2], sacc[j][3]));
        }
        #pragma unroll
        for (int o = 1; o < 4; o <<= 1) {
            mx0 = fmaxf(mx0, __shfl_xor_sync(0xffffffffu, mx0, o));
            mx1 = fmaxf(mx1, __shfl_xor_sync(0xffffffffu, mx1, o));
        }
        const float mn0 = fmaxf(m0, mx0), mn1 = fmaxf(m1, mx1);
        const float e0 = __expf(m0 - mn0), e1 = __expf(m1 - mn1);
        m0 = mn0; m1 = mn1;
        float rs0 = 0.f, rs1 = 0.f;
        #pragma unroll
        for (int j = 0; j < 8; ++j) {
            sacc[j][0] = __expf(sacc[j][0] - mn0); rs0 += sacc[j][0];
            sacc[j][1] = __expf(sacc[j][1] - mn0); rs0 += sacc[j][1];
            sacc[j][2] = __expf(sacc[j][2] - mn1); rs1 += sacc[j][2];
            sacc[j][3] = __expf(sacc[j][3] - mn1); rs1 += sacc[j][3];
        }
        #pragma unroll
        for (int o = 1; o < 4; o <<= 1) {
            rs0 += __shfl_xor_sync(0xffffffffu, rs0, o);
            rs1 += __shfl_xor_sync(0xffffffffu, rs1, o);
        }
        l0 = l0 * e0 + rs0;
        l1 = l1 * e1 + rs1;
        #pragma unroll
        for (int t = 0; t < 16; t++) {
            oacc[t][0] *= e0; oacc[t][1] *= e0;
            oacc[t][2] *= e1; oacc[t][3] *= e1;
        }

        #pragma unroll
        for (int c = 0; c < 4; ++c) {
            uint32_t pah[4], pal[4];
            packhl(sacc[2*c][0],   sacc[2*c][1],   pah[0], pal[0]);
            packhl(sacc[2*c][2],   sacc[2*c][3],   pah[1], pal[1]);
            packhl(sacc[2*c+1][0], sacc[2*c+1][1], pah[2], pal[2]);
            packhl(sacc[2*c+1][2], sacc[2*c+1][3], pah[3], pal[3]);
            #pragma unroll
            for (int tp = 0; tp < 8; ++tp) {
                uint32_t rvh[4], rvl[4];
                ldm_x4_t(rvh, sb + 2 * ATILE + vb_off + (c * 16 * AST + tp * 16) * 2);
                ldm_x4_t(rvl, sb + 3 * ATILE + vb_off + (c * 16 * AST + tp * 16) * 2);
                mma_bf16(oacc[2*tp],   pah, &rvh[0]);
                mma_bf16(oacc[2*tp],   pal, &rvh[0]);
                mma_bf16(oacc[2*tp],   pah, &rvl[0]);
                mma_bf16(oacc[2*tp+1], pah, &rvh[2]);
                mma_bf16(oacc[2*tp+1], pal, &rvh[2]);
                mma_bf16(oacc[2*tp+1], pah, &rvl[2]);
            }
        }
        __syncthreads();
    }

    const float inv0 = 1.0f / l0, inv1 = 1.0f / l1;
    const size_t ob0 = ((size_t)b * SS + qrow0) * HID + h * HD;
    const size_t ob1 = ((size_t)b * SS + qrow1) * HID + h * HD;
    #pragma unroll
    for (int t = 0; t < 16; ++t) {
        const int d = t * 8 + (lane & 3) * 2;
        uint32_t hi, lo;
        packhl(oacc[t][0] * inv0, oacc[t][1] * inv0, hi, lo);
        *(uint32_t*)(ctxh + ob0 + d) = hi;
        *(uint32_t*)(ctxl + ob0 + d) = lo;
        packhl(oacc[t][2] * inv1, oacc[t][3] * inv1, hi, lo);
        *(uint32_t*)(ctxh + ob1 + d) = hi;
        *(uint32_t*)(ctxl + ob1 + d) = lo;
    }
}

// ---------------- launch (stream fork/join for overlap) ----------------
extern "C" void kernel_launch(void* const* d_in, const int* in_sizes, int n_in,
                              void* d_out, int out_size) {
    const float* hid   = (const float*)d_in[0];
    const float* ln1g  = (const float*)d_in[1];
    const float* ln1b  = (const float*)d_in[2];
    const float* ln2g  = (const float*)d_in[3];
    const float* ln2b  = (const float*)d_in[4];
    const float* Wqkv  = (const float*)d_in[5];
    const float* bqkv  = (const float*)d_in[6];
    const float* Wo    = (const float*)d_in[7];
    const float* bo    = (const float*)d_in[8];
    const float* Wfc   = (const float*)d_in[9];
    const float* bfc   = (const float*)d_in[10];
    const float* Wproj = (const float*)d_in[11];
    const float* bproj = (const float*)d_in[12];
    float* out = (float*)d_out;

    float *att, *rope;
    bf16 *ln1h, *ln1l, *ln2h, *ln2l, *ctxh, *ctxl, *fch, *fcl;
    bf16 *Qh, *Ql, *Kh, *Kl, *Vh, *Vl;
    bf16 *wqkvh, *wqkvl, *woh, *wol, *wfch, *wfcl, *wprojh, *wprojl;
    cudaGetSymbolAddress((void**)&att, g_att);
    cudaGetSymbolAddress((void**)&rope, g_rope);
    cudaGetSymbolAddress((void**)&ln1h, g_ln1h);
    cudaGetSymbolAddress((void**)&ln1l, g_ln1l);
    cudaGetSymbolAddress((void**)&ln2h, g_ln2h);
    cudaGetSymbolAddress((void**)&ln2l, g_ln2l);
    cudaGetSymbolAddress((void**)&ctxh, g_ctxh);
    cudaGetSymbolAddress((void**)&ctxl, g_ctxl);
    cudaGetSymbolAddress((void**)&fch, g_fch);
    cudaGetSymbolAddress((void**)&fcl, g_fcl);
    cudaGetSymbolAddress((void**)&Qh, g_Qh);
    cudaGetSymbolAddress((void**)&Ql, g_Ql);
    cudaGetSymbolAddress((void**)&Kh, g_Kh);
    cudaGetSymbolAddress((void**)&Kl, g_Kl);
    cudaGetSymbolAddress((void**)&Vh, g_Vh);
    cudaGetSymbolAddress((void**)&Vl, g_Vl);
    cudaGetSymbolAddress((void**)&wqkvh, g_wqkvh);
    cudaGetSymbolAddress((void**)&wqkvl, g_wqkvl);
    cudaGetSymbolAddress((void**)&woh, g_woh);
    cudaGetSymbolAddress((void**)&wol, g_wol);
    cudaGetSymbolAddress((void**)&wfch, g_wfch);
    cudaGetSymbolAddress((void**)&wfcl, g_wfcl);
    cudaGetSymbolAddress((void**)&wprojh, g_wprojh);
    cudaGetSymbolAddress((void**)&wprojl, g_wprojl);

    cudaFuncSetAttribute(mma_gemm<0>, cudaFuncAttributeMaxDynamicSharedMemorySize, G_SMEM);
    cudaFuncSetAttribute(mma_gemm<1>, cudaFuncAttributeMaxDynamicSharedMemorySize, G_SMEM);
    cudaFuncSetAttribute(mma_gemm<2>, cudaFuncAttributeMaxDynamicSharedMemorySize, G_SMEM);
    cudaFuncSetAttribute(mma_gemm<3>, cudaFuncAttributeMaxDynamicSharedMemorySize, G_SMEM);
    cudaFuncSetAttribute(attn_mma_kernel, cudaFuncAttributeMaxDynamicSharedMemorySize, A_SMEM);

    // lazily-created side streams + events (host resources only; no device mem)
    static cudaStream_t sB = nullptr, sC = nullptr;
    static cudaEvent_t evRoot = nullptr, evLn = nullptr, evFC = nullptr, evC = nullptr;
    if (!sB) {
        cudaStreamCreateWithFlags(&sB, cudaStreamNonBlocking);
        cudaStreamCreateWithFlags(&sC, cudaStreamNonBlocking);
        cudaEventCreateWithFlags(&evRoot, cudaEventDisableTiming);
        cudaEventCreateWithFlags(&evLn,   cudaEventDisableTiming);
        cudaEventCreateWithFlags(&evFC,   cudaEventDisableTiming);
        cudaEventCreateWithFlags(&evC,    cudaEventDisableTiming);
    }

    // fork side streams from the origin stream
    cudaEventRecord(evRoot, 0);
    cudaStreamWaitEvent(sB, evRoot, 0);
    cudaStreamWaitEvent(sC, evRoot, 0);

    // --- stream C: Wo + Wproj weight conversions ---
    wconv_kernel<<<dim3(HID / 32, HID / 32), dim3(32, 8), 0, sC>>>(Wo, woh, wol, HID, HID);
    wconv_kernel<<<dim3(HID / 32, FF / 32),  dim3(32, 8), 0, sC>>>(Wproj, wprojh, wprojl, FF, HID);
    cudaEventRecord(evC, sC);

    // --- stream B: Wfc conversion, then FC gemm after ln ---
    wconv_kernel<<<dim3(FF / 32, HID / 32), dim3(32, 8), 0, sB>>>(Wfc, wfch, wfcl, HID, FF);

    // --- origin: ln (+ rope table), Wqkv conversion, QKV gemm, attention ---
    ln_kernel<<<NTOK, 256>>>(hid, ln1g, ln1b, ln2g, ln2b, ln1h, ln1l, ln2h, ln2l, rope);
    cudaEventRecord(evLn, 0);
    wconv_kernel<<<dim3(3 * HID / 32, HID / 32), dim3(32, 8)>>>(Wqkv, wqkvh, wqkvl, HID, 3 * HID);

    mma_gemm<3><<<16 * (3 * HID / 128), 512, G_SMEM>>>(
        ln1h, ln1l, wqkvh, wqkvl, bqkv, nullptr, nullptr, rope,
        nullptr, Qh, Ql, Kh, Kl, Vh, Vl, 3 * HID, HID);

    // stream B: FC = gelu(ln2 @ W_fc + b_fc), concurrent with QKV/attn/Wo
    cudaStreamWaitEvent(sB, evLn, 0);
    mma_gemm<1><<<16 * (FF / 128), 512, G_SMEM, sB>>>(
        ln2h, ln2l, wfch, wfcl, bfc, nullptr, nullptr, nullptr,
        nullptr, fch, fcl, nullptr, nullptr, nullptr, nullptr, FF, HID);
    cudaEventRecord(evFC, sB);

    // origin: attention
    attn_mma_kernel<<<dim3(SS / 128, BB * HH), 256, A_SMEM>>>(
        Qh, Ql, Kh, Kl, Vh, Vl, ctxh, ctxl);

    // origin: attn_out = ctx @ W_o + b_o (needs Wo weights from sC)
    cudaStreamWaitEvent(0, evC, 0);
    mma_gemm<0><<<16 * (HID / 128), 512, G_SMEM>>>(
        ctxh, ctxl, woh, wol, bo, nullptr, nullptr, nullptr,
        att, nullptr, nullptr, nullptr, nullptr, nullptr, nullptr, HID, HID);

    // origin: out = fc @ W_proj + b_proj + attn_out + hidden (joins FC)
    cudaStreamWaitEvent(0, evFC, 0);
    mma_gemm<2><<<16 * (HID / 128), 512, G_SMEM>>>(
        fch, fcl, wprojh, wprojl, bproj, att, hid, nullptr,
        out, nullptr, nullptr, nullptr, nullptr, nullptr, nullptr, HID, FF);
}

// round 10
// speedup vs baseline: 1.0948x; 1.0317x over previous
#include <cuda_runtime.h>
#include <cuda_bf16.h>
#include <cstdint>

// Problem constants
#define BB 2
#define SS 2048
#define HH 16
#define HD 128
#define HID 2048
#define FF 8192
#define NTOK 4096

typedef __nv_bfloat16 bf16;

// ---------------- scratch (device globals; no allocation allowed) ----------
__device__ float g_rope[SS * 16 * 2];
__device__ bf16 g_ln1h[(size_t)NTOK * HID];
__device__ bf16 g_ln1l[(size_t)NTOK * HID];
__device__ bf16 g_ln2h[(size_t)NTOK * HID];
__device__ bf16 g_ln2l[(size_t)NTOK * HID];
__device__ bf16 g_ctxh[(size_t)NTOK * HID];
__device__ bf16 g_ctxl[(size_t)NTOK * HID];
__device__ bf16 g_fch[(size_t)NTOK * FF];
__device__ bf16 g_fcl[(size_t)NTOK * FF];
__device__ bf16 g_Qh[(size_t)NTOK * HID];
__device__ bf16 g_Ql[(size_t)NTOK * HID];
__device__ bf16 g_Kh[(size_t)NTOK * HID];
__device__ bf16 g_Kl[(size_t)NTOK * HID];
__device__ bf16 g_Vh[(size_t)NTOK * HID];
__device__ bf16 g_Vl[(size_t)NTOK * HID];
__device__ bf16 g_wqkvh[(size_t)3 * HID * HID];
__device__ bf16 g_wqkvl[(size_t)3 * HID * HID];
__device__ bf16 g_woh[(size_t)HID * HID];
__device__ bf16 g_wol[(size_t)HID * HID];
__device__ bf16 g_wfch[(size_t)FF * HID];
__device__ bf16 g_wfcl[(size_t)FF * HID];
__device__ bf16 g_wprojh[(size_t)HID * FF];
__device__ bf16 g_wprojl[(size_t)HID * FF];

// ---------------- helpers ----------------
__device__ __forceinline__ uint32_t smem_u32(const void* p) {
    uint32_t a;
    asm("{ .reg .u64 t; cvta.to.shared.u64 t, %1; cvt.u32.u64 %0, t; }" : "=r"(a) : "l"(p));
    return a;
}
#define CP16(dst, src) \
    asm volatile("cp.async.cg.shared.global [%0], [%1], 16;" :: "r"(dst), "l"(src) : "memory")
#define CP_COMMIT() asm volatile("cp.async.commit_group;" ::: "memory")
#define CP_WAIT1()  asm volatile("cp.async.wait_group 1;" ::: "memory")
#define CP_WAIT0()  asm volatile("cp.async.wait_group 0;" ::: "memory")

__device__ __forceinline__ void ldm_x4(uint32_t* r, uint32_t addr) {
    asm volatile("ldmatrix.sync.aligned.m8n8.x4.shared.b16 {%0,%1,%2,%3}, [%4];"
                 : "=r"(r[0]), "=r"(r[1]), "=r"(r[2]), "=r"(r[3]) : "r"(addr));
}
__device__ __forceinline__ void ldm_x4_t(uint32_t* r, uint32_t addr) {
    asm volatile("ldmatrix.sync.aligned.m8n8.x4.trans.shared.b16 {%0,%1,%2,%3}, [%4];"
                 : "=r"(r[0]), "=r"(r[1]), "=r"(r[2]), "=r"(r[3]) : "r"(addr));
}
__device__ __forceinline__ void mma_bf16(float* c, const uint32_t* a, const uint32_t* b) {
    asm volatile("mma.sync.aligned.m16n8k16.row.col.f32.bf16.bf16.f32 "
                 "{%0,%1,%2,%3},{%4,%5,%6,%7},{%8,%9},{%0,%1,%2,%3};"
                 : "+f"(c[0]), "+f"(c[1]), "+f"(c[2]), "+f"(c[3])
                 : "r"(a[0]), "r"(a[1]), "r"(a[2]), "r"(a[3]), "r"(b[0]), "r"(b[1]));
}
__device__ __forceinline__ void split_bf16(float v, bf16& h, bf16& l) {
    h = __float2bfloat16(v);
    l = __float2bfloat16(v - __bfloat162float(h));
}
__device__ __forceinline__ void packhl(float a, float b, uint32_t& hi, uint32_t& lo) {
    __nv_bfloat162 hv, lv;
    split_bf16(a, hv.x, lv.x);
    split_bf16(b, hv.y, lv.y);
    hi = *(uint32_t*)&hv;
    lo = *(uint32_t*)&lv;
}
__device__ __forceinline__ float gelu_exact(float v) {
    return 0.5f * v * (1.0f + erff(v * 0.70710678118654752f));
}

// ------- fused double layernorm (2 rows/block) + RoPE table ----------------
__global__ void ln_kernel(const float* __restrict__ x,
                          const float* __restrict__ g1, const float* __restrict__ b1,
                          const float* __restrict__ g2, const float* __restrict__ b2,
                          bf16* __restrict__ o1h, bf16* __restrict__ o1l,
                          bf16* __restrict__ o2h, bf16* __restrict__ o2l,
                          float* __restrict__ rtab) {
    __shared__ float redS[16];
    __shared__ float redQ[16];
    const int t = threadIdx.x;             // 512
    const int half = t >> 8;               // 0/1: which row
    const int tt = t & 255;
    const int row = blockIdx.x * 2 + half;

    if (blockIdx.x < 64) {                 // rope table: 512 entries/block
        const int i = blockIdx.x * 512 + t;
        const int s = i >> 4, fi = i & 15;
        const float inv = powf(10000.0f, -(float)fi * (1.0f / 16.0f));
        float sn, cs;
        sincosf((float)s * inv, &sn, &cs);
        rtab[i * 2]     = cs;
        rtab[i * 2 + 1] = sn;
    }

    const float* xr = x + (size_t)row * HID;
    float4 a = *(const float4*)(xr + tt * 8);
    float4 b = *(const float4*)(xr + tt * 8 + 4);
    float s  = a.x + a.y + a.z + a.w + b.x + b.y + b.z + b.w;
    float ss = a.x*a.x + a.y*a.y + a.z*a.z + a.w*a.w
             + b.x*b.x + b.y*b.y + b.z*b.z + b.w*b.w;
    #pragma unroll
    for (int o = 16; o; o >>= 1) {
        s  += __shfl_xor_sync(0xffffffffu, s,  o);
        ss += __shfl_xor_sync(0xffffffffu, ss, o);
    }
    if ((t & 31) == 0) { redS[t >> 5] = s; redQ[t >> 5] = ss; }
    __syncthreads();
    s = 0.f; ss = 0.f;
    #pragma unroll
    for (int i = 0; i < 8; i++) { s += redS[half * 8 + i]; ss += redQ[half * 8 + i]; }
    const float mu  = s * (1.0f / HID);
    const float var = ss * (1.0f / HID) - mu * mu;
    const float rs  = rsqrtf(var + 1e-5f);

    float vals[8] = {a.x,a.y,a.z,a.w,b.x,b.y,b.z,b.w};
    __align__(16) bf16 h1[8], l1[8], h2[8], l2[8];
    #pragma unroll
    for (int q = 0; q < 8; q++) {
        const int col = tt * 8 + q;
        const float xn = (vals[q] - mu) * rs;
        split_bf16(xn * g1[col] + b1[col], h1[q], l1[q]);
        split_bf16(xn * g2[col] + b2[col], h2[q], l2[q]);
    }
    const size_t off = (size_t)row * HID + tt * 8;
    *(uint4*)(o1h + off) = *(uint4*)h1;
    *(uint4*)(o1l + off) = *(uint4*)l1;
    *(uint4*)(o2h + off) = *(uint4*)h2;
    *(uint4*)(o2l + off) = *(uint4*)l2;
}

// ---------------- weight convert + transpose: W[K][N] -> T{h,l}[N][K] ------
__global__ void wconv_kernel(const float* __restrict__ W, bf16* __restrict__ Th,
                             bf16* __restrict__ Tl, int K, int N) {
    __shared__ float tile[32][33];
    const int n0 = blockIdx.x * 32, k0 = blockIdx.y * 32;
    const int tx = threadIdx.x, ty = threadIdx.y;  // 32 x 8
    #pragma unroll
    for (int i = 0; i < 4; i++)
        tile[ty + 8 * i][tx] = W[(size_t)(k0 + ty + 8 * i) * N + n0 + tx];
    __syncthreads();
    #pragma unroll
    for (int i = 0; i < 4; i++) {
        const float v = tile[tx][ty + 8 * i];
        const size_t idx = (size_t)(n0 + ty + 8 * i) * K + k0 + tx;
        bf16 h, l;
        split_bf16(v, h, l);
        Th[idx] = h; Tl[idx] = l;
    }
}

// ------------ mma.sync bf16-split GEMM, CTA 256x128, BK=64, 512 thr --------
#define ROWP   72
#define A_ARR  36864u
#define B_ARR  18432u
#define STG_B  110592u
#define G_SMEM (2u * STG_B)

// EPI: 0 +bias->f32 | 1 gelu(+bias)->bf16 h/l | 3 qkv fused | 4 +bias+add1->f32
template <int EPI>
__global__ void __launch_bounds__(512, 1) mma_gemm(
    const bf16* __restrict__ Ah, const bf16* __restrict__ Al,
    const bf16* __restrict__ Bh, const bf16* __restrict__ Bl,
    const float* __restrict__ bias,
    const float* __restrict__ add1,
    const float* __restrict__ rtab,
    float* __restrict__ Cf, bf16* __restrict__ Ch, bf16* __restrict__ Cl,
    bf16* __restrict__ o2h, bf16* __restrict__ o2l,
    bf16* __restrict__ o3h, bf16* __restrict__ o3l,
    int N, int K) {
    extern __shared__ char sm[];
    const uint32_t smb = smem_u32(sm);
    const int tid = threadIdx.x;
    const int lane = tid & 31;
    const int warp = tid >> 5;
    const int wm = warp >> 2;
    const int wn = warp & 3;

    const int Nt = N >> 7;
    const int pid = blockIdx.x;
    const int mt = (pid / (8 * Nt)) * 8 + (pid & 7);
    const int nt = (pid % (8 * Nt)) >> 3;

    const size_t arow0 = (size_t)mt * 256;
    const size_t brow0 = (size_t)nt * 128;
    const bf16* pa_h = Ah + arow0 * K;
    const bf16* pa_l = Al + arow0 * K;
    const bf16* pb_h = Bh + brow0 * K;
    const bf16* pb_l = Bl + brow0 * K;
    const int nch = K >> 6;

    const uint32_t aoff = ((wm * 64 + (lane & 15)) * ROWP + (lane >> 4) * 8) * 2;
    const uint32_t boff = ((wn * 32 + (lane & 7) + ((lane >> 4) & 1) * 8) * ROWP
                           + ((lane >> 3) & 1) * 8) * 2;

    float acc[4][4][4];
    #pragma unroll
    for (int m = 0; m < 4; m++)
        #pragma unroll
        for (int n = 0; n < 4; n++)
            #pragma unroll
            for (int q = 0; q < 4; q++) acc[m][n][q] = 0.f;

    auto load_stage = [&](int stg, int k0) {
        const uint32_t sb = smb + (uint32_t)stg * STG_B;
        #pragma unroll
        for (int i = 0; i < 4; ++i) {
            const int id = tid + i * 512;
            const int row = id >> 3, cc = id & 7;
            const uint32_t so = (uint32_t)(row * ROWP + cc * 8) * 2;
            const size_t go = (size_t)row * K + k0 + cc * 8;
            CP16(sb + so,         pa_h + go);
            CP16(sb + A_ARR + so, pa_l + go);
        }
        #pragma unroll
        for (int i = 0; i < 2; ++i) {
            const int id = tid + i * 512;
            const int row = id >> 3, cc = id & 7;
            const uint32_t so = (uint32_t)(row * ROWP + cc * 8) * 2;
            const size_t go = (size_t)row * K + k0 + cc * 8;
            CP16(sb + 2 * A_ARR + so,         pb_h + go);
            CP16(sb + 2 * A_ARR + B_ARR + so, pb_l + go);
        }
    };

    load_stage(0, 0);
    CP_COMMIT();

    for (int c = 0; c < nch; ++c) {
        CP_WAIT0();
        __syncthreads();
        if (c + 1 < nch) {
            load_stage((c + 1) & 1, (c + 1) << 6);
            CP_COMMIT();
        }
        const uint32_t sb = smb + (uint32_t)(c & 1) * STG_B;
        #pragma unroll
        for (int ks = 0; ks < 4; ++ks) {
            const uint32_t kb = ks * 32;
            uint32_t ah[4][4], bh[2][4];
            #pragma unroll
            for (int i = 0; i < 4; ++i)
                ldm_x4(ah[i], sb + aoff + kb + i * 16 * ROWP * 2);
            #pragma unroll
            for (int t2 = 0; t2 < 2; ++t2)
                ldm_x4(bh[t2], sb + 2 * A_ARR + boff + kb + t2 * 16 * ROWP * 2);
            #pragma unroll
            for (int m = 0; m < 4; ++m)
                #pragma unroll
                for (int n = 0; n < 4; ++n)
                    mma_bf16(acc[m][n], ah[m], &bh[n >> 1][(n & 1) * 2]);
            {
                uint32_t al[4][4];
                #pragma unroll
                for (int i = 0; i < 4; ++i)
                    ldm_x4(al[i], sb + A_ARR + aoff + kb + i * 16 * ROWP * 2);
                #pragma unroll
                for (int m = 0; m < 4; ++m)
                    #pragma unroll
                    for (int n = 0; n < 4; ++n)
                        mma_bf16(acc[m][n], al[m], &bh[n >> 1][(n & 1) * 2]);
            }
            {
                uint32_t bl[2][4];
                #pragma unroll
                for (int t2 = 0; t2 < 2; ++t2)
                    ldm_x4(bl[t2], sb + 2 * A_ARR + B_ARR + boff + kb + t2 * 16 * ROWP * 2);
                #pragma unroll
                for (int m = 0; m < 4; ++m)
                    #pragma unroll
                    for (int n = 0; n < 4; ++n)
                        mma_bf16(acc[m][n], ah[m], &bl[n >> 1][(n & 1) * 2]);
            }
        }
    }

    // ---------------- epilogue ----------------
    const int row_base = mt * 256 + wm * 64;
    const int col_base = nt * 128 + wn * 32;

    if (EPI == 3) {
        const int hh2 = col_base / 384;
        const int sub0 = col_base % 384;
        const int sect = sub0 >> 7;
        const int dbase = sub0 & 127;
        const bool ropeW = (dbase == 0) && (sect < 2);
        const float qsc = (sect == 0) ? 0.08838834764831845f : 1.0f;
        bf16* Oh = (sect == 0) ? Ch : (sect == 1) ? o2h : o3h;
        bf16* Ol = (sect == 0) ? Cl : (sect == 1) ? o2l : o3l;
        #pragma unroll
        for (int m = 0; m < 4; ++m) {
            const int r0 = row_base + m * 16 + (lane >> 2);
            const int r1 = r0 + 8;
            const int bb2 = r0 >> 11;
            const int s0 = r0 & (SS - 1), s1 = r1 & (SS - 1);
            float v[4][4];
            #pragma unroll
            for (int n = 0; n < 4; ++n) {
                const int cc = col_base + n * 8 + (lane & 3) * 2;
                const float b0 = bias[cc], b1 = bias[cc + 1];
                v[n][0] = acc[m][n][0] + b0; v[n][1] = acc[m][n][1] + b1;
                v[n][2] = acc[m][n][2] + b0; v[n][3] = acc[m][n][3] + b1;
            }
            if (ropeW) {
                float rp[4][4];
                #pragma unroll
                for (int n = 0; n < 4; ++n) {
                    const int dl = n * 8 + (lane & 3) * 2;
                    const bool first = dl < 16;
                    const int np = first ? n + 2 : n - 2;
                    const float sign = first ? -1.0f : 1.0f;
                    const int fi0 = dl & 15, fi1 = (dl + 1) & 15;
                    const float2 c00 = *(const float2*)(rtab + (s0 * 16 + fi0) * 2);
                    const float2 c01 = *(const float2*)(rtab + (s0 * 16 + fi1) * 2);
                    const float2 c10 = *(const float2*)(rtab + (s1 * 16 + fi0) * 2);
                    const float2 c11 = *(const float2*)(rtab + (s1 * 16 + fi1) * 2);
                    rp[n][0] = v[n][0] * c00.x + sign * v[np][0] * c00.y;
                    rp[n][1] = v[n][1] * c01.x + sign * v[np][1] * c01.y;
                    rp[n][2] = v[n][2] * c10.x + sign * v[np][2] * c10.y;
                    rp[n][3] = v[n][3] * c11.x + sign * v[np][3] * c11.y;
                }
                #pragma unroll
                for (int n = 0; n < 4; ++n)
                    #pragma unroll
                    for (int q = 0; q < 4; ++q) v[n][q] = rp[n][q];
            }
            const size_t base0 = (((size_t)bb2 * HH + hh2) * SS + s0) * HD;
            const size_t base1 = (((size_t)bb2 * HH + hh2) * SS + s1) * HD;
            #pragma unroll
            for (int n = 0; n < 4; ++n) {
                const int d = dbase + n * 8 + (lane & 3) * 2;
                uint32_t hi, lo;
                packhl(v[n][0] * qsc, v[n][1] * qsc, hi, lo);
                *(uint32_t*)(Oh + base0 + d) = hi;
                *(uint32_t*)(Ol + base0 + d) = lo;
                packhl(v[n][2] * qsc, v[n][3] * qsc, hi, lo);
                *(uint32_t*)(Oh + base1 + d) = hi;
                *(uint32_t*)(Ol + base1 + d) = lo;
            }
        }
        return;
    }

    #pragma unroll
    for (int m = 0; m < 4; ++m) {
        const int r0 = row_base + m * 16 + (lane >> 2);
        #pragma unroll
        for (int n = 0; n < 4; ++n) {
            const int cc = col_base + n * 8 + (lane & 3) * 2;
            const float b0 = bias[cc], b1 = bias[cc + 1];
            float v0 = acc[m][n][0] + b0, v1 = acc[m][n][1] + b1;
            float v2 = acc[m][n][2] + b0, v3 = acc[m][n][3] + b1;
            const size_t off0 = (size_t)r0 * N + cc;
            const size_t off1 = (size_t)(r0 + 8) * N + cc;
            if (EPI == 1) {
                uint32_t hi, lo;
                packhl(gelu_exact(v0), gelu_exact(v1), hi, lo);
                *(uint32_t*)(Ch + off0) = hi;
                *(uint32_t*)(Cl + off0) = lo;
                packhl(gelu_exact(v2), gelu_exact(v3), hi, lo);
                *(uint32_t*)(Ch + off1) = hi;
                *(uint32_t*)(Cl + off1) = lo;
            } else {
                if (EPI == 4) {
                    const float2 x0 = *(const float2*)(add1 + off0);
                    const float2 x1 = *(const float2*)(add1 + off1);
                    v0 += x0.x; v1 += x0.y;
                    v2 += x1.x; v3 += x1.y;
                }
                *(float2*)(Cf + off0) = make_float2(v0, v1);
                *(float2*)(Cf + off1) = make_float2(v2, v3);
            }
        }
    }
}

// ---------------- causal flash attention via mma.sync, BQ=128 --------------
#define AST   136
#define ATILE (64 * AST * 2)
#define AQ_H  0
#define AQ_L  (2 * ATILE)
#define ASTAGE0 (4 * ATILE)
#define ASTG_B  (4 * ATILE)
#define A_SMEM  (4 * ATILE + 2 * ASTG_B)

__global__ void __launch_bounds__(256, 1) attn_mma_kernel(
    const bf16* __restrict__ Qh, const bf16* __restrict__ Ql,
    const bf16* __restrict__ Kh, const bf16* __restrict__ Kl,
    const bf16* __restrict__ Vh, const bf16* __restrict__ Vl,
    bf16* __restrict__ ctxh, bf16* __restrict__ ctxl) {
    extern __shared__ char sm[];
    const uint32_t smb = smem_u32(sm);
    const int qt = gridDim.x - 1 - blockIdx.x;
    const int bhid = blockIdx.y;
    const int b = bhid >> 4, h = bhid & 15;
    const int tid = threadIdx.x;
    const int lane = tid & 31;
    const int w = tid >> 5;

    const size_t headbase = (size_t)bhid * SS * HD;

    auto ldq = [&]() {
        const size_t gb = headbase + (size_t)qt * 128 * HD;
        #pragma unroll
        for (int i = 0; i < 8; i++) {
            const int c = tid + i * 256;
            const int row = c >> 4, ch = c & 15;
            const uint32_t so = row * (AST * 2) + ch * 16;
            const size_t go = gb + (size_t)row * HD + ch * 8;
            CP16(smb + AQ_H + so, Qh + go);
            CP16(smb + AQ_L + so, Ql + go);
        }
    };
    auto ldkv = [&](int kt, int stg) {
        const uint32_t sb = smb + ASTAGE0 + (uint32_t)stg * ASTG_B;
        const size_t gb = headbase + (size_t)kt * 64 * HD;
        #pragma unroll
        for (int i = 0; i < 4; i++) {
            const int c = tid + i * 256;
            const int row = c >> 4, ch = c & 15;
            const uint32_t so = row * (AST * 2) + ch * 16;
            const size_t go = gb + (size_t)row * HD + ch * 8;
            CP16(sb + so,             Kh + go);
            CP16(sb + ATILE + so,     Kl + go);
            CP16(sb + 2 * ATILE + so, Vh + go);
            CP16(sb + 3 * ATILE + so, Vl + go);
        }
    };

    const uint32_t qa_off = ((w * 16 + (lane & 15)) * AST + (lane >> 4) * 8) * 2;
    const int lm = lane >> 3, li = lane & 7;
    const uint32_t kb_off = (((lm >> 1) * 8 + li) * AST + (lm & 1) * 8) * 2;
    const uint32_t vb_off = (((lm & 1) * 8 + li) * AST + (lm >> 1) * 8) * 2;

    float oacc[16][4];
    #pragma unroll
    for (int t = 0; t < 16; t++)
        #pragma unroll
        for (int q = 0; q < 4; q++) oacc[t][q] = 0.f;
    float m0 = -1e30f, m1 = -1e30f, l0 = 0.f, l1 = 0.f;
    const int qrow0 = qt * 128 + w * 16 + (lane >> 2);
    const int qrow1 = qrow0 + 8;
    const int nkt = 2 * qt + 2;

    ldq();
    ldkv(0, 0);
    CP_COMMIT();

    for (int kt = 0; kt < nkt; ++kt) {
        if (kt + 1 < nkt) {
            ldkv(kt + 1, (kt + 1) & 1);
            CP_COMMIT();
            CP_WAIT1();
        } else {
            CP_WAIT0();
        }
        __syncthreads();
        const uint32_t sb = smb + ASTAGE0 + (uint32_t)(kt & 1) * ASTG_B;

        float sacc[8][4];
        #pragma unroll
        for (int j = 0; j < 8; j++)
            #pragma unroll
            for (int q = 0; q < 4; q++) sacc[j][q] = 0.f;

        #pragma unroll
        for (int ks = 0; ks < 8; ++ks) {
            uint32_t ah[4], al[4], kfh[8][2], kfl[8][2];
            ldm_x4(ah, smb + AQ_H + qa_off + ks * 32);
            ldm_x4(al, smb + AQ_L + qa_off + ks * 32);
            #pragma unroll
            for (int jp = 0; jp < 4; ++jp) {
                uint32_t r[4];
                ldm_x4(r, sb + kb_off + (jp * 16 * AST + ks * 16) * 2);
                kfh[2*jp][0] = r[0]; kfh[2*jp][1] = r[1];
                kfh[2*jp+1][0] = r[2]; kfh[2*jp+1][1] = r[3];
                ldm_x4(r, sb + ATILE + kb_off + (jp * 16 * AST + ks * 16) * 2);
                kfl[2*jp][0] = r[0]; kfl[2*jp][1] = r[1];
                kfl[2*jp+1][0] = r[2]; kfl[2*jp+1][1] = r[3];
            }
            #pragma unroll
            for (int j = 0; j < 8; ++j) mma_bf16(sacc[j], ah, kfh[j]);
            #pragma unroll
            for (int j = 0; j < 8; ++j) mma_bf16(sacc[j], al, kfh[j]);
            #pragma unroll
            for (int j = 0; j < 8; ++j) mma_bf16(sacc[j], ah, kfl[j]);
        }

        if (kt >= 2 * qt) {
            #pragma unroll
            for (int j = 0; j < 8; ++j) {
                const int c0 = kt * 64 + j * 8 + (lane & 3) * 2;
                if (c0     > qrow0) sacc[j][0] = -1e30f;
                if (c0 + 1 > qrow0) sacc[j][1] = -1e30f;
                if (c0     > qrow1) sacc[j][2] = -1e30f;
                if (c0 + 1 > qrow1) sacc[j][3] = -1e30f;
            }
        }

        float mx0 = -1e30f, mx1 = -1e30f;
        #pragma unroll
        for (int j = 0; j < 8; ++j) {
            mx0 = fmaxf(mx0, fmaxf(sacc[j][0], sacc[j][1]));
            mx1 = fmaxf(mx1, fmaxf(sacc[j][2], sacc[j][3]));
        }
        #pragma unroll
        for (int o = 1; o < 4; o <<= 1) {
            mx0 = fmaxf(mx0, __shfl_xor_sync(0xffffffffu, mx0, o));
            mx1 = fmaxf(mx1, __shfl_xor_sync(0xffffffffu, mx1, o));
        }
        const float mn0 = fmaxf(m0, mx0), mn1 = fmaxf(m1, mx1);
        const float e0 = __expf(m0 - mn0), e1 = __expf(m1 - mn1);
        m0 = mn0; m1 = mn1;
        float rs0 = 0.f, rs1 = 0.f;
        #pragma unroll
        for (int j = 0; j < 8; ++j) {
            sacc[j][0] = __expf(sacc[j][0] - mn0); rs0 += sacc[j][0];
            sacc[j][1] = __expf(sacc[j][1] - mn0); rs0 += sacc[j][1];
            sacc[j][2] = __expf(sacc[j][2] - mn1); rs1 += sacc[j][2];
            sacc[j][3] = __expf(sacc[j][3] - mn1); rs1 += sacc[j][3];
        }
        #pragma unroll
        for (int o = 1; o < 4; o <<= 1) {
            rs0 += __shfl_xor_sync(0xffffffffu, rs0, o);
            rs1 += __shfl_xor_sync(0xffffffffu, rs1, o);
        }
        l0 = l0 * e0 + rs0;
        l1 = l1 * e1 + rs1;
        #pragma unroll
        for (int t = 0; t < 16; t++) {
            oacc[t][0] *= e0; oacc[t][1] *= e0;
            oacc[t][2] *= e1; oacc[t][3] *= e1;
        }

        #pragma unroll
        for (int c = 0; c < 4; ++c) {
            uint32_t pah[4], pal[4];
            packhl(sacc[2*c][0],   sacc[2*c][1],   pah[0], pal[0]);
            packhl(sacc[2*c][2],   sacc[2*c][3],   pah[1], pal[1]);
            packhl(sacc[2*c+1][0], sacc[2*c+1][1], pah[2], pal[2]);
            packhl(sacc[2*c+1][2], sacc[2*c+1][3], pah[3], pal[3]);
            #pragma unroll
            for (int tp = 0; tp < 8; ++tp) {
                uint32_t rvh[4], rvl[4];
                ldm_x4_t(rvh, sb + 2 * ATILE + vb_off + (c * 16 * AST + tp * 16) * 2);
                ldm_x4_t(rvl, sb + 3 * ATILE + vb_off + (c * 16 * AST + tp * 16) * 2);
                mma_bf16(oacc[2*tp],   pah, &rvh[0]);
                mma_bf16(oacc[2*tp],   pal, &rvh[0]);
                mma_bf16(oacc[2*tp],   pah, &rvl[0]);
                mma_bf16(oacc[2*tp+1], pah, &rvh[2]);
                mma_bf16(oacc[2*tp+1], pal, &rvh[2]);
                mma_bf16(oacc[2*tp+1], pah, &rvl[2]);
            }
        }
        __syncthreads();
    }

    const float inv0 = 1.0f / l0, inv1 = 1.0f / l1;
    const size_t ob0 = ((size_t)b * SS + qrow0) * HID + h * HD;
    const size_t ob1 = ((size_t)b * SS + qrow1) * HID + h * HD;
    #pragma unroll
    for (int t = 0; t < 16; ++t) {
        const int d = t * 8 + (lane & 3) * 2;
        uint32_t hi, lo;
        packhl(oacc[t][0] * inv0, oacc[t][1] * inv0, hi, lo);
        *(uint32_t*)(ctxh + ob0 + d) = hi;
        *(uint32_t*)(ctxl + ob0 + d) = lo;
        packhl(oacc[t][2] * inv1, oacc[t][3] * inv1, hi, lo);
        *(uint32_t*)(ctxh + ob1 + d) = hi;
        *(uint32_t*)(ctxl + ob1 + d) = lo;
    }
}

// ---------------- launch (dense stream DAG; Wo last) ----------------
extern "C" void kernel_launch(void* const* d_in, const int* in_sizes, int n_in,
                              void* d_out, int out_size) {
    const float* hid   = (const float*)d_in[0];
    const float* ln1g  = (const float*)d_in[1];
    const float* ln1b  = (const float*)d_in[2];
    const float* ln2g  = (const float*)d_in[3];
    const float* ln2b  = (const float*)d_in[4];
    const float* Wqkv  = (const float*)d_in[5];
    const float* bqkv  = (const float*)d_in[6];
    const float* Wo    = (const float*)d_in[7];
    const float* bo    = (const float*)d_in[8];
    const float* Wfc   = (const float*)d_in[9];
    const float* bfc   = (const float*)d_in[10];
    const float* Wproj = (const float*)d_in[11];
    const float* bproj = (const float*)d_in[12];
    float* out = (float*)d_out;

    float *rope;
    bf16 *ln1h, *ln1l, *ln2h, *ln2l, *ctxh, *ctxl, *fch, *fcl;
    bf16 *Qh, *Ql, *Kh, *Kl, *Vh, *Vl;
    bf16 *wqkvh, *wqkvl, *woh, *wol, *wfch, *wfcl, *wprojh, *wprojl;
    cudaGetSymbolAddress((void**)&rope, g_rope);
    cudaGetSymbolAddress((void**)&ln1h, g_ln1h);
    cudaGetSymbolAddress((void**)&ln1l, g_ln1l);
    cudaGetSymbolAddress((void**)&ln2h, g_ln2h);
    cudaGetSymbolAddress((void**)&ln2l, g_ln2l);
    cudaGetSymbolAddress((void**)&ctxh, g_ctxh);
    cudaGetSymbolAddress((void**)&ctxl, g_ctxl);
    cudaGetSymbolAddress((void**)&fch, g_fch);
    cudaGetSymbolAddress((void**)&fcl, g_fcl);
    cudaGetSymbolAddress((void**)&Qh, g_Qh);
    cudaGetSymbolAddress((void**)&Ql, g_Ql);
    cudaGetSymbolAddress((void**)&Kh, g_Kh);
    cudaGetSymbolAddress((void**)&Kl, g_Kl);
    cudaGetSymbolAddress((void**)&Vh, g_Vh);
    cudaGetSymbolAddress((void**)&Vl, g_Vl);
    cudaGetSymbolAddress((void**)&wqkvh, g_wqkvh);
    cudaGetSymbolAddress((void**)&wqkvl, g_wqkvl);
    cudaGetSymbolAddress((void**)&woh, g_woh);
    cudaGetSymbolAddress((void**)&wol, g_wol);
    cudaGetSymbolAddress((void**)&wfch, g_wfch);
    cudaGetSymbolAddress((void**)&wfcl, g_wfcl);
    cudaGetSymbolAddress((void**)&wprojh, g_wprojh);
    cudaGetSymbolAddress((void**)&wprojl, g_wprojl);

    cudaFuncSetAttribute(mma_gemm<0>, cudaFuncAttributeMaxDynamicSharedMemorySize, G_SMEM);
    cudaFuncSetAttribute(mma_gemm<1>, cudaFuncAttributeMaxDynamicSharedMemorySize, G_SMEM);
    cudaFuncSetAttribute(mma_gemm<3>, cudaFuncAttributeMaxDynamicSharedMemorySize, G_SMEM);
    cudaFuncSetAttribute(mma_gemm<4>, cudaFuncAttributeMaxDynamicSharedMemorySize, G_SMEM);
    cudaFuncSetAttribute(attn_mma_kernel, cudaFuncAttributeMaxDynamicSharedMemorySize, A_SMEM);

    static cudaStream_t sB = nullptr, sC = nullptr;
    static cudaEvent_t evRoot = nullptr, evLn = nullptr, evWq = nullptr,
                       evWo = nullptr, evWp = nullptr, evPROJ = nullptr;
    if (!sB) {
        cudaStreamCreateWithFlags(&sB, cudaStreamNonBlocking);
        cudaStreamCreateWithFlags(&sC, cudaStreamNonBlocking);
        cudaEventCreateWithFlags(&evRoot, cudaEventDisableTiming);
        cudaEventCreateWithFlags(&evLn,   cudaEventDisableTiming);
        cudaEventCreateWithFlags(&evWq,   cudaEventDisableTiming);
        cudaEventCreateWithFlags(&evWo,   cudaEventDisableTiming);
        cudaEventCreateWithFlags(&evWp,   cudaEventDisableTiming);
        cudaEventCreateWithFlags(&evPROJ, cudaEventDisableTiming);
    }

    cudaEventRecord(evRoot, 0);
    cudaStreamWaitEvent(sB, evRoot, 0);
    cudaStreamWaitEvent(sC, evRoot, 0);

    // --- stream C: Wqkv, Wo, Wproj conversions ---
    wconv_kernel<<<dim3(3 * HID / 32, HID / 32), dim3(32, 8), 0, sC>>>(Wqkv, wqkvh, wqkvl, HID, 3 * HID);
    cudaEventRecord(evWq, sC);
    wconv_kernel<<<dim3(HID / 32, HID / 32), dim3(32, 8), 0, sC>>>(Wo, woh, wol, HID, HID);
    cudaEventRecord(evWo, sC);
    wconv_kernel<<<dim3(HID / 32, FF / 32),  dim3(32, 8), 0, sC>>>(Wproj, wprojh, wprojl, FF, HID);
    cudaEventRecord(evWp, sC);

    // --- stream B: Wfc conversion, FC gemm, PROJ gemm (out = proj+bias+hid) ---
    wconv_kernel<<<dim3(FF / 32, HID / 32), dim3(32, 8), 0, sB>>>(Wfc, wfch, wfcl, HID, FF);

    // --- origin: ln (+rope table) ---
    ln_kernel<<<NTOK / 2, 512>>>(hid, ln1g, ln1b, ln2g, ln2b, ln1h, ln1l, ln2h, ln2l, rope);
    cudaEventRecord(evLn, 0);

    // stream B: FC = gelu(ln2 @ W_fc + b_fc)
    cudaStreamWaitEvent(sB, evLn, 0);
    mma_gemm<1><<<16 * (FF / 128), 512, G_SMEM, sB>>>(
        ln2h, ln2l, wfch, wfcl, bfc, nullptr, nullptr,
        nullptr, fch, fcl, nullptr, nullptr, nullptr, nullptr, FF, HID);
    // stream B: out = fc @ W_proj + b_proj + hid
    cudaStreamWaitEvent(sB, evWp, 0);
    mma_gemm<4><<<16 * (HID / 128), 512, G_SMEM, sB>>>(
        fch, fcl, wprojh, wprojl, bproj, hid, nullptr,
        out, nullptr, nullptr, nullptr, nullptr, nullptr, nullptr, HID, FF);
    cudaEventRecord(evPROJ, sB);

    // origin: QKV gemm + fused bias/RoPE/scale/head-transpose
    cudaStreamWaitEvent(0, evWq, 0);
    mma_gemm<3><<<16 * (3 * HID / 128), 512, G_SMEM>>>(
        ln1h, ln1l, wqkvh, wqkvl, bqkv, nullptr, rope,
        nullptr, Qh, Ql, Kh, Kl, Vh, Vl, 3 * HID, HID);

    // origin: attention
    attn_mma_kernel<<<dim3(SS / 128, BB * HH), 256, A_SMEM>>>(
        Qh, Ql, Kh, Kl, Vh, Vl, ctxh, ctxl);

    // origin: out += ctx @ W_o + b_o   (joins PROJ + Wo weights)
    cudaStreamWaitEvent(0, evWo, 0);
    cudaStreamWaitEvent(0, evPROJ, 0);
    mma_gemm<4><<<16 * (HID / 128), 512, G_SMEM>>>(
        ctxh, ctxl, woh, wol, bo, out, nullptr,
        out, nullptr, nullptr, nullptr, nullptr, nullptr, nullptr, HID, HID);
}

// round 11
// speedup vs baseline: 1.0996x; 1.0043x over previous
#include <cuda_runtime.h>
#include <cuda_bf16.h>
#include <cstdint>

// Problem constants
#define BB 2
#define SS 2048
#define HH 16
#define HD 128
#define HID 2048
#define FF 8192
#define NTOK 4096

typedef __nv_bfloat16 bf16;

// ---------------- scratch (device globals; no allocation allowed) ----------
__device__ float g_rope[SS * 16 * 2];
__device__ bf16 g_ln1h[(size_t)NTOK * HID];
__device__ bf16 g_ln1l[(size_t)NTOK * HID];
__device__ bf16 g_ln2h[(size_t)NTOK * HID];
__device__ bf16 g_ln2l[(size_t)NTOK * HID];
__device__ bf16 g_ctxh[(size_t)NTOK * HID];
__device__ bf16 g_ctxl[(size_t)NTOK * HID];
__device__ bf16 g_fch[(size_t)NTOK * FF];
__device__ bf16 g_fcl[(size_t)NTOK * FF];
__device__ bf16 g_Qh[(size_t)NTOK * HID];
__device__ bf16 g_Ql[(size_t)NTOK * HID];
__device__ bf16 g_Kh[(size_t)NTOK * HID];
__device__ bf16 g_Kl[(size_t)NTOK * HID];
__device__ bf16 g_Vh[(size_t)NTOK * HID];
__device__ bf16 g_Vl[(size_t)NTOK * HID];
__device__ bf16 g_wqkvh[(size_t)3 * HID * HID];
__device__ bf16 g_wqkvl[(size_t)3 * HID * HID];
__device__ bf16 g_woh[(size_t)HID * HID];
__device__ bf16 g_wol[(size_t)HID * HID];
__device__ bf16 g_wfch[(size_t)FF * HID];
__device__ bf16 g_wfcl[(size_t)FF * HID];
__device__ bf16 g_wprojh[(size_t)HID * FF];
__device__ bf16 g_wprojl[(size_t)HID * FF];

// ---------------- helpers ----------------
__device__ __forceinline__ uint32_t smem_u32(const void* p) {
    uint32_t a;
    asm("{ .reg .u64 t; cvta.to.shared.u64 t, %1; cvt.u32.u64 %0, t; }" : "=r"(a) : "l"(p));
    return a;
}
#define CP16(dst, src) \
    asm volatile("cp.async.cg.shared.global [%0], [%1], 16;" :: "r"(dst), "l"(src) : "memory")
#define CP_COMMIT() asm volatile("cp.async.commit_group;" ::: "memory")
#define CP_WAIT1()  asm volatile("cp.async.wait_group 1;" ::: "memory")
#define CP_WAIT0()  asm volatile("cp.async.wait_group 0;" ::: "memory")

__device__ __forceinline__ void ldm_x4(uint32_t* r, uint32_t addr) {
    asm volatile("ldmatrix.sync.aligned.m8n8.x4.shared.b16 {%0,%1,%2,%3}, [%4];"
                 : "=r"(r[0]), "=r"(r[1]), "=r"(r[2]), "=r"(r[3]) : "r"(addr));
}
__device__ __forceinline__ void ldm_x4_t(uint32_t* r, uint32_t addr) {
    asm volatile("ldmatrix.sync.aligned.m8n8.x4.trans.shared.b16 {%0,%1,%2,%3}, [%4];"
                 : "=r"(r[0]), "=r"(r[1]), "=r"(r[2]), "=r"(r[3]) : "r"(addr));
}
__device__ __forceinline__ void mma_bf16(float* c, const uint32_t* a, const uint32_t* b) {
    asm volatile("mma.sync.aligned.m16n8k16.row.col.f32.bf16.bf16.f32 "
                 "{%0,%1,%2,%3},{%4,%5,%6,%7},{%8,%9},{%0,%1,%2,%3};"
                 : "+f"(c[0]), "+f"(c[1]), "+f"(c[2]), "+f"(c[3])
                 : "r"(a[0]), "r"(a[1]), "r"(a[2]), "r"(a[3]), "r"(b[0]), "r"(b[1]));
}
__device__ __forceinline__ void split_bf16(float v, bf16& h, bf16& l) {
    h = __float2bfloat16(v);
    l = __float2bfloat16(v - __bfloat162float(h));
}
__device__ __forceinline__ void packhl(float a, float b, uint32_t& hi, uint32_t& lo) {
    __nv_bfloat162 hv, lv;
    split_bf16(a, hv.x, lv.x);
    split_bf16(b, hv.y, lv.y);
    hi = *(uint32_t*)&hv;
    lo = *(uint32_t*)&lv;
}
__device__ __forceinline__ float gelu_exact(float v) {
    return 0.5f * v * (1.0f + erff(v * 0.70710678118654752f));
}

// ------- fused double layernorm (2 rows/block) + RoPE table ----------------
__global__ void ln_kernel(const float* __restrict__ x,
                          const float* __restrict__ g1, const float* __restrict__ b1,
                          const float* __restrict__ g2, const float* __restrict__ b2,
                          bf16* __restrict__ o1h, bf16* __restrict__ o1l,
                          bf16* __restrict__ o2h, bf16* __restrict__ o2l,
                          float* __restrict__ rtab) {
    __shared__ float redS[16];
    __shared__ float redQ[16];
    const int t = threadIdx.x;             // 512
    const int half = t >> 8;
    const int tt = t & 255;
    const int row = blockIdx.x * 2 + half;

    if (blockIdx.x < 64) {
        const int i = blockIdx.x * 512 + t;
        const int s = i >> 4, fi = i & 15;
        const float inv = powf(10000.0f, -(float)fi * (1.0f / 16.0f));
        float sn, cs;
        sincosf((float)s * inv, &sn, &cs);
        rtab[i * 2]     = cs;
        rtab[i * 2 + 1] = sn;
    }

    const float* xr = x + (size_t)row * HID;
    float4 a = *(const float4*)(xr + tt * 8);
    float4 b = *(const float4*)(xr + tt * 8 + 4);
    float s  = a.x + a.y + a.z + a.w + b.x + b.y + b.z + b.w;
    float ss = a.x*a.x + a.y*a.y + a.z*a.z + a.w*a.w
             + b.x*b.x + b.y*b.y + b.z*b.z + b.w*b.w;
    #pragma unroll
    for (int o = 16; o; o >>= 1) {
        s  += __shfl_xor_sync(0xffffffffu, s,  o);
        ss += __shfl_xor_sync(0xffffffffu, ss, o);
    }
    if ((t & 31) == 0) { redS[t >> 5] = s; redQ[t >> 5] = ss; }
    __syncthreads();
    s = 0.f; ss = 0.f;
    #pragma unroll
    for (int i = 0; i < 8; i++) { s += redS[half * 8 + i]; ss += redQ[half * 8 + i]; }
    const float mu  = s * (1.0f / HID);
    const float var = ss * (1.0f / HID) - mu * mu;
    const float rs  = rsqrtf(var + 1e-5f);

    float vals[8] = {a.x,a.y,a.z,a.w,b.x,b.y,b.z,b.w};
    __align__(16) bf16 h1[8], l1[8], h2[8], l2[8];
    #pragma unroll
    for (int q = 0; q < 8; q++) {
        const int col = tt * 8 + q;
        const float xn = (vals[q] - mu) * rs;
        split_bf16(xn * g1[col] + b1[col], h1[q], l1[q]);
        split_bf16(xn * g2[col] + b2[col], h2[q], l2[q]);
    }
    const size_t off = (size_t)row * HID + tt * 8;
    *(uint4*)(o1h + off) = *(uint4*)h1;
    *(uint4*)(o1l + off) = *(uint4*)l1;
    *(uint4*)(o2h + off) = *(uint4*)h2;
    *(uint4*)(o2l + off) = *(uint4*)l2;
}

// ------- weight convert + transpose (vectorized): W[K][N] -> T{h,l}[N][K] --
// 64x64 tile, 256 threads; float4 loads, uint4 (8xbf16) stores.
__global__ void wconv_kernel(const float* __restrict__ W, bf16* __restrict__ Th,
                             bf16* __restrict__ Tl, int K, int N) {
    __shared__ float tile[64][65];
    const int n0 = blockIdx.x * 64, k0 = blockIdx.y * 64;
    const int tid = threadIdx.x;           // 256
    // load 64(k) x 64(n) floats: thread -> row = tid>>4 + 16*i, col4 = (tid&15)*4
    {
        const int r = tid >> 4, c = (tid & 15) * 4;
        #pragma unroll
        for (int i = 0; i < 4; i++) {
            const float4 v = *(const float4*)(W + (size_t)(k0 + r + 16 * i) * N + n0 + c);
            tile[r + 16 * i][c]     = v.x;
            tile[r + 16 * i][c + 1] = v.y;
            tile[r + 16 * i][c + 2] = v.z;
            tile[r + 16 * i][c + 3] = v.w;
        }
    }
    __syncthreads();
    // store: 512 chunks of 8 k-elems: idx -> n = idx>>3, kc = (idx&7)*8
    #pragma unroll
    for (int it = 0; it < 2; ++it) {
        const int idx = tid + it * 256;
        const int n = idx >> 3, kc = (idx & 7) * 8;
        __align__(16) bf16 h[8], l[8];
        #pragma unroll
        for (int j = 0; j < 8; j++)
            split_bf16(tile[kc + j][n], h[j], l[j]);
        const size_t o = (size_t)(n0 + n) * K + k0 + kc;
        *(uint4*)(Th + o) = *(uint4*)h;
        *(uint4*)(Tl + o) = *(uint4*)l;
    }
}

// ------------ mma.sync bf16-split GEMM, CTA 256x128, BK=64, 512 thr --------
#define ROWP   72
#define A_ARR  36864u
#define B_ARR  18432u
#define STG_B  110592u
#define G_SMEM (2u * STG_B)

// EPI: 0 +bias->f32 | 1 gelu(+bias)->bf16 h/l | 3 qkv fused | 4 +bias+add1->f32
template <int EPI>
__global__ void __launch_bounds__(512, 1) mma_gemm(
    const bf16* __restrict__ Ah, const bf16* __restrict__ Al,
    const bf16* __restrict__ Bh, const bf16* __restrict__ Bl,
    const float* __restrict__ bias,
    const float* __restrict__ add1,
    const float* __restrict__ rtab,
    float* __restrict__ Cf, bf16* __restrict__ Ch, bf16* __restrict__ Cl,
    bf16* __restrict__ o2h, bf16* __restrict__ o2l,
    bf16* __restrict__ o3h, bf16* __restrict__ o3l,
    int N, int K) {
    extern __shared__ char sm[];
    const uint32_t smb = smem_u32(sm);
    const int tid = threadIdx.x;
    const int lane = tid & 31;
    const int warp = tid >> 5;
    const int wm = warp >> 2;
    const int wn = warp & 3;

    const int Nt = N >> 7;
    const int pid = blockIdx.x;
    const int mt = (pid / (8 * Nt)) * 8 + (pid & 7);
    const int nt = (pid % (8 * Nt)) >> 3;

    const size_t arow0 = (size_t)mt * 256;
    const size_t brow0 = (size_t)nt * 128;
    const bf16* pa_h = Ah + arow0 * K;
    const bf16* pa_l = Al + arow0 * K;
    const bf16* pb_h = Bh + brow0 * K;
    const bf16* pb_l = Bl + brow0 * K;
    const int nch = K >> 6;

    const uint32_t aoff = ((wm * 64 + (lane & 15)) * ROWP + (lane >> 4) * 8) * 2;
    const uint32_t boff = ((wn * 32 + (lane & 7) + ((lane >> 4) & 1) * 8) * ROWP
                           + ((lane >> 3) & 1) * 8) * 2;

    float acc[4][4][4];
    #pragma unroll
    for (int m = 0; m < 4; m++)
        #pragma unroll
        for (int n = 0; n < 4; n++)
            #pragma unroll
            for (int q = 0; q < 4; q++) acc[m][n][q] = 0.f;

    auto load_stage = [&](int stg, int k0) {
        const uint32_t sb = smb + (uint32_t)stg * STG_B;
        #pragma unroll
        for (int i = 0; i < 4; ++i) {
            const int id = tid + i * 512;
            const int row = id >> 3, cc = id & 7;
            const uint32_t so = (uint32_t)(row * ROWP + cc * 8) * 2;
            const size_t go = (size_t)row * K + k0 + cc * 8;
            CP16(sb + so,         pa_h + go);
            CP16(sb + A_ARR + so, pa_l + go);
        }
        #pragma unroll
        for (int i = 0; i < 2; ++i) {
            const int id = tid + i * 512;
            const int row = id >> 3, cc = id & 7;
            const uint32_t so = (uint32_t)(row * ROWP + cc * 8) * 2;
            const size_t go = (size_t)row * K + k0 + cc * 8;
            CP16(sb + 2 * A_ARR + so,         pb_h + go);
            CP16(sb + 2 * A_ARR + B_ARR + so, pb_l + go);
        }
    };

    load_stage(0, 0);
    CP_COMMIT();

    for (int c = 0; c < nch; ++c) {
        CP_WAIT0();
        __syncthreads();
        if (c + 1 < nch) {
            load_stage((c + 1) & 1, (c + 1) << 6);
            CP_COMMIT();
        }
        const uint32_t sb = smb + (uint32_t)(c & 1) * STG_B;
        #pragma unroll
        for (int ks = 0; ks < 4; ++ks) {
            const uint32_t kb = ks * 32;
            uint32_t ah[4][4], bh[2][4];
            #pragma unroll
            for (int i = 0; i < 4; ++i)
                ldm_x4(ah[i], sb + aoff + kb + i * 16 * ROWP * 2);
            #pragma unroll
            for (int t2 = 0; t2 < 2; ++t2)
                ldm_x4(bh[t2], sb + 2 * A_ARR + boff + kb + t2 * 16 * ROWP * 2);
            #pragma unroll
            for (int m = 0; m < 4; ++m)
                #pragma unroll
                for (int n = 0; n < 4; ++n)
                    mma_bf16(acc[m][n], ah[m], &bh[n >> 1][(n & 1) * 2]);
            {
                uint32_t al[4][4];
                #pragma unroll
                for (int i = 0; i < 4; ++i)
                    ldm_x4(al[i], sb + A_ARR + aoff + kb + i * 16 * ROWP * 2);
                #pragma unroll
                for (int m = 0; m < 4; ++m)
                    #pragma unroll
                    for (int n = 0; n < 4; ++n)
                        mma_bf16(acc[m][n], al[m], &bh[n >> 1][(n & 1) * 2]);
            }
            {
                uint32_t bl[2][4];
                #pragma unroll
                for (int t2 = 0; t2 < 2; ++t2)
                    ldm_x4(bl[t2], sb + 2 * A_ARR + B_ARR + boff + kb + t2 * 16 * ROWP * 2);
                #pragma unroll
                for (int m = 0; m < 4; ++m)
                    #pragma unroll
                    for (int n = 0; n < 4; ++n)
                        mma_bf16(acc[m][n], ah[m], &bl[n >> 1][(n & 1) * 2]);
            }
        }
    }

    // ---------------- epilogue ----------------
    const int row_base = mt * 256 + wm * 64;
    const int col_base = nt * 128 + wn * 32;

    if (EPI == 3) {
        const int hh2 = col_base / 384;
        const int sub0 = col_base % 384;
        const int sect = sub0 >> 7;
        const int dbase = sub0 & 127;
        const bool ropeW = (dbase == 0) && (sect < 2);
        const float qsc = (sect == 0) ? 0.08838834764831845f : 1.0f;
        bf16* Oh = (sect == 0) ? Ch : (sect == 1) ? o2h : o3h;
        bf16* Ol = (sect == 0) ? Cl : (sect == 1) ? o2l : o3l;
        #pragma unroll
        for (int m = 0; m < 4; ++m) {
            const int r0 = row_base + m * 16 + (lane >> 2);
            const int r1 = r0 + 8;
            const int bb2 = r0 >> 11;
            const int s0 = r0 & (SS - 1), s1 = r1 & (SS - 1);
            float v[4][4];
            #pragma unroll
            for (int n = 0; n < 4; ++n) {
                const int cc = col_base + n * 8 + (lane & 3) * 2;
                const float b0 = bias[cc], b1 = bias[cc + 1];
                v[n][0] = acc[m][n][0] + b0; v[n][1] = acc[m][n][1] + b1;
                v[n][2] = acc[m][n][2] + b0; v[n][3] = acc[m][n][3] + b1;
            }
            if (ropeW) {
                float rp[4][4];
                #pragma unroll
                for (int n = 0; n < 4; ++n) {
                    const int dl = n * 8 + (lane & 3) * 2;
                    const bool first = dl < 16;
                    const int np = first ? n + 2 : n - 2;
                    const float sign = first ? -1.0f : 1.0f;
                    const int fi0 = dl & 15, fi1 = (dl + 1) & 15;
                    const float2 c00 = *(const float2*)(rtab + (s0 * 16 + fi0) * 2);
                    const float2 c01 = *(const float2*)(rtab + (s0 * 16 + fi1) * 2);
                    const float2 c10 = *(const float2*)(rtab + (s1 * 16 + fi0) * 2);
                    const float2 c11 = *(const float2*)(rtab + (s1 * 16 + fi1) * 2);
                    rp[n][0] = v[n][0] * c00.x + sign * v[np][0] * c00.y;
                    rp[n][1] = v[n][1] * c01.x + sign * v[np][1] * c01.y;
                    rp[n][2] = v[n][2] * c10.x + sign * v[np][2] * c10.y;
                    rp[n][3] = v[n][3] * c11.x + sign * v[np][3] * c11.y;
                }
                #pragma unroll
                for (int n = 0; n < 4; ++n)
                    #pragma unroll
                    for (int q = 0; q < 4; ++q) v[n][q] = rp[n][q];
            }
            const size_t base0 = (((size_t)bb2 * HH + hh2) * SS + s0) * HD;
            const size_t base1 = (((size_t)bb2 * HH + hh2) * SS + s1) * HD;
            #pragma unroll
            for (int n = 0; n < 4; ++n) {
                const int d = dbase + n * 8 + (lane & 3) * 2;
                uint32_t hi, lo;
                packhl(v[n][0] * qsc, v[n][1] * qsc, hi, lo);
                *(uint32_t*)(Oh + base0 + d) = hi;
                *(uint32_t*)(Ol + base0 + d) = lo;
                packhl(v[n][2] * qsc, v[n][3] * qsc, hi, lo);
                *(uint32_t*)(Oh + base1 + d) = hi;
                *(uint32_t*)(Ol + base1 + d) = lo;
            }
        }
        return;
    }

    #pragma unroll
    for (int m = 0; m < 4; ++m) {
        const int r0 = row_base + m * 16 + (lane >> 2);
        #pragma unroll
        for (int n = 0; n < 4; ++n) {
            const int cc = col_base + n * 8 + (lane & 3) * 2;
            const float b0 = bias[cc], b1 = bias[cc + 1];
            float v0 = acc[m][n][0] + b0, v1 = acc[m][n][1] + b1;
            float v2 = acc[m][n][2] + b0, v3 = acc[m][n][3] + b1;
            const size_t off0 = (size_t)r0 * N + cc;
            const size_t off1 = (size_t)(r0 + 8) * N + cc;
            if (EPI == 1) {
                uint32_t hi, lo;
                packhl(gelu_exact(v0), gelu_exact(v1), hi, lo);
                *(uint32_t*)(Ch + off0) = hi;
                *(uint32_t*)(Cl + off0) = lo;
                packhl(gelu_exact(v2), gelu_exact(v3), hi, lo);
                *(uint32_t*)(Ch + off1) = hi;
                *(uint32_t*)(Cl + off1) = lo;
            } else {
                if (EPI == 4) {
                    const float2 x0 = *(const float2*)(add1 + off0);
                    const float2 x1 = *(const float2*)(add1 + off1);
                    v0 += x0.x; v1 += x0.y;
                    v2 += x1.x; v3 += x1.y;
                }
                *(float2*)(Cf + off0) = make_float2(v0, v1);
                *(float2*)(Cf + off1) = make_float2(v2, v3);
            }
        }
    }
}

// ---------------- causal flash attention via mma.sync, BQ=128 --------------
#define AST   136
#define ATILE (64 * AST * 2)
#define AQ_H  0
#define AQ_L  (2 * ATILE)
#define ASTAGE0 (4 * ATILE)
#define ASTG_B  (4 * ATILE)
#define A_SMEM  (4 * ATILE + 2 * ASTG_B)

__global__ void __launch_bounds__(256, 1) attn_mma_kernel(
    const bf16* __restrict__ Qh, const bf16* __restrict__ Ql,
    const bf16* __restrict__ Kh, const bf16* __restrict__ Kl,
    const bf16* __restrict__ Vh, const bf16* __restrict__ Vl,
    bf16* __restrict__ ctxh, bf16* __restrict__ ctxl) {
    extern __shared__ char sm[];
    const uint32_t smb = smem_u32(sm);
    const int qt = gridDim.x - 1 - blockIdx.x;
    const int bhid = blockIdx.y;
    const int b = bhid >> 4, h = bhid & 15;
    const int tid = threadIdx.x;
    const int lane = tid & 31;
    const int w = tid >> 5;

    const size_t headbase = (size_t)bhid * SS * HD;

    auto ldq = [&]() {
        const size_t gb = headbase + (size_t)qt * 128 * HD;
        #pragma unroll
        for (int i = 0; i < 8; i++) {
            const int c = tid + i * 256;
            const int row = c >> 4, ch = c & 15;
            const uint32_t so = row * (AST * 2) + ch * 16;
            const size_t go = gb + (size_t)row * HD + ch * 8;
            CP16(smb + AQ_H + so, Qh + go);
            CP16(smb + AQ_L + so, Ql + go);
        }
    };
    auto ldkv = [&](int kt, int stg) {
        const uint32_t sb = smb + ASTAGE0 + (uint32_t)stg * ASTG_B;
        const size_t gb = headbase + (size_t)kt * 64 * HD;
        #pragma unroll
        for (int i = 0; i < 4; i++) {
            const int c = tid + i * 256;
            const int row = c >> 4, ch = c & 15;
            const uint32_t so = row * (AST * 2) + ch * 16;
            const size_t go = gb + (size_t)row * HD + ch * 8;
            CP16(sb + so,             Kh + go);
            CP16(sb + ATILE + so,     Kl + go);
            CP16(sb + 2 * ATILE + so, Vh + go);
            CP16(sb + 3 * ATILE + so, Vl + go);
        }
    };

    const uint32_t qa_off = ((w * 16 + (lane & 15)) * AST + (lane >> 4) * 8) * 2;
    const int lm = lane >> 3, li = lane & 7;
    const uint32_t kb_off = (((lm >> 1) * 8 + li) * AST + (lm & 1) * 8) * 2;
    const uint32_t vb_off = (((lm & 1) * 8 + li) * AST + (lm >> 1) * 8) * 2;

    float oacc[16][4];
    #pragma unroll
    for (int t = 0; t < 16; t++)
        #pragma unroll
        for (int q = 0; q < 4; q++) oacc[t][q] = 0.f;
    float m0 = -1e30f, m1 = -1e30f, l0 = 0.f, l1 = 0.f;
    const int qrow0 = qt * 128 + w * 16 + (lane >> 2);
    const int qrow1 = qrow0 + 8;
    const int nkt = 2 * qt + 2;

    ldq();
    ldkv(0, 0);
    CP_COMMIT();

    for (int kt = 0; kt < nkt; ++kt) {
        if (kt + 1 < nkt) {
            ldkv(kt + 1, (kt + 1) & 1);
            CP_COMMIT();
            CP_WAIT1();
        } else {
            CP_WAIT0();
        }
        __syncthreads();
        const uint32_t sb = smb + ASTAGE0 + (uint32_t)(kt & 1) * ASTG_B;

        float sacc[8][4];
        #pragma unroll
        for (int j = 0; j < 8; j++)
            #pragma unroll
            for (int q = 0; q < 4; q++) sacc[j][q] = 0.f;

        #pragma unroll
        for (int ks = 0; ks < 8; ++ks) {
            uint32_t ah[4], al[4], kfh[8][2], kfl[8][2];
            ldm_x4(ah, smb + AQ_H + qa_off + ks * 32);
            ldm_x4(al, smb + AQ_L + qa_off + ks * 32);
            #pragma unroll
            for (int jp = 0; jp < 4; ++jp) {
                uint32_t r[4];
                ldm_x4(r, sb + kb_off + (jp * 16 * AST + ks * 16) * 2);
                kfh[2*jp][0] = r[0]; kfh[2*jp][1] = r[1];
                kfh[2*jp+1][0] = r[2]; kfh[2*jp+1][1] = r[3];
                ldm_x4(r, sb + ATILE + kb_off + (jp * 16 * AST + ks * 16) * 2);
                kfl[2*jp][0] = r[0]; kfl[2*jp][1] = r[1];
                kfl[2*jp+1][0] = r[2]; kfl[2*jp+1][1] = r[3];
            }
            #pragma unroll
            for (int j = 0; j < 8; ++j) mma_bf16(sacc[j], ah, kfh[j]);
            #pragma unroll
            for (int j = 0; j < 8; ++j) mma_bf16(sacc[j], al, kfh[j]);
            #pragma unroll
            for (int j = 0; j < 8; ++j) mma_bf16(sacc[j], ah, kfl[j]);
        }

        if (kt >= 2 * qt) {
            #pragma unroll
            for (int j = 0; j < 8; ++j) {
                const int c0 = kt * 64 + j * 8 + (lane & 3) * 2;
                if (c0     > qrow0) sacc[j][0] = -1e30f;
                if (c0 + 1 > qrow0) sacc[j][1] = -1e30f;
                if (c0     > qrow1) sacc[j][2] = -1e30f;
                if (c0 + 1 > qrow1) sacc[j][3] = -1e30f;
            }
        }

        float mx0 = -1e30f, mx1 = -1e30f;
        #pragma unroll
        for (int j = 0; j < 8; ++j) {
            mx0 = fmaxf(mx0, fmaxf(sacc[j][0], sacc[j][1]));
            mx1 = fmaxf(mx1, fmaxf(sacc[j][2], sacc[j][3]));
        }
        #pragma unroll
        for (int o = 1; o < 4; o <<= 1) {
            mx0 = fmaxf(mx0, __shfl_xor_sync(0xffffffffu, mx0, o));
            mx1 = fmaxf(mx1, __shfl_xor_sync(0xffffffffu, mx1, o));
        }
        const float mn0 = fmaxf(m0, mx0), mn1 = fmaxf(m1, mx1);
        const float e0 = __expf(m0 - mn0), e1 = __expf(m1 - mn1);
        m0 = mn0; m1 = mn1;
        float rs0 = 0.f, rs1 = 0.f;
        #pragma unroll
        for (int j = 0; j < 8; ++j) {
            sacc[j][0] = __expf(sacc[j][0] - mn0); rs0 += sacc[j][0];
            sacc[j][1] = __expf(sacc[j][1] - mn0); rs0 += sacc[j][1];
            sacc[j][2] = __expf(sacc[j][2] - mn1); rs1 += sacc[j][2];
            sacc[j][3] = __expf(sacc[j][3] - mn1); rs1 += sacc[j][3];
        }
        #pragma unroll
        for (int o = 1; o < 4; o <<= 1) {
            rs0 += __shfl_xor_sync(0xffffffffu, rs0, o);
            rs1 += __shfl_xor_sync(0xffffffffu, rs1, o);
        }
        l0 = l0 * e0 + rs0;
        l1 = l1 * e1 + rs1;
        #pragma unroll
        for (int t = 0; t < 16; t++) {
            oacc[t][0] *= e0; oacc[t][1] *= e0;
            oacc[t][2] *= e1; oacc[t][3] *= e1;
        }

        #pragma unroll
        for (int c = 0; c < 4; ++c) {
            uint32_t pah[4], pal[4];
            packhl(sacc[2*c][0],   sacc[2*c][1],   pah[0], pal[0]);
            packhl(sacc[2*c][2],   sacc[2*c][3],   pah[1], pal[1]);
            packhl(sacc[2*c+1][0], sacc[2*c+1][1], pah[2], pal[2]);
            packhl(sacc[2*c+1][2], sacc[2*c+1][3], pah[3], pal[3]);
            #pragma unroll
            for (int tp = 0; tp < 8; ++tp) {
                uint32_t rvh[4], rvl[4];
                ldm_x4_t(rvh, sb + 2 * ATILE + vb_off + (c * 16 * AST + tp * 16) * 2);
                ldm_x4_t(rvl, sb + 3 * ATILE + vb_off + (c * 16 * AST + tp * 16) * 2);
                mma_bf16(oacc[2*tp],   pah, &rvh[0]);
                mma_bf16(oacc[2*tp],   pal, &rvh[0]);
                mma_bf16(oacc[2*tp],   pah, &rvl[0]);
                mma_bf16(oacc[2*tp+1], pah, &rvh[2]);
                mma_bf16(oacc[2*tp+1], pal, &rvh[2]);
                mma_bf16(oacc[2*tp+1], pah, &rvl[2]);
            }
        }
        __syncthreads();
    }

    const float inv0 = 1.0f / l0, inv1 = 1.0f / l1;
    const size_t ob0 = ((size_t)b * SS + qrow0) * HID + h * HD;
    const size_t ob1 = ((size_t)b * SS + qrow1) * HID + h * HD;
    #pragma unroll
    for (int t = 0; t < 16; ++t) {
        const int d = t * 8 + (lane & 3) * 2;
        uint32_t hi, lo;
        packhl(oacc[t][0] * inv0, oacc[t][1] * inv0, hi, lo);
        *(uint32_t*)(ctxh + ob0 + d) = hi;
        *(uint32_t*)(ctxl + ob0 + d) = lo;
        packhl(oacc[t][2] * inv1, oacc[t][3] * inv1, hi, lo);
        *(uint32_t*)(ctxh + ob1 + d) = hi;
        *(uint32_t*)(ctxl + ob1 + d) = lo;
    }
}

// ---------------- launch (dense stream DAG; Wo last) ----------------
extern "C" void kernel_launch(void* const* d_in, const int* in_sizes, int n_in,
                              void* d_out, int out_size) {
    const float* hid   = (const float*)d_in[0];
    const float* ln1g  = (const float*)d_in[1];
    const float* ln1b  = (const float*)d_in[2];
    const float* ln2g  = (const float*)d_in[3];
    const float* ln2b  = (const float*)d_in[4];
    const float* Wqkv  = (const float*)d_in[5];
    const float* bqkv  = (const float*)d_in[6];
    const float* Wo    = (const float*)d_in[7];
    const float* bo    = (const float*)d_in[8];
    const float* Wfc   = (const float*)d_in[9];
    const float* bfc   = (const float*)d_in[10];
    const float* Wproj = (const float*)d_in[11];
    const float* bproj = (const float*)d_in[12];
    float* out = (float*)d_out;

    float *rope;
    bf16 *ln1h, *ln1l, *ln2h, *ln2l, *ctxh, *ctxl, *fch, *fcl;
    bf16 *Qh, *Ql, *Kh, *Kl, *Vh, *Vl;
    bf16 *wqkvh, *wqkvl, *woh, *wol, *wfch, *wfcl, *wprojh, *wprojl;
    cudaGetSymbolAddress((void**)&rope, g_rope);
    cudaGetSymbolAddress((void**)&ln1h, g_ln1h);
    cudaGetSymbolAddress((void**)&ln1l, g_ln1l);
    cudaGetSymbolAddress((void**)&ln2h, g_ln2h);
    cudaGetSymbolAddress((void**)&ln2l, g_ln2l);
    cudaGetSymbolAddress((void**)&ctxh, g_ctxh);
    cudaGetSymbolAddress((void**)&ctxl, g_ctxl);
    cudaGetSymbolAddress((void**)&fch, g_fch);
    cudaGetSymbolAddress((void**)&fcl, g_fcl);
    cudaGetSymbolAddress((void**)&Qh, g_Qh);
    cudaGetSymbolAddress((void**)&Ql, g_Ql);
    cudaGetSymbolAddress((void**)&Kh, g_Kh);
    cudaGetSymbolAddress((void**)&Kl, g_Kl);
    cudaGetSymbolAddress((void**)&Vh, g_Vh);
    cudaGetSymbolAddress((void**)&Vl, g_Vl);
    cudaGetSymbolAddress((void**)&wqkvh, g_wqkvh);
    cudaGetSymbolAddress((void**)&wqkvl, g_wqkvl);
    cudaGetSymbolAddress((void**)&woh, g_woh);
    cudaGetSymbolAddress((void**)&wol, g_wol);
    cudaGetSymbolAddress((void**)&wfch, g_wfch);
    cudaGetSymbolAddress((void**)&wfcl, g_wfcl);
    cudaGetSymbolAddress((void**)&wprojh, g_wprojh);
    cudaGetSymbolAddress((void**)&wprojl, g_wprojl);

    cudaFuncSetAttribute(mma_gemm<0>, cudaFuncAttributeMaxDynamicSharedMemorySize, G_SMEM);
    cudaFuncSetAttribute(mma_gemm<1>, cudaFuncAttributeMaxDynamicSharedMemorySize, G_SMEM);
    cudaFuncSetAttribute(mma_gemm<3>, cudaFuncAttributeMaxDynamicSharedMemorySize, G_SMEM);
    cudaFuncSetAttribute(mma_gemm<4>, cudaFuncAttributeMaxDynamicSharedMemorySize, G_SMEM);
    cudaFuncSetAttribute(attn_mma_kernel, cudaFuncAttributeMaxDynamicSharedMemorySize, A_SMEM);

    static cudaStream_t sB = nullptr, sC = nullptr;
    static cudaEvent_t evRoot = nullptr, evLn = nullptr, evWq = nullptr,
                       evWo = nullptr, evWp = nullptr, evPROJ = nullptr;
    if (!sB) {
        cudaStreamCreateWithFlags(&sB, cudaStreamNonBlocking);
        cudaStreamCreateWithFlags(&sC, cudaStreamNonBlocking);
        cudaEventCreateWithFlags(&evRoot, cudaEventDisableTiming);
        cudaEventCreateWithFlags(&evLn,   cudaEventDisableTiming);
        cudaEventCreateWithFlags(&evWq,   cudaEventDisableTiming);
        cudaEventCreateWithFlags(&evWo,   cudaEventDisableTiming);
        cudaEventCreateWithFlags(&evWp,   cudaEventDisableTiming);
        cudaEventCreateWithFlags(&evPROJ, cudaEventDisableTiming);
    }

    cudaEventRecord(evRoot, 0);
    cudaStreamWaitEvent(sB, evRoot, 0);
    cudaStreamWaitEvent(sC, evRoot, 0);

    // --- stream C: Wqkv, Wo, Wproj conversions ---
    wconv_kernel<<<dim3(3 * HID / 64, HID / 64), 256, 0, sC>>>(Wqkv, wqkvh, wqkvl, HID, 3 * HID);
    cudaEventRecord(evWq, sC);
    wconv_kernel<<<dim3(HID / 64, HID / 64), 256, 0, sC>>>(Wo, woh, wol, HID, HID);
    cudaEventRecord(evWo, sC);
    wconv_kernel<<<dim3(HID / 64, FF / 64),  256, 0, sC>>>(Wproj, wprojh, wprojl, FF, HID);
    cudaEventRecord(evWp, sC);

    // --- stream B: Wfc conversion, FC gemm, PROJ gemm ---
    wconv_kernel<<<dim3(FF / 64, HID / 64), 256, 0, sB>>>(Wfc, wfch, wfcl, HID, FF);

    // --- origin: ln (+rope table) ---
    ln_kernel<<<NTOK / 2, 512>>>(hid, ln1g, ln1b, ln2g, ln2b, ln1h, ln1l, ln2h, ln2l, rope);
    cudaEventRecord(evLn, 0);

    // stream B: FC = gelu(ln2 @ W_fc + b_fc)
    cudaStreamWaitEvent(sB, evLn, 0);
    mma_gemm<1><<<16 * (FF / 128), 512, G_SMEM, sB>>>(
        ln2h, ln2l, wfch, wfcl, bfc, nullptr, nullptr,
        nullptr, fch, fcl, nullptr, nullptr, nullptr, nullptr, FF, HID);
    // stream B: out = fc @ W_proj + b_proj + hid
    cudaStreamWaitEvent(sB, evWp, 0);
    mma_gemm<4><<<16 * (HID / 128), 512, G_SMEM, sB>>>(
        fch, fcl, wprojh, wprojl, bproj, hid, nullptr,
        out, nullptr, nullptr, nullptr, nullptr, nullptr, nullptr, HID, FF);
    cudaEventRecord(evPROJ, sB);

    // origin: QKV gemm + fused bias/RoPE/scale/head-transpose
    cudaStreamWaitEvent(0, evWq, 0);
    mma_gemm<3><<<16 * (3 * HID / 128), 512, G_SMEM>>>(
        ln1h, ln1l, wqkvh, wqkvl, bqkv, nullptr, rope,
        nullptr, Qh, Ql, Kh, Kl, Vh, Vl, 3 * HID, HID);

    // origin: attention
    attn_mma_kernel<<<dim3(SS / 128, BB * HH), 256, A_SMEM>>>(
        Qh, Ql, Kh, Kl, Vh, Vl, ctxh, ctxl);

    // origin: out += ctx @ W_o + b_o   (joins PROJ + Wo weights)
    cudaStreamWaitEvent(0, evWo, 0);
    cudaStreamWaitEvent(0, evPROJ, 0);
    mma_gemm<4><<<16 * (HID / 128), 512, G_SMEM>>>(
        ctxh, ctxl, woh, wol, bo, out, nullptr,
        out, nullptr, nullptr, nullptr, nullptr, nullptr, nullptr, HID, HID);
}

// round 12
// speedup vs baseline: 1.3426x; 1.2210x over previous
#include <cuda_runtime.h>
#include <cuda_bf16.h>
#include <cuda_fp16.h>
#include <cstdint>

// Problem constants
#define BB 2
#define SS 2048
#define HH 16
#define HD 128
#define HID 2048
#define FF 8192
#define NTOK 4096

typedef __nv_bfloat16 bf16;
typedef __half hf;

// ---------------- scratch (device globals; no allocation allowed) ----------
__device__ float g_rope[SS * 16 * 2];
__device__ bf16 g_ln1h[(size_t)NTOK * HID];
__device__ bf16 g_ln1l[(size_t)NTOK * HID];
__device__ hf   g_ln2h[(size_t)NTOK * HID];
__device__ hf   g_ln2l[(size_t)NTOK * HID];
__device__ bf16 g_ctxh[(size_t)NTOK * HID];
__device__ bf16 g_ctxl[(size_t)NTOK * HID];
__device__ hf   g_fch[(size_t)NTOK * FF];
__device__ hf   g_fcl[(size_t)NTOK * FF];
__device__ bf16 g_Qh[(size_t)NTOK * HID];
__device__ bf16 g_Ql[(size_t)NTOK * HID];
__device__ bf16 g_Kh[(size_t)NTOK * HID];
__device__ bf16 g_Kl[(size_t)NTOK * HID];
__device__ bf16 g_Vh[(size_t)NTOK * HID];
__device__ bf16 g_Vl[(size_t)NTOK * HID];
__device__ bf16 g_wqkvh[(size_t)3 * HID * HID];
__device__ bf16 g_wqkvl[(size_t)3 * HID * HID];
__device__ bf16 g_woh[(size_t)HID * HID];
__device__ bf16 g_wol[(size_t)HID * HID];
__device__ hf   g_wfch[(size_t)FF * HID];
__device__ hf   g_wprojh[(size_t)HID * FF];

// ---------------- helpers ----------------
__device__ __forceinline__ uint32_t smem_u32(const void* p) {
    uint32_t a;
    asm("{ .reg .u64 t; cvta.to.shared.u64 t, %1; cvt.u32.u64 %0, t; }" : "=r"(a) : "l"(p));
    return a;
}
#define CP16(dst, src) \
    asm volatile("cp.async.cg.shared.global [%0], [%1], 16;" :: "r"(dst), "l"(src) : "memory")
#define CP_COMMIT() asm volatile("cp.async.commit_group;" ::: "memory")
#define CP_WAIT1()  asm volatile("cp.async.wait_group 1;" ::: "memory")
#define CP_WAIT0()  asm volatile("cp.async.wait_group 0;" ::: "memory")

__device__ __forceinline__ void ldm_x4(uint32_t* r, uint32_t addr) {
    asm volatile("ldmatrix.sync.aligned.m8n8.x4.shared.b16 {%0,%1,%2,%3}, [%4];"
                 : "=r"(r[0]), "=r"(r[1]), "=r"(r[2]), "=r"(r[3]) : "r"(addr));
}
__device__ __forceinline__ void ldm_x4_t(uint32_t* r, uint32_t addr) {
    asm volatile("ldmatrix.sync.aligned.m8n8.x4.trans.shared.b16 {%0,%1,%2,%3}, [%4];"
                 : "=r"(r[0]), "=r"(r[1]), "=r"(r[2]), "=r"(r[3]) : "r"(addr));
}
__device__ __forceinline__ void mma_bf16(float* c, const uint32_t* a, const uint32_t* b) {
    asm volatile("mma.sync.aligned.m16n8k16.row.col.f32.bf16.bf16.f32 "
                 "{%0,%1,%2,%3},{%4,%5,%6,%7},{%8,%9},{%0,%1,%2,%3};"
                 : "+f"(c[0]), "+f"(c[1]), "+f"(c[2]), "+f"(c[3])
                 : "r"(a[0]), "r"(a[1]), "r"(a[2]), "r"(a[3]), "r"(b[0]), "r"(b[1]));
}
__device__ __forceinline__ void mma_f16(float* c, const uint32_t* a, const uint32_t* b) {
    asm volatile("mma.sync.aligned.m16n8k16.row.col.f32.f16.f16.f32 "
                 "{%0,%1,%2,%3},{%4,%5,%6,%7},{%8,%9},{%0,%1,%2,%3};"
                 : "+f"(c[0]), "+f"(c[1]), "+f"(c[2]), "+f"(c[3])
                 : "r"(a[0]), "r"(a[1]), "r"(a[2]), "r"(a[3]), "r"(b[0]), "r"(b[1]));
}
__device__ __forceinline__ void split_bf16(float v, bf16& h, bf16& l) {
    h = __float2bfloat16(v);
    l = __float2bfloat16(v - __bfloat162float(h));
}
__device__ __forceinline__ void split_hf(float v, hf& h, hf& l) {
    h = __float2half_rn(v);
    l = __float2half_rn(v - __half2float(h));
}
__device__ __forceinline__ void packhl(float a, float b, uint32_t& hi, uint32_t& lo) {
    __nv_bfloat162 hv, lv;
    split_bf16(a, hv.x, lv.x);
    split_bf16(b, hv.y, lv.y);
    hi = *(uint32_t*)&hv;
    lo = *(uint32_t*)&lv;
}
__device__ __forceinline__ void packhl_h(float a, float b, uint32_t& hi, uint32_t& lo) {
    __half2 hv, lv;
    hf h, l;
    split_hf(a, h, l); hv.x = h; lv.x = l;
    split_hf(b, h, l); hv.y = h; lv.y = l;
    hi = *(uint32_t*)&hv;
    lo = *(uint32_t*)&lv;
}
__device__ __forceinline__ float gelu_exact(float v) {
    return 0.5f * v * (1.0f + erff(v * 0.70710678118654752f));
}

// ------- fused double layernorm (2 rows/block) + RoPE table ----------------
// ln1 -> bf16 hi/lo (for QKV), ln2 -> fp16 hi/lo (for FC)
__global__ void ln_kernel(const float* __restrict__ x,
                          const float* __restrict__ g1, const float* __restrict__ b1,
                          const float* __restrict__ g2, const float* __restrict__ b2,
                          bf16* __restrict__ o1h, bf16* __restrict__ o1l,
                          hf* __restrict__ o2h, hf* __restrict__ o2l,
                          float* __restrict__ rtab) {
    __shared__ float redS[16];
    __shared__ float redQ[16];
    const int t = threadIdx.x;
    const int half_ = t >> 8;
    const int tt = t & 255;
    const int row = blockIdx.x * 2 + half_;

    if (blockIdx.x < 64) {
        const int i = blockIdx.x * 512 + t;
        const int s = i >> 4, fi = i & 15;
        const float inv = powf(10000.0f, -(float)fi * (1.0f / 16.0f));
        float sn, cs;
        sincosf((float)s * inv, &sn, &cs);
        rtab[i * 2]     = cs;
        rtab[i * 2 + 1] = sn;
    }

    const float* xr = x + (size_t)row * HID;
    float4 a = *(const float4*)(xr + tt * 8);
    float4 b = *(const float4*)(xr + tt * 8 + 4);
    float s  = a.x + a.y + a.z + a.w + b.x + b.y + b.z + b.w;
    float ss = a.x*a.x + a.y*a.y + a.z*a.z + a.w*a.w
             + b.x*b.x + b.y*b.y + b.z*b.z + b.w*b.w;
    #pragma unroll
    for (int o = 16; o; o >>= 1) {
        s  += __shfl_xor_sync(0xffffffffu, s,  o);
        ss += __shfl_xor_sync(0xffffffffu, ss, o);
    }
    if ((t & 31) == 0) { redS[t >> 5] = s; redQ[t >> 5] = ss; }
    __syncthreads();
    s = 0.f; ss = 0.f;
    #pragma unroll
    for (int i = 0; i < 8; i++) { s += redS[half_ * 8 + i]; ss += redQ[half_ * 8 + i]; }
    const float mu  = s * (1.0f / HID);
    const float var = ss * (1.0f / HID) - mu * mu;
    const float rs  = rsqrtf(var + 1e-5f);

    float vals[8] = {a.x,a.y,a.z,a.w,b.x,b.y,b.z,b.w};
    __align__(16) bf16 h1[8], l1[8];
    __align__(16) hf h2[8], l2[8];
    #pragma unroll
    for (int q = 0; q < 8; q++) {
        const int col = tt * 8 + q;
        const float xn = (vals[q] - mu) * rs;
        split_bf16(xn * g1[col] + b1[col], h1[q], l1[q]);
        split_hf(xn * g2[col] + b2[col], h2[q], l2[q]);
    }
    const size_t off = (size_t)row * HID + tt * 8;
    *(uint4*)(o1h + off) = *(uint4*)h1;
    *(uint4*)(o1l + off) = *(uint4*)l1;
    *(uint4*)(o2h + off) = *(uint4*)h2;
    *(uint4*)(o2l + off) = *(uint4*)l2;
}

// ------- weight convert + transpose (bf16 hi/lo): W[K][N] -> T{h,l}[N][K] --
__global__ void wconv_kernel(const float* __restrict__ W, bf16* __restrict__ Th,
                             bf16* __restrict__ Tl, int K, int N) {
    __shared__ float tile[64][65];
    const int n0 = blockIdx.x * 64, k0 = blockIdx.y * 64;
    const int tid = threadIdx.x;
    {
        const int r = tid >> 4, c = (tid & 15) * 4;
        #pragma unroll
        for (int i = 0; i < 4; i++) {
            const float4 v = *(const float4*)(W + (size_t)(k0 + r + 16 * i) * N + n0 + c);
            tile[r + 16 * i][c]     = v.x;
            tile[r + 16 * i][c + 1] = v.y;
            tile[r + 16 * i][c + 2] = v.z;
            tile[r + 16 * i][c + 3] = v.w;
        }
    }
    __syncthreads();
    #pragma unroll
    for (int it = 0; it < 2; ++it) {
        const int idx = tid + it * 256;
        const int n = idx >> 3, kc = (idx & 7) * 8;
        __align__(16) bf16 h[8], l[8];
        #pragma unroll
        for (int j = 0; j < 8; j++)
            split_bf16(tile[kc + j][n], h[j], l[j]);
        const size_t o = (size_t)(n0 + n) * K + k0 + kc;
        *(uint4*)(Th + o) = *(uint4*)h;
        *(uint4*)(Tl + o) = *(uint4*)l;
    }
}

// ------- weight convert + transpose (fp16 hi only): W[K][N] -> Th[N][K] ----
__global__ void wconv_h_kernel(const float* __restrict__ W, hf* __restrict__ Th,
                               int K, int N) {
    __shared__ float tile[64][65];
    const int n0 = blockIdx.x * 64, k0 = blockIdx.y * 64;
    const int tid = threadIdx.x;
    {
        const int r = tid >> 4, c = (tid & 15) * 4;
        #pragma unroll
        for (int i = 0; i < 4; i++) {
            const float4 v = *(const float4*)(W + (size_t)(k0 + r + 16 * i) * N + n0 + c);
            tile[r + 16 * i][c]     = v.x;
            tile[r + 16 * i][c + 1] = v.y;
            tile[r + 16 * i][c + 2] = v.z;
            tile[r + 16 * i][c + 3] = v.w;
        }
    }
    __syncthreads();
    #pragma unroll
    for (int it = 0; it < 2; ++it) {
        const int idx = tid + it * 256;
        const int n = idx >> 3, kc = (idx & 7) * 8;
        __align__(16) hf h[8];
        #pragma unroll
        for (int j = 0; j < 8; j++)
            h[j] = __float2half_rn(tile[kc + j][n]);
        const size_t o = (size_t)(n0 + n) * K + k0 + kc;
        *(uint4*)(Th + o) = *(uint4*)h;
    }
}

// ------------ bf16-split GEMM (3-pass), CTA 256x128, BK=64, 512 thr --------
#define ROWP   72
#define A_ARR  36864u
#define B_ARR  18432u
#define STG_B  110592u
#define G_SMEM (2u * STG_B)

// EPI: 3 qkv fused | 4 +bias+add1->f32
template <int EPI>
__global__ void __launch_bounds__(512, 1) mma_gemm(
    const bf16* __restrict__ Ah, const bf16* __restrict__ Al,
    const bf16* __restrict__ Bh, const bf16* __restrict__ Bl,
    const float* __restrict__ bias,
    const float* __restrict__ add1,
    const float* __restrict__ rtab,
    float* __restrict__ Cf,
    bf16* __restrict__ Ch, bf16* __restrict__ Cl,
    bf16* __restrict__ o2h, bf16* __restrict__ o2l,
    bf16* __restrict__ o3h, bf16* __restrict__ o3l,
    int N, int K) {
    extern __shared__ char sm[];
    const uint32_t smb = smem_u32(sm);
    const int tid = threadIdx.x;
    const int lane = tid & 31;
    const int warp = tid >> 5;
    const int wm = warp >> 2;
    const int wn = warp & 3;

    const int Nt = N >> 7;
    const int pid = blockIdx.x;
    const int mt = (pid / (8 * Nt)) * 8 + (pid & 7);
    const int nt = (pid % (8 * Nt)) >> 3;

    const size_t arow0 = (size_t)mt * 256;
    const size_t brow0 = (size_t)nt * 128;
    const bf16* pa_h = Ah + arow0 * K;
    const bf16* pa_l = Al + arow0 * K;
    const bf16* pb_h = Bh + brow0 * K;
    const bf16* pb_l = Bl + brow0 * K;
    const int nch = K >> 6;

    const uint32_t aoff = ((wm * 64 + (lane & 15)) * ROWP + (lane >> 4) * 8) * 2;
    const uint32_t boff = ((wn * 32 + (lane & 7) + ((lane >> 4) & 1) * 8) * ROWP
                           + ((lane >> 3) & 1) * 8) * 2;

    float acc[4][4][4];
    #pragma unroll
    for (int m = 0; m < 4; m++)
        #pragma unroll
        for (int n = 0; n < 4; n++)
            #pragma unroll
            for (int q = 0; q < 4; q++) acc[m][n][q] = 0.f;

    auto load_stage = [&](int stg, int k0) {
        const uint32_t sb = smb + (uint32_t)stg * STG_B;
        #pragma unroll
        for (int i = 0; i < 4; ++i) {
            const int id = tid + i * 512;
            const int row = id >> 3, cc = id & 7;
            const uint32_t so = (uint32_t)(row * ROWP + cc * 8) * 2;
            const size_t go = (size_t)row * K + k0 + cc * 8;
            CP16(sb + so,         pa_h + go);
            CP16(sb + A_ARR + so, pa_l + go);
        }
        #pragma unroll
        for (int i = 0; i < 2; ++i) {
            const int id = tid + i * 512;
            const int row = id >> 3, cc = id & 7;
            const uint32_t so = (uint32_t)(row * ROWP + cc * 8) * 2;
            const size_t go = (size_t)row * K + k0 + cc * 8;
            CP16(sb + 2 * A_ARR + so,         pb_h + go);
            CP16(sb + 2 * A_ARR + B_ARR + so, pb_l + go);
        }
    };

    load_stage(0, 0);
    CP_COMMIT();

    for (int c = 0; c < nch; ++c) {
        CP_WAIT0();
        __syncthreads();
        if (c + 1 < nch) {
            load_stage((c + 1) & 1, (c + 1) << 6);
            CP_COMMIT();
        }
        const uint32_t sb = smb + (uint32_t)(c & 1) * STG_B;
        #pragma unroll
        for (int ks = 0; ks < 4; ++ks) {
            const uint32_t kb = ks * 32;
            uint32_t ah[4][4], bh[2][4];
            #pragma unroll
            for (int i = 0; i < 4; ++i)
                ldm_x4(ah[i], sb + aoff + kb + i * 16 * ROWP * 2);
            #pragma unroll
            for (int t2 = 0; t2 < 2; ++t2)
                ldm_x4(bh[t2], sb + 2 * A_ARR + boff + kb + t2 * 16 * ROWP * 2);
            #pragma unroll
            for (int m = 0; m < 4; ++m)
                #pragma unroll
                for (int n = 0; n < 4; ++n)
                    mma_bf16(acc[m][n], ah[m], &bh[n >> 1][(n & 1) * 2]);
            {
                uint32_t al[4][4];
                #pragma unroll
                for (int i = 0; i < 4; ++i)
                    ldm_x4(al[i], sb + A_ARR + aoff + kb + i * 16 * ROWP * 2);
                #pragma unroll
                for (int m = 0; m < 4; ++m)
                    #pragma unroll
                    for (int n = 0; n < 4; ++n)
                        mma_bf16(acc[m][n], al[m], &bh[n >> 1][(n & 1) * 2]);
            }
            {
                uint32_t bl[2][4];
                #pragma unroll
                for (int t2 = 0; t2 < 2; ++t2)
                    ldm_x4(bl[t2], sb + 2 * A_ARR + B_ARR + boff + kb + t2 * 16 * ROWP * 2);
                #pragma unroll
                for (int m = 0; m < 4; ++m)
                    #pragma unroll
                    for (int n = 0; n < 4; ++n)
                        mma_bf16(acc[m][n], ah[m], &bl[n >> 1][(n & 1) * 2]);
            }
        }
    }

    // ---------------- epilogue ----------------
    const int row_base = mt * 256 + wm * 64;
    const int col_base = nt * 128 + wn * 32;

    if (EPI == 3) {
        const int hh2 = col_base / 384;
        const int sub0 = col_base % 384;
        const int sect = sub0 >> 7;
        const int dbase = sub0 & 127;
        const bool ropeW = (dbase == 0) && (sect < 2);
        const float qsc = (sect == 0) ? 0.08838834764831845f : 1.0f;
        bf16* Oh = (sect == 0) ? Ch : (sect == 1) ? o2h : o3h;
        bf16* Ol = (sect == 0) ? Cl : (sect == 1) ? o2l : o3l;
        #pragma unroll
        for (int m = 0; m < 4; ++m) {
            const int r0 = row_base + m * 16 + (lane >> 2);
            const int r1 = r0 + 8;
            const int bb2 = r0 >> 11;
            const int s0 = r0 & (SS - 1), s1 = r1 & (SS - 1);
            float v[4][4];
            #pragma unroll
            for (int n = 0; n < 4; ++n) {
                const int cc = col_base + n * 8 + (lane & 3) * 2;
                const float b0 = bias[cc], b1 = bias[cc + 1];
                v[n][0] = acc[m][n][0] + b0; v[n][1] = acc[m][n][1] + b1;
                v[n][2] = acc[m][n][2] + b0; v[n][3] = acc[m][n][3] + b1;
            }
            if (ropeW) {
                float rp[4][4];
                #pragma unroll
                for (int n = 0; n < 4; ++n) {
                    const int dl = n * 8 + (lane & 3) * 2;
                    const bool first = dl < 16;
                    const int np = first ? n + 2 : n - 2;
                    const float sign = first ? -1.0f : 1.0f;
                    const int fi0 = dl & 15, fi1 = (dl + 1) & 15;
                    const float2 c00 = *(const float2*)(rtab + (s0 * 16 + fi0) * 2);
                    const float2 c01 = *(const float2*)(rtab + (s0 * 16 + fi1) * 2);
                    const float2 c10 = *(const float2*)(rtab + (s1 * 16 + fi0) * 2);
                    const float2 c11 = *(const float2*)(rtab + (s1 * 16 + fi1) * 2);
                    rp[n][0] = v[n][0] * c00.x + sign * v[np][0] * c00.y;
                    rp[n][1] = v[n][1] * c01.x + sign * v[np][1] * c01.y;
                    rp[n][2] = v[n][2] * c10.x + sign * v[np][2] * c10.y;
                    rp[n][3] = v[n][3] * c11.x + sign * v[np][3] * c11.y;
                }
                #pragma unroll
                for (int n = 0; n < 4; ++n)
                    #pragma unroll
                    for (int q = 0; q < 4; ++q) v[n][q] = rp[n][q];
            }
            const size_t base0 = (((size_t)bb2 * HH + hh2) * SS + s0) * HD;
            const size_t base1 = (((size_t)bb2 * HH + hh2) * SS + s1) * HD;
            #pragma unroll
            for (int n = 0; n < 4; ++n) {
                const int d = dbase + n * 8 + (lane & 3) * 2;
                uint32_t hi, lo;
                packhl(v[n][0] * qsc, v[n][1] * qsc, hi, lo);
                *(uint32_t*)(Oh + base0 + d) = hi;
                *(uint32_t*)(Ol + base0 + d) = lo;
                packhl(v[n][2] * qsc, v[n][3] * qsc, hi, lo);
                *(uint32_t*)(Oh + base1 + d) = hi;
                *(uint32_t*)(Ol + base1 + d) = lo;
            }
        }
        return;
    }

    #pragma unroll
    for (int m = 0; m < 4; ++m) {
        const int r0 = row_base + m * 16 + (lane >> 2);
        #pragma unroll
        for (int n = 0; n < 4; ++n) {
            const int cc = col_base + n * 8 + (lane & 3) * 2;
            const float b0 = bias[cc], b1 = bias[cc + 1];
            float v0 = acc[m][n][0] + b0, v1 = acc[m][n][1] + b1;
            float v2 = acc[m][n][2] + b0, v3 = acc[m][n][3] + b1;
            const size_t off0 = (size_t)r0 * N + cc;
            const size_t off1 = (size_t)(r0 + 8) * N + cc;
            if (EPI == 4) {
                const float2 x0 = *(const float2*)(add1 + off0);
                const float2 x1 = *(const float2*)(add1 + off1);
                v0 += x0.x; v1 += x0.y;
                v2 += x1.x; v3 += x1.y;
            }
            *(float2*)(Cf + off0) = make_float2(v0, v1);
            *(float2*)(Cf + off1) = make_float2(v2, v3);
        }
    }
}

// ------------ fp16-split GEMM (2-pass), CTA 256x128, BK=64, 512 thr --------
// D = Ah*Bh + Al*Bh  (B = fp16-rounded weights, hi only)
#define H_STG  (2u * A_ARR + B_ARR)     // 92160
#define H_SMEM (2u * H_STG)             // 184320

// EPI: 1 gelu(+bias)->fp16 h/l | 4 +bias+add1->f32
template <int EPI>
__global__ void __launch_bounds__(512, 1) mma_gemm_h(
    const hf* __restrict__ Ah, const hf* __restrict__ Al,
    const hf* __restrict__ Bh,
    const float* __restrict__ bias,
    const float* __restrict__ add1,
    float* __restrict__ Cf, hf* __restrict__ Ch, hf* __restrict__ Cl,
    int N, int K) {
    extern __shared__ char sm[];
    const uint32_t smb = smem_u32(sm);
    const int tid = threadIdx.x;
    const int lane = tid & 31;
    const int warp = tid >> 5;
    const int wm = warp >> 2;
    const int wn = warp & 3;

    const int Nt = N >> 7;
    const int pid = blockIdx.x;
    const int mt = (pid / (8 * Nt)) * 8 + (pid & 7);
    const int nt = (pid % (8 * Nt)) >> 3;

    const size_t arow0 = (size_t)mt * 256;
    const size_t brow0 = (size_t)nt * 128;
    const hf* pa_h = Ah + arow0 * K;
    const hf* pa_l = Al + arow0 * K;
    const hf* pb_h = Bh + brow0 * K;
    const int nch = K >> 6;

    const uint32_t aoff = ((wm * 64 + (lane & 15)) * ROWP + (lane >> 4) * 8) * 2;
    const uint32_t boff = ((wn * 32 + (lane & 7) + ((lane >> 4) & 1) * 8) * ROWP
                           + ((lane >> 3) & 1) * 8) * 2;

    float acc[4][4][4];
    #pragma unroll
    for (int m = 0; m < 4; m++)
        #pragma unroll
        for (int n = 0; n < 4; n++)
            #pragma unroll
            for (int q = 0; q < 4; q++) acc[m][n][q] = 0.f;

    auto load_stage = [&](int stg, int k0) {
        const uint32_t sb = smb + (uint32_t)stg * H_STG;
        #pragma unroll
        for (int i = 0; i < 4; ++i) {
            const int id = tid + i * 512;
            const int row = id >> 3, cc = id & 7;
            const uint32_t so = (uint32_t)(row * ROWP + cc * 8) * 2;
            const size_t go = (size_t)row * K + k0 + cc * 8;
            CP16(sb + so,         pa_h + go);
            CP16(sb + A_ARR + so, pa_l + go);
        }
        #pragma unroll
        for (int i = 0; i < 2; ++i) {
            const int id = tid + i * 512;
            const int row = id >> 3, cc = id & 7;
            const uint32_t so = (uint32_t)(row * ROWP + cc * 8) * 2;
            const size_t go = (size_t)row * K + k0 + cc * 8;
            CP16(sb + 2 * A_ARR + so, pb_h + go);
        }
    };

    load_stage(0, 0);
    CP_COMMIT();

    for (int c = 0; c < nch; ++c) {
        CP_WAIT0();
        __syncthreads();
        if (c + 1 < nch) {
            load_stage((c + 1) & 1, (c + 1) << 6);
            CP_COMMIT();
        }
        const uint32_t sb = smb + (uint32_t)(c & 1) * H_STG;
        #pragma unroll
        for (int ks = 0; ks < 4; ++ks) {
            const uint32_t kb = ks * 32;
            uint32_t ah[4][4], bh[2][4];
            #pragma unroll
            for (int i = 0; i < 4; ++i)
                ldm_x4(ah[i], sb + aoff + kb + i * 16 * ROWP * 2);
            #pragma unroll
            for (int t2 = 0; t2 < 2; ++t2)
                ldm_x4(bh[t2], sb + 2 * A_ARR + boff + kb + t2 * 16 * ROWP * 2);
            #pragma unroll
            for (int m = 0; m < 4; ++m)
                #pragma unroll
                for (int n = 0; n < 4; ++n)
                    mma_f16(acc[m][n], ah[m], &bh[n >> 1][(n & 1) * 2]);
            {
                uint32_t al[4][4];
                #pragma unroll
                for (int i = 0; i < 4; ++i)
                    ldm_x4(al[i], sb + A_ARR + aoff + kb + i * 16 * ROWP * 2);
                #pragma unroll
                for (int m = 0; m < 4; ++m)
                    #pragma unroll
                    for (int n = 0; n < 4; ++n)
                        mma_f16(acc[m][n], al[m], &bh[n >> 1][(n & 1) * 2]);
            }
        }
    }

    // ---------------- epilogue ----------------
    const int row_base = mt * 256 + wm * 64;
    const int col_base = nt * 128 + wn * 32;

    #pragma unroll
    for (int m = 0; m < 4; ++m) {
        const int r0 = row_base + m * 16 + (lane >> 2);
        #pragma unroll
        for (int n = 0; n < 4; ++n) {
            const int cc = col_base + n * 8 + (lane & 3) * 2;
            const float b0 = bias[cc], b1 = bias[cc + 1];
            float v0 = acc[m][n][0] + b0, v1 = acc[m][n][1] + b1;
            float v2 = acc[m][n][2] + b0, v3 = acc[m][n][3] + b1;
            const size_t off0 = (size_t)r0 * N + cc;
            const size_t off1 = (size_t)(r0 + 8) * N + cc;
            if (EPI == 1) {
                uint32_t hi, lo;
                packhl_h(gelu_exact(v0), gelu_exact(v1), hi, lo);
                *(uint32_t*)(Ch + off0) = hi;
                *(uint32_t*)(Cl + off0) = lo;
                packhl_h(gelu_exact(v2), gelu_exact(v3), hi, lo);
                *(uint32_t*)(Ch + off1) = hi;
                *(uint32_t*)(Cl + off1) = lo;
            } else {
                const float2 x0 = *(const float2*)(add1 + off0);
                const float2 x1 = *(const float2*)(add1 + off1);
                v0 += x0.x; v1 += x0.y;
                v2 += x1.x; v3 += x1.y;
                *(float2*)(Cf + off0) = make_float2(v0, v1);
                *(float2*)(Cf + off1) = make_float2(v2, v3);
            }
        }
    }
}

// ---------------- causal flash attention via mma.sync, BQ=128 --------------
#define AST   136
#define ATILE (64 * AST * 2)
#define AQ_H  0
#define AQ_L  (2 * ATILE)
#define ASTAGE0 (4 * ATILE)
#define ASTG_B  (4 * ATILE)
#define A_SMEM  (4 * ATILE + 2 * ASTG_B)

__global__ void __launch_bounds__(256, 1) attn_mma_kernel(
    const bf16* __restrict__ Qh, const bf16* __restrict__ Ql,
    const bf16* __restrict__ Kh, const bf16* __restrict__ Kl,
    const bf16* __restrict__ Vh, const bf16* __restrict__ Vl,
    bf16* __restrict__ ctxh, bf16* __restrict__ ctxl) {
    extern __shared__ char sm[];
    const uint32_t smb = smem_u32(sm);
    const int qt = gridDim.x - 1 - blockIdx.x;
    const int bhid = blockIdx.y;
    const int b = bhid >> 4, h = bhid & 15;
    const int tid = threadIdx.x;
    const int lane = tid & 31;
    const int w = tid >> 5;

    const size_t headbase = (size_t)bhid * SS * HD;

    auto ldq = [&]() {
        const size_t gb = headbase + (size_t)qt * 128 * HD;
        #pragma unroll
        for (int i = 0; i < 8; i++) {
            const int c = tid + i * 256;
            const int row = c >> 4, ch = c & 15;
            const uint32_t so = row * (AST * 2) + ch * 16;
            const size_t go = gb + (size_t)row * HD + ch * 8;
            CP16(smb + AQ_H + so, Qh + go);
            CP16(smb + AQ_L + so, Ql + go);
        }
    };
    auto ldkv = [&](int kt, int stg) {
        const uint32_t sb = smb + ASTAGE0 + (uint32_t)stg * ASTG_B;
        const size_t gb = headbase + (size_t)kt * 64 * HD;
        #pragma unroll
        for (int i = 0; i < 4; i++) {
            const int c = tid + i * 256;
            const int row = c >> 4, ch = c & 15;
            const uint32_t so = row * (AST * 2) + ch * 16;
            const size_t go = gb + (size_t)row * HD + ch * 8;
            CP16(sb + so,             Kh + go);
            CP16(sb + ATILE + so,     Kl + go);
            CP16(sb + 2 * ATILE + so, Vh + go);
            CP16(sb + 3 * ATILE + so, Vl + go);
        }
    };

    const uint32_t qa_off = ((w * 16 + (lane & 15)) * AST + (lane >> 4) * 8) * 2;
    const int lm = lane >> 3, li = lane & 7;
    const uint32_t kb_off = (((lm >> 1) * 8 + li) * AST + (lm & 1) * 8) * 2;
    const uint32_t vb_off = (((lm & 1) * 8 + li) * AST + (lm >> 1) * 8) * 2;

    float oacc[16][4];
    #pragma unroll
    for (int t = 0; t < 16; t++)
        #pragma unroll
        for (int q = 0; q < 4; q++) oacc[t][q] = 0.f;
    float m0 = -1e30f, m1 = -1e30f, l0 = 0.f, l1 = 0.f;
    const int qrow0 = qt * 128 + w * 16 + (lane >> 2);
    const int qrow1 = qrow0 + 8;
    const int nkt = 2 * qt + 2;

    ldq();
    ldkv(0, 0);
    CP_COMMIT();

    for (int kt = 0; kt < nkt; ++kt) {
        if (kt + 1 < nkt) {
            ldkv(kt + 1, (kt + 1) & 1);
            CP_COMMIT();
            CP_WAIT1();
        } else {
            CP_WAIT0();
        }
        __syncthreads();
        const uint32_t sb = smb + ASTAGE0 + (uint32_t)(kt & 1) * ASTG_B;

        float sacc[8][4];
        #pragma unroll
        for (int j = 0; j < 8; j++)
            #pragma unroll
            for (int q = 0; q < 4; q++) sacc[j][q] = 0.f;

        #pragma unroll
        for (int ks = 0; ks < 8; ++ks) {
            uint32_t ah[4], al[4], kfh[8][2], kfl[8][2];
            ldm_x4(ah, smb + AQ_H + qa_off + ks * 32);
            ldm_x4(al, smb + AQ_L + qa_off + ks * 32);
            #pragma unroll
            for (int jp = 0; jp < 4; ++jp) {
                uint32_t r[4];
                ldm_x4(r, sb + kb_off + (jp * 16 * AST + ks * 16) * 2);
                kfh[2*jp][0] = r[0]; kfh[2*jp][1] = r[1];
                kfh[2*jp+1][0] = r[2]; kfh[2*jp+1][1] = r[3];
                ldm_x4(r, sb + ATILE + kb_off + (jp * 16 * AST + ks * 16) * 2);
                kfl[2*jp][0] = r[0]; kfl[2*jp][1] = r[1];
                kfl[2*jp+1][0] = r[2]; kfl[2*jp+1][1] = r[3];
            }
            #pragma unroll
            for (int j = 0; j < 8; ++j) mma_bf16(sacc[j], ah, kfh[j]);
            #pragma unroll
            for (int j = 0; j < 8; ++j) mma_bf16(sacc[j], al, kfh[j]);
            #pragma unroll
            for (int j = 0; j < 8; ++j) mma_bf16(sacc[j], ah, kfl[j]);
        }

        if (kt >= 2 * qt) {
            #pragma unroll
            for (int j = 0; j < 8; ++j) {
                const int c0 = kt * 64 + j * 8 + (lane & 3) * 2;
                if (c0     > qrow0) sacc[j][0] = -1e30f;
                if (c0 + 1 > qrow0) sacc[j][1] = -1e30f;
                if (c0     > qrow1) sacc[j][2] = -1e30f;
                if (c0 + 1 > qrow1) sacc[j][3] = -1e30f;
            }
        }

        float mx0 = -1e30f, mx1 = -1e30f;
        #pragma unroll
        for (int j = 0; j < 8; ++j) {
            mx0 = fmaxf(mx0, fmaxf(sacc[j][0], sacc[j][1]));
            mx1 = fmaxf(mx1, fmaxf(sacc[j][2], sacc[j][3]));
        }
        #pragma unroll
        for (int o = 1; o < 4; o <<= 1) {
            mx0 = fmaxf(mx0, __shfl_xor_sync(0xffffffffu, mx0, o));
            mx1 = fmaxf(mx1, __shfl_xor_sync(0xffffffffu, mx1, o));
        }
        const float mn0 = fmaxf(m0, mx0), mn1 = fmaxf(m1, mx1);
        const float e0 = __expf(m0 - mn0), e1 = __expf(m1 - mn1);
        m0 = mn0; m1 = mn1;
        float rs0 = 0.f, rs1 = 0.f;
        #pragma unroll
        for (int j = 0; j < 8; ++j) {
            sacc[j][0] = __expf(sacc[j][0] - mn0); rs0 += sacc[j][0];
            sacc[j][1] = __expf(sacc[j][1] - mn0); rs0 += sacc[j][1];
            sacc[j][2] = __expf(sacc[j][2] - mn1); rs1 += sacc[j][2];
            sacc[j][3] = __expf(sacc[j][3] - mn1); rs1 += sacc[j][3];
        }
        #pragma unroll
        for (int o = 1; o < 4; o <<= 1) {
            rs0 += __shfl_xor_sync(0xffffffffu, rs0, o);
            rs1 += __shfl_xor_sync(0xffffffffu, rs1, o);
        }
        l0 = l0 * e0 + rs0;
        l1 = l1 * e1 + rs1;
        #pragma unroll
        for (int t = 0; t < 16; t++) {
            oacc[t][0] *= e0; oacc[t][1] *= e0;
            oacc[t][2] *= e1; oacc[t][3] *= e1;
        }

        #pragma unroll
        for (int c = 0; c < 4; ++c) {
            uint32_t pah[4], pal[4];
            packhl(sacc[2*c][0],   sacc[2*c][1],   pah[0], pal[0]);
            packhl(sacc[2*c][2],   sacc[2*c][3],   pah[1], pal[1]);
            packhl(sacc[2*c+1][0], sacc[2*c+1][1], pah[2], pal[2]);
            packhl(sacc[2*c+1][2], sacc[2*c+1][3], pah[3], pal[3]);
            #pragma unroll
            for (int tp = 0; tp < 8; ++tp) {
                uint32_t rvh[4], rvl[4];
                ldm_x4_t(rvh, sb + 2 * ATILE + vb_off + (c * 16 * AST + tp * 16) * 2);
                ldm_x4_t(rvl, sb + 3 * ATILE + vb_off + (c * 16 * AST + tp * 16) * 2);
                mma_bf16(oacc[2*tp],   pah, &rvh[0]);
                mma_bf16(oacc[2*tp],   pal, &rvh[0]);
                mma_bf16(oacc[2*tp],   pah, &rvl[0]);
                mma_bf16(oacc[2*tp+1], pah, &rvh[2]);
                mma_bf16(oacc[2*tp+1], pal, &rvh[2]);
                mma_bf16(oacc[2*tp+1], pah, &rvl[2]);
            }
        }
        __syncthreads();
    }

    const float inv0 = 1.0f / l0, inv1 = 1.0f / l1;
    const size_t ob0 = ((size_t)b * SS + qrow0) * HID + h * HD;
    const size_t ob1 = ((size_t)b * SS + qrow1) * HID + h * HD;
    #pragma unroll
    for (int t = 0; t < 16; ++t) {
        const int d = t * 8 + (lane & 3) * 2;
        uint32_t hi, lo;
        packhl(oacc[t][0] * inv0, oacc[t][1] * inv0, hi, lo);
        *(uint32_t*)(ctxh + ob0 + d) = hi;
        *(uint32_t*)(ctxl + ob0 + d) = lo;
        packhl(oacc[t][2] * inv1, oacc[t][3] * inv1, hi, lo);
        *(uint32_t*)(ctxh + ob1 + d) = hi;
        *(uint32_t*)(ctxl + ob1 + d) = lo;
    }
}

// ---------------- launch (dense stream DAG; Wo last) ----------------
extern "C" void kernel_launch(void* const* d_in, const int* in_sizes, int n_in,
                              void* d_out, int out_size) {
    const float* hid   = (const float*)d_in[0];
    const float* ln1g  = (const float*)d_in[1];
    const float* ln1b  = (const float*)d_in[2];
    const float* ln2g  = (const float*)d_in[3];
    const float* ln2b  = (const float*)d_in[4];
    const float* Wqkv  = (const float*)d_in[5];
    const float* bqkv  = (const float*)d_in[6];
    const float* Wo    = (const float*)d_in[7];
    const float* bo    = (const float*)d_in[8];
    const float* Wfc   = (const float*)d_in[9];
    const float* bfc   = (const float*)d_in[10];
    const float* Wproj = (const float*)d_in[11];
    const float* bproj = (const float*)d_in[12];
    float* out = (float*)d_out;

    float *rope;
    bf16 *ln1h, *ln1l, *ctxh, *ctxl;
    hf *ln2h, *ln2l, *fch, *fcl, *wfch, *wprojh;
    bf16 *Qh, *Ql, *Kh, *Kl, *Vh, *Vl;
    bf16 *wqkvh, *wqkvl, *woh, *wol;
    cudaGetSymbolAddress((void**)&rope, g_rope);
    cudaGetSymbolAddress((void**)&ln1h, g_ln1h);
    cudaGetSymbolAddress((void**)&ln1l, g_ln1l);
    cudaGetSymbolAddress((void**)&ln2h, g_ln2h);
    cudaGetSymbolAddress((void**)&ln2l, g_ln2l);
    cudaGetSymbolAddress((void**)&ctxh, g_ctxh);
    cudaGetSymbolAddress((void**)&ctxl, g_ctxl);
    cudaGetSymbolAddress((void**)&fch, g_fch);
    cudaGetSymbolAddress((void**)&fcl, g_fcl);
    cudaGetSymbolAddress((void**)&Qh, g_Qh);
    cudaGetSymbolAddress((void**)&Ql, g_Ql);
    cudaGetSymbolAddress((void**)&Kh, g_Kh);
    cudaGetSymbolAddress((void**)&Kl, g_Kl);
    cudaGetSymbolAddress((void**)&Vh, g_Vh);
    cudaGetSymbolAddress((void**)&Vl, g_Vl);
    cudaGetSymbolAddress((void**)&wqkvh, g_wqkvh);
    cudaGetSymbolAddress((void**)&wqkvl, g_wqkvl);
    cudaGetSymbolAddress((void**)&woh, g_woh);
    cudaGetSymbolAddress((void**)&wol, g_wol);
    cudaGetSymbolAddress((void**)&wfch, g_wfch);
    cudaGetSymbolAddress((void**)&wprojh, g_wprojh);

    cudaFuncSetAttribute(mma_gemm<3>, cudaFuncAttributeMaxDynamicSharedMemorySize, G_SMEM);
    cudaFuncSetAttribute(mma_gemm<4>, cudaFuncAttributeMaxDynamicSharedMemorySize, G_SMEM);
    cudaFuncSetAttribute(mma_gemm_h<1>, cudaFuncAttributeMaxDynamicSharedMemorySize, H_SMEM);
    cudaFuncSetAttribute(mma_gemm_h<4>, cudaFuncAttributeMaxDynamicSharedMemorySize, H_SMEM);
    cudaFuncSetAttribute(attn_mma_kernel, cudaFuncAttributeMaxDynamicSharedMemorySize, A_SMEM);

    static cudaStream_t sB = nullptr, sC = nullptr;
    static cudaEvent_t evRoot = nullptr, evLn = nullptr, evWq = nullptr,
                       evWo = nullptr, evWp = nullptr, evPROJ = nullptr;
    if (!sB) {
        cudaStreamCreateWithFlags(&sB, cudaStreamNonBlocking);
        cudaStreamCreateWithFlags(&sC, cudaStreamNonBlocking);
        cudaEventCreateWithFlags(&evRoot, cudaEventDisableTiming);
        cudaEventCreateWithFlags(&evLn,   cudaEventDisableTiming);
        cudaEventCreateWithFlags(&evWq,   cudaEventDisableTiming);
        cudaEventCreateWithFlags(&evWo,   cudaEventDisableTiming);
        cudaEventCreateWithFlags(&evWp,   cudaEventDisableTiming);
        cudaEventCreateWithFlags(&evPROJ, cudaEventDisableTiming);
    }

    cudaEventRecord(evRoot, 0);
    cudaStreamWaitEvent(sB, evRoot, 0);
    cudaStreamWaitEvent(sC, evRoot, 0);

    // --- stream C: Wqkv (bf16 h/l), Wo (bf16 h/l), Wproj (fp16 hi) ---
    wconv_kernel<<<dim3(3 * HID / 64, HID / 64), 256, 0, sC>>>(Wqkv, wqkvh, wqkvl, HID, 3 * HID);
    cudaEventRecord(evWq, sC);
    wconv_kernel<<<dim3(HID / 64, HID / 64), 256, 0, sC>>>(Wo, woh, wol, HID, HID);
    cudaEventRecord(evWo, sC);
    wconv_h_kernel<<<dim3(HID / 64, FF / 64), 256, 0, sC>>>(Wproj, wprojh, FF, HID);
    cudaEventRecord(evWp, sC);

    // --- stream B: Wfc (fp16 hi), FC gemm, PROJ gemm ---
    wconv_h_kernel<<<dim3(FF / 64, HID / 64), 256, 0, sB>>>(Wfc, wfch, HID, FF);

    // --- origin: ln (+rope table) ---
    ln_kernel<<<NTOK / 2, 512>>>(hid, ln1g, ln1b, ln2g, ln2b, ln1h, ln1l, ln2h, ln2l, rope);
    cudaEventRecord(evLn, 0);

    // stream B: FC = gelu(ln2 @ W_fc + b_fc)  (fp16 2-pass)
    cudaStreamWaitEvent(sB, evLn, 0);
    mma_gemm_h<1><<<16 * (FF / 128), 512, H_SMEM, sB>>>(
        ln2h, ln2l, wfch, bfc, nullptr, nullptr, fch, fcl, FF, HID);
    // stream B: out = fc @ W_proj + b_proj + hid  (fp16 2-pass)
    cudaStreamWaitEvent(sB, evWp, 0);
    mma_gemm_h<4><<<16 * (HID / 128), 512, H_SMEM, sB>>>(
        fch, fcl, wprojh, bproj, hid, out, nullptr, nullptr, HID, FF);
    cudaEventRecord(evPROJ, sB);

    // origin: QKV gemm + fused bias/RoPE/scale/head-transpose (bf16 3-pass)
    cudaStreamWaitEvent(0, evWq, 0);
    mma_gemm<3><<<16 * (3 * HID / 128), 512, G_SMEM>>>(
        ln1h, ln1l, wqkvh, wqkvl, bqkv, nullptr, rope,
        nullptr, Qh, Ql, Kh, Kl, Vh, Vl, 3 * HID, HID);

    // origin: attention (bf16 3-pass)
    attn_mma_kernel<<<dim3(SS / 128, BB * HH), 256, A_SMEM>>>(
        Qh, Ql, Kh, Kl, Vh, Vl, ctxh, ctxl);

    // origin: out += ctx @ W_o + b_o   (bf16 3-pass; joins PROJ + Wo weights)
    cudaStreamWaitEvent(0, evWo, 0);
    cudaStreamWaitEvent(0, evPROJ, 0);
    mma_gemm<4><<<16 * (HID / 128), 512, G_SMEM>>>(
        ctxh, ctxl, woh, wol, bo, out, nullptr,
        out, nullptr, nullptr, nullptr, nullptr, nullptr, nullptr, HID, HID);
}

// round 13
// speedup vs baseline: 1.5680x; 1.1679x over previous
#include <cuda_runtime.h>
#include <cuda_bf16.h>
#include <cuda_fp16.h>
#include <cstdint>

// Problem constants
#define BB 2
#define SS 2048
#define HH 16
#define HD 128
#define HID 2048
#define FF 8192
#define NTOK 4096

typedef __half hf;

// ---------------- scratch (device globals; no allocation allowed) ----------
__device__ float g_rope[SS * 16 * 2];
__device__ hf g_ln1h[(size_t)NTOK * HID];
__device__ hf g_ln1l[(size_t)NTOK * HID];
__device__ hf g_ln2h[(size_t)NTOK * HID];
__device__ hf g_ln2l[(size_t)NTOK * HID];
__device__ hf g_ctxh[(size_t)NTOK * HID];
__device__ hf g_ctxl[(size_t)NTOK * HID];
__device__ hf g_fch[(size_t)NTOK * FF];
__device__ hf g_fcl[(size_t)NTOK * FF];
__device__ hf g_Qh[(size_t)NTOK * HID];
__device__ hf g_Ql[(size_t)NTOK * HID];
__device__ hf g_Kh[(size_t)NTOK * HID];
__device__ hf g_Vh[(size_t)NTOK * HID];
__device__ hf g_wqkvh[(size_t)3 * HID * HID];
__device__ hf g_woh[(size_t)HID * HID];
__device__ hf g_wfch[(size_t)FF * HID];
__device__ hf g_wprojh[(size_t)HID * FF];

// ---------------- helpers ----------------
__device__ __forceinline__ uint32_t smem_u32(const void* p) {
    uint32_t a;
    asm("{ .reg .u64 t; cvta.to.shared.u64 t, %1; cvt.u32.u64 %0, t; }" : "=r"(a) : "l"(p));
    return a;
}
#define CP16(dst, src) \
    asm volatile("cp.async.cg.shared.global [%0], [%1], 16;" :: "r"(dst), "l"(src) : "memory")
#define CP_COMMIT() asm volatile("cp.async.commit_group;" ::: "memory")
#define CP_WAIT1()  asm volatile("cp.async.wait_group 1;" ::: "memory")
#define CP_WAIT0()  asm volatile("cp.async.wait_group 0;" ::: "memory")

__device__ __forceinline__ void ldm_x4(uint32_t* r, uint32_t addr) {
    asm volatile("ldmatrix.sync.aligned.m8n8.x4.shared.b16 {%0,%1,%2,%3}, [%4];"
                 : "=r"(r[0]), "=r"(r[1]), "=r"(r[2]), "=r"(r[3]) : "r"(addr));
}
__device__ __forceinline__ void ldm_x4_t(uint32_t* r, uint32_t addr) {
    asm volatile("ldmatrix.sync.aligned.m8n8.x4.trans.shared.b16 {%0,%1,%2,%3}, [%4];"
                 : "=r"(r[0]), "=r"(r[1]), "=r"(r[2]), "=r"(r[3]) : "r"(addr));
}
__device__ __forceinline__ void mma_f16(float* c, const uint32_t* a, const uint32_t* b) {
    asm volatile("mma.sync.aligned.m16n8k16.row.col.f32.f16.f16.f32 "
                 "{%0,%1,%2,%3},{%4,%5,%6,%7},{%8,%9},{%0,%1,%2,%3};"
                 : "+f"(c[0]), "+f"(c[1]), "+f"(c[2]), "+f"(c[3])
                 : "r"(a[0]), "r"(a[1]), "r"(a[2]), "r"(a[3]), "r"(b[0]), "r"(b[1]));
}
__device__ __forceinline__ void split_hf(float v, hf& h, hf& l) {
    h = __float2half_rn(v);
    l = __float2half_rn(v - __half2float(h));
}
__device__ __forceinline__ void packhl_h(float a, float b, uint32_t& hi, uint32_t& lo) {
    __half2 hv, lv;
    hf h, l;
    split_hf(a, h, l); hv.x = h; lv.x = l;
    split_hf(b, h, l); hv.y = h; lv.y = l;
    hi = *(uint32_t*)&hv;
    lo = *(uint32_t*)&lv;
}
__device__ __forceinline__ uint32_t pack_h(float a, float b) {
    __half2 hv;
    hv.x = __float2half_rn(a);
    hv.y = __float2half_rn(b);
    return *(uint32_t*)&hv;
}
__device__ __forceinline__ float gelu_exact(float v) {
    return 0.5f * v * (1.0f + erff(v * 0.70710678118654752f));
}

// ------- fused double layernorm (2 rows/block) + RoPE table ----------------
__global__ void ln_kernel(const float* __restrict__ x,
                          const float* __restrict__ g1, const float* __restrict__ b1,
                          const float* __restrict__ g2, const float* __restrict__ b2,
                          hf* __restrict__ o1h, hf* __restrict__ o1l,
                          hf* __restrict__ o2h, hf* __restrict__ o2l,
                          float* __restrict__ rtab) {
    __shared__ float redS[16];
    __shared__ float redQ[16];
    const int t = threadIdx.x;
    const int half_ = t >> 8;
    const int tt = t & 255;
    const int row = blockIdx.x * 2 + half_;

    if (blockIdx.x < 64) {
        const int i = blockIdx.x * 512 + t;
        const int s = i >> 4, fi = i & 15;
        const float inv = powf(10000.0f, -(float)fi * (1.0f / 16.0f));
        float sn, cs;
        sincosf((float)s * inv, &sn, &cs);
        rtab[i * 2]     = cs;
        rtab[i * 2 + 1] = sn;
    }

    const float* xr = x + (size_t)row * HID;
    float4 a = *(const float4*)(xr + tt * 8);
    float4 b = *(const float4*)(xr + tt * 8 + 4);
    float s  = a.x + a.y + a.z + a.w + b.x + b.y + b.z + b.w;
    float ss = a.x*a.x + a.y*a.y + a.z*a.z + a.w*a.w
             + b.x*b.x + b.y*b.y + b.z*b.z + b.w*b.w;
    #pragma unroll
    for (int o = 16; o; o >>= 1) {
        s  += __shfl_xor_sync(0xffffffffu, s,  o);
        ss += __shfl_xor_sync(0xffffffffu, ss, o);
    }
    if ((t & 31) == 0) { redS[t >> 5] = s; redQ[t >> 5] = ss; }
    __syncthreads();
    s = 0.f; ss = 0.f;
    #pragma unroll
    for (int i = 0; i < 8; i++) { s += redS[half_ * 8 + i]; ss += redQ[half_ * 8 + i]; }
    const float mu  = s * (1.0f / HID);
    const float var = ss * (1.0f / HID) - mu * mu;
    const float rs  = rsqrtf(var + 1e-5f);

    float vals[8] = {a.x,a.y,a.z,a.w,b.x,b.y,b.z,b.w};
    __align__(16) hf h1[8], l1[8], h2[8], l2[8];
    #pragma unroll
    for (int q = 0; q < 8; q++) {
        const int col = tt * 8 + q;
        const float xn = (vals[q] - mu) * rs;
        split_hf(xn * g1[col] + b1[col], h1[q], l1[q]);
        split_hf(xn * g2[col] + b2[col], h2[q], l2[q]);
    }
    const size_t off = (size_t)row * HID + tt * 8;
    *(uint4*)(o1h + off) = *(uint4*)h1;
    *(uint4*)(o1l + off) = *(uint4*)l1;
    *(uint4*)(o2h + off) = *(uint4*)h2;
    *(uint4*)(o2l + off) = *(uint4*)l2;
}

// ------- weight convert + transpose (fp16 hi): W[K][N] -> Th[N][K] ---------
__global__ void wconv_h_kernel(const float* __restrict__ W, hf* __restrict__ Th,
                               int K, int N) {
    __shared__ float tile[64][65];
    const int n0 = blockIdx.x * 64, k0 = blockIdx.y * 64;
    const int tid = threadIdx.x;
    {
        const int r = tid >> 4, c = (tid & 15) * 4;
        #pragma unroll
        for (int i = 0; i < 4; i++) {
            const float4 v = *(const float4*)(W + (size_t)(k0 + r + 16 * i) * N + n0 + c);
            tile[r + 16 * i][c]     = v.x;
            tile[r + 16 * i][c + 1] = v.y;
            tile[r + 16 * i][c + 2] = v.z;
            tile[r + 16 * i][c + 3] = v.w;
        }
    }
    __syncthreads();
    #pragma unroll
    for (int it = 0; it < 2; ++it) {
        const int idx = tid + it * 256;
        const int n = idx >> 3, kc = (idx & 7) * 8;
        __align__(16) hf h[8];
        #pragma unroll
        for (int j = 0; j < 8; j++)
            h[j] = __float2half_rn(tile[kc + j][n]);
        const size_t o = (size_t)(n0 + n) * K + k0 + kc;
        *(uint4*)(Th + o) = *(uint4*)h;
    }
}

// ------------ fp16-split GEMM (2-pass), CTA 256x128, BK=64, 512 thr --------
// D = Ah*Bh + Al*Bh  (B = fp16-rounded weights)
#define ROWP   72
#define A_ARR  36864u
#define B_ARR  18432u
#define H_STG  (2u * A_ARR + B_ARR)     // 92160
#define H_SMEM (2u * H_STG)             // 184320

// EPI: 1 gelu(+bias)->fp16 h/l | 3 qkv fused | 4 +bias+add1->f32
template <int EPI>
__global__ void __launch_bounds__(512, 1) mma_gemm_h(
    const hf* __restrict__ Ah, const hf* __restrict__ Al,
    const hf* __restrict__ Bh,
    const float* __restrict__ bias,
    const float* __restrict__ add1,
    const float* __restrict__ rtab,
    float* __restrict__ Cf, hf* __restrict__ Ch, hf* __restrict__ Cl,
    hf* __restrict__ Ko, hf* __restrict__ Vo,
    int N, int K) {
    extern __shared__ char sm[];
    const uint32_t smb = smem_u32(sm);
    const int tid = threadIdx.x;
    const int lane = tid & 31;
    const int warp = tid >> 5;
    const int wm = warp >> 2;
    const int wn = warp & 3;

    const int Nt = N >> 7;
    const int pid = blockIdx.x;
    const int mt = (pid / (8 * Nt)) * 8 + (pid & 7);
    const int nt = (pid % (8 * Nt)) >> 3;

    const size_t arow0 = (size_t)mt * 256;
    const size_t brow0 = (size_t)nt * 128;
    const hf* pa_h = Ah + arow0 * K;
    const hf* pa_l = Al + arow0 * K;
    const hf* pb_h = Bh + brow0 * K;
    const int nch = K >> 6;

    const uint32_t aoff = ((wm * 64 + (lane & 15)) * ROWP + (lane >> 4) * 8) * 2;
    const uint32_t boff = ((wn * 32 + (lane & 7) + ((lane >> 4) & 1) * 8) * ROWP
                           + ((lane >> 3) & 1) * 8) * 2;

    float acc[4][4][4];
    #pragma unroll
    for (int m = 0; m < 4; m++)
        #pragma unroll
        for (int n = 0; n < 4; n++)
            #pragma unroll
            for (int q = 0; q < 4; q++) acc[m][n][q] = 0.f;

    auto load_stage = [&](int stg, int k0) {
        const uint32_t sb = smb + (uint32_t)stg * H_STG;
        #pragma unroll
        for (int i = 0; i < 4; ++i) {
            const int id = tid + i * 512;
            const int row = id >> 3, cc = id & 7;
            const uint32_t so = (uint32_t)(row * ROWP + cc * 8) * 2;
            const size_t go = (size_t)row * K + k0 + cc * 8;
            CP16(sb + so,         pa_h + go);
            CP16(sb + A_ARR + so, pa_l + go);
        }
        #pragma unroll
        for (int i = 0; i < 2; ++i) {
            const int id = tid + i * 512;
            const int row = id >> 3, cc = id & 7;
            const uint32_t so = (uint32_t)(row * ROWP + cc * 8) * 2;
            const size_t go = (size_t)row * K + k0 + cc * 8;
            CP16(sb + 2 * A_ARR + so, pb_h + go);
        }
    };

    load_stage(0, 0);
    CP_COMMIT();

    for (int c = 0; c < nch; ++c) {
        CP_WAIT0();
        __syncthreads();
        if (c + 1 < nch) {
            load_stage((c + 1) & 1, (c + 1) << 6);
            CP_COMMIT();
        }
        const uint32_t sb = smb + (uint32_t)(c & 1) * H_STG;
        #pragma unroll
        for (int ks = 0; ks < 4; ++ks) {
            const uint32_t kb = ks * 32;
            uint32_t ah[4][4], bh[2][4];
            #pragma unroll
            for (int i = 0; i < 4; ++i)
                ldm_x4(ah[i], sb + aoff + kb + i * 16 * ROWP * 2);
            #pragma unroll
            for (int t2 = 0; t2 < 2; ++t2)
                ldm_x4(bh[t2], sb + 2 * A_ARR + boff + kb + t2 * 16 * ROWP * 2);
            #pragma unroll
            for (int m = 0; m < 4; ++m)
                #pragma unroll
                for (int n = 0; n < 4; ++n)
                    mma_f16(acc[m][n], ah[m], &bh[n >> 1][(n & 1) * 2]);
            {
                uint32_t al[4][4];
                #pragma unroll
                for (int i = 0; i < 4; ++i)
                    ldm_x4(al[i], sb + A_ARR + aoff + kb + i * 16 * ROWP * 2);
                #pragma unroll
                for (int m = 0; m < 4; ++m)
                    #pragma unroll
                    for (int n = 0; n < 4; ++n)
                        mma_f16(acc[m][n], al[m], &bh[n >> 1][(n & 1) * 2]);
            }
        }
    }

    // ---------------- epilogue ----------------
    const int row_base = mt * 256 + wm * 64;
    const int col_base = nt * 128 + wn * 32;

    if (EPI == 3) {
        // qkv: bias, RoPE (d<32 of q/k), q-scale; q -> hi/lo, k/v -> hi only
        const int hh2 = col_base / 384;
        const int sub0 = col_base % 384;
        const int sect = sub0 >> 7;            // 0=q 1=k 2=v
        const int dbase = sub0 & 127;
        const bool ropeW = (dbase == 0) && (sect < 2);
        const float qsc = (sect == 0) ? 0.08838834764831845f : 1.0f;
        #pragma unroll
        for (int m = 0; m < 4; ++m) {
            const int r0 = row_base + m * 16 + (lane >> 2);
            const int r1 = r0 + 8;
            const int bb2 = r0 >> 11;
            const int s0 = r0 & (SS - 1), s1 = r1 & (SS - 1);
            float v[4][4];
            #pragma unroll
            for (int n = 0; n < 4; ++n) {
                const int cc = col_base + n * 8 + (lane & 3) * 2;
                const float b0 = bias[cc], b1 = bias[cc + 1];
                v[n][0] = acc[m][n][0] + b0; v[n][1] = acc[m][n][1] + b1;
                v[n][2] = acc[m][n][2] + b0; v[n][3] = acc[m][n][3] + b1;
            }
            if (ropeW) {
                float rp[4][4];
                #pragma unroll
                for (int n = 0; n < 4; ++n) {
                    const int dl = n * 8 + (lane & 3) * 2;
                    const bool first = dl < 16;
                    const int np = first ? n + 2 : n - 2;
                    const float sign = first ? -1.0f : 1.0f;
                    const int fi0 = dl & 15, fi1 = (dl + 1) & 15;
                    const float2 c00 = *(const float2*)(rtab + (s0 * 16 + fi0) * 2);
                    const float2 c01 = *(const float2*)(rtab + (s0 * 16 + fi1) * 2);
                    const float2 c10 = *(const float2*)(rtab + (s1 * 16 + fi0) * 2);
                    const float2 c11 = *(const float2*)(rtab + (s1 * 16 + fi1) * 2);
                    rp[n][0] = v[n][0] * c00.x + sign * v[np][0] * c00.y;
                    rp[n][1] = v[n][1] * c01.x + sign * v[np][1] * c01.y;
                    rp[n][2] = v[n][2] * c10.x + sign * v[np][2] * c10.y;
                    rp[n][3] = v[n][3] * c11.x + sign * v[np][3] * c11.y;
                }
                #pragma unroll
                for (int n = 0; n < 4; ++n)
                    #pragma unroll
                    for (int q = 0; q < 4; ++q) v[n][q] = rp[n][q];
            }
            const size_t base0 = (((size_t)bb2 * HH + hh2) * SS + s0) * HD;
            const size_t base1 = (((size_t)bb2 * HH + hh2) * SS + s1) * HD;
            #pragma unroll
            for (int n = 0; n < 4; ++n) {
                const int d = dbase + n * 8 + (lane & 3) * 2;
                if (sect == 0) {
                    uint32_t hi, lo;
                    packhl_h(v[n][0] * qsc, v[n][1] * qsc, hi, lo);
                    *(uint32_t*)(Ch + base0 + d) = hi;
                    *(uint32_t*)(Cl + base0 + d) = lo;
                    packhl_h(v[n][2] * qsc, v[n][3] * qsc, hi, lo);
                    *(uint32_t*)(Ch + base1 + d) = hi;
                    *(uint32_t*)(Cl + base1 + d) = lo;
                } else {
                    hf* Oo = (sect == 1) ? Ko : Vo;
                    *(uint32_t*)(Oo + base0 + d) = pack_h(v[n][0], v[n][1]);
                    *(uint32_t*)(Oo + base1 + d) = pack_h(v[n][2], v[n][3]);
                }
            }
        }
        return;
    }

    #pragma unroll
    for (int m = 0; m < 4; ++m) {
        const int r0 = row_base + m * 16 + (lane >> 2);
        #pragma unroll
        for (int n = 0; n < 4; ++n) {
            const int cc = col_base + n * 8 + (lane & 3) * 2;
            const float b0 = bias[cc], b1 = bias[cc + 1];
            float v0 = acc[m][n][0] + b0, v1 = acc[m][n][1] + b1;
            float v2 = acc[m][n][2] + b0, v3 = acc[m][n][3] + b1;
            const size_t off0 = (size_t)r0 * N + cc;
            const size_t off1 = (size_t)(r0 + 8) * N + cc;
            if (EPI == 1) {
                uint32_t hi, lo;
                packhl_h(gelu_exact(v0), gelu_exact(v1), hi, lo);
                *(uint32_t*)(Ch + off0) = hi;
                *(uint32_t*)(Cl + off0) = lo;
                packhl_h(gelu_exact(v2), gelu_exact(v3), hi, lo);
                *(uint32_t*)(Ch + off1) = hi;
                *(uint32_t*)(Cl + off1) = lo;
            } else {
                const float2 x0 = *(const float2*)(add1 + off0);
                const float2 x1 = *(const float2*)(add1 + off1);
                v0 += x0.x; v1 += x0.y;
                v2 += x1.x; v3 += x1.y;
                *(float2*)(Cf + off0) = make_float2(v0, v1);
                *(float2*)(Cf + off1) = make_float2(v2, v3);
            }
        }
    }
}

// ---------- causal flash attention, fp16 2-pass, BQ=128 --------------------
// Q hi/lo; K,V fp16 hi only.  S = Qh K + Ql K;  O = Ph V + Pl V.
#define AST   136
#define ATILE (64 * AST * 2)
#define AQ_H  0
#define AQ_L  (2 * ATILE)
#define ASTAGE0 (4 * ATILE)
#define ASTG_B  (2 * ATILE)              // Kh, Vh
#define A_SMEM  (4 * ATILE + 2 * ASTG_B) // 139264

__global__ void __launch_bounds__(256, 1) attn_mma_kernel(
    const hf* __restrict__ Qh, const hf* __restrict__ Ql,
    const hf* __restrict__ Kh, const hf* __restrict__ Vh,
    hf* __restrict__ ctxh, hf* __restrict__ ctxl) {
    extern __shared__ char sm[];
    const uint32_t smb = smem_u32(sm);
    const int qt = gridDim.x - 1 - blockIdx.x;
    const int bhid = blockIdx.y;
    const int b = bhid >> 4, h = bhid & 15;
    const int tid = threadIdx.x;
    const int lane = tid & 31;
    const int w = tid >> 5;

    const size_t headbase = (size_t)bhid * SS * HD;

    auto ldq = [&]() {
        const size_t gb = headbase + (size_t)qt * 128 * HD;
        #pragma unroll
        for (int i = 0; i < 8; i++) {
            const int c = tid + i * 256;
            const int row = c >> 4, ch = c & 15;
            const uint32_t so = row * (AST * 2) + ch * 16;
            const size_t go = gb + (size_t)row * HD + ch * 8;
            CP16(smb + AQ_H + so, Qh + go);
            CP16(smb + AQ_L + so, Ql + go);
        }
    };
    auto ldkv = [&](int kt, int stg) {
        const uint32_t sb = smb + ASTAGE0 + (uint32_t)stg * ASTG_B;
        const size_t gb = headbase + (size_t)kt * 64 * HD;
        #pragma unroll
        for (int i = 0; i < 4; i++) {
            const int c = tid + i * 256;
            const int row = c >> 4, ch = c & 15;
            const uint32_t so = row * (AST * 2) + ch * 16;
            const size_t go = gb + (size_t)row * HD + ch * 8;
            CP16(sb + so,         Kh + go);
            CP16(sb + ATILE + so, Vh + go);
        }
    };

    const uint32_t qa_off = ((w * 16 + (lane & 15)) * AST + (lane >> 4) * 8) * 2;
    const int lm = lane >> 3, li = lane & 7;
    const uint32_t kb_off = (((lm >> 1) * 8 + li) * AST + (lm & 1) * 8) * 2;
    const uint32_t vb_off = (((lm & 1) * 8 + li) * AST + (lm >> 1) * 8) * 2;

    float oacc[16][4];
    #pragma unroll
    for (int t = 0; t < 16; t++)
        #pragma unroll
        for (int q = 0; q < 4; q++) oacc[t][q] = 0.f;
    float m0 = -1e30f, m1 = -1e30f, l0 = 0.f, l1 = 0.f;
    const int qrow0 = qt * 128 + w * 16 + (lane >> 2);
    const int qrow1 = qrow0 + 8;
    const int nkt = 2 * qt + 2;

    ldq();
    ldkv(0, 0);
    CP_COMMIT();

    for (int kt = 0; kt < nkt; ++kt) {
        if (kt + 1 < nkt) {
            ldkv(kt + 1, (kt + 1) & 1);
            CP_COMMIT();
            CP_WAIT1();
        } else {
            CP_WAIT0();
        }
        __syncthreads();
        const uint32_t sb = smb + ASTAGE0 + (uint32_t)(kt & 1) * ASTG_B;

        float sacc[8][4];
        #pragma unroll
        for (int j = 0; j < 8; j++)
            #pragma unroll
            for (int q = 0; q < 4; q++) sacc[j][q] = 0.f;

        #pragma unroll
        for (int ks = 0; ks < 8; ++ks) {
            uint32_t ah[4], al[4], kfh[8][2];
            ldm_x4(ah, smb + AQ_H + qa_off + ks * 32);
            ldm_x4(al, smb + AQ_L + qa_off + ks * 32);
            #pragma unroll
            for (int jp = 0; jp < 4; ++jp) {
                uint32_t r[4];
                ldm_x4(r, sb + kb_off + (jp * 16 * AST + ks * 16) * 2);
                kfh[2*jp][0] = r[0]; kfh[2*jp][1] = r[1];
                kfh[2*jp+1][0] = r[2]; kfh[2*jp+1][1] = r[3];
            }
            #pragma unroll
            for (int j = 0; j < 8; ++j) mma_f16(sacc[j], ah, kfh[j]);
            #pragma unroll
            for (int j = 0; j < 8; ++j) mma_f16(sacc[j], al, kfh[j]);
        }

        if (kt >= 2 * qt) {
            #pragma unroll
            for (int j = 0; j < 8; ++j) {
                const int c0 = kt * 64 + j * 8 + (lane & 3) * 2;
                if (c0     > qrow0) sacc[j][0] = -1e30f;
                if (c0 + 1 > qrow0) sacc[j][1] = -1e30f;
                if (c0     > qrow1) sacc[j][2] = -1e30f;
                if (c0 + 1 > qrow1) sacc[j][3] = -1e30f;
            }
        }

        float mx0 = -1e30f, mx1 = -1e30f;
        #pragma unroll
        for (int j = 0; j < 8; ++j) {
            mx0 = fmaxf(mx0, fmaxf(sacc[j][0], sacc[j][1]));
            mx1 = fmaxf(mx1, fmaxf(sacc[j][2], sacc[j][3]));
        }
        #pragma unroll
        for (int o = 1; o < 4; o <<= 1) {
            mx0 = fmaxf(mx0, __shfl_xor_sync(0xffffffffu, mx0, o));
            mx1 = fmaxf(mx1, __shfl_xor_sync(0xffffffffu, mx1, o));
        }
        const float mn0 = fmaxf(m0, mx0), mn1 = fmaxf(m1, mx1);
        const float e0 = __expf(m0 - mn0), e1 = __expf(m1 - mn1);
        m0 = mn0; m1 = mn1;
        float rs0 = 0.f, rs1 = 0.f;
        #pragma unroll
        for (int j = 0; j < 8; ++j) {
            sacc[j][0] = __expf(sacc[j][0] - mn0); rs0 += sacc[j][0];
            sacc[j][1] = __expf(sacc[j][1] - mn0); rs0 += sacc[j][1];
            sacc[j][2] = __expf(sacc[j][2] - mn1); rs1 += sacc[j][2];
            sacc[j][3] = __expf(sacc[j][3] - mn1); rs1 += sacc[j][3];
        }
        #pragma unroll
        for (int o = 1; o < 4; o <<= 1) {
            rs0 += __shfl_xor_sync(0xffffffffu, rs0, o);
            rs1 += __shfl_xor_sync(0xffffffffu, rs1, o);
        }
        l0 = l0 * e0 + rs0;
        l1 = l1 * e1 + rs1;
        #pragma unroll
        for (int t = 0; t < 16; t++) {
            oacc[t][0] *= e0; oacc[t][1] *= e0;
            oacc[t][2] *= e1; oacc[t][3] *= e1;
        }

        #pragma unroll
        for (int c = 0; c < 4; ++c) {
            uint32_t pah[4], pal[4];
            packhl_h(sacc[2*c][0],   sacc[2*c][1],   pah[0], pal[0]);
            packhl_h(sacc[2*c][2],   sacc[2*c][3],   pah[1], pal[1]);
            packhl_h(sacc[2*c+1][0], sacc[2*c+1][1], pah[2], pal[2]);
            packhl_h(sacc[2*c+1][2], sacc[2*c+1][3], pah[3], pal[3]);
            #pragma unroll
            for (int tp = 0; tp < 8; ++tp) {
                uint32_t rvh[4];
                ldm_x4_t(rvh, sb + ATILE + vb_off + (c * 16 * AST + tp * 16) * 2);
                mma_f16(oacc[2*tp],   pah, &rvh[0]);
                mma_f16(oacc[2*tp],   pal, &rvh[0]);
                mma_f16(oacc[2*tp+1], pah, &rvh[2]);
                mma_f16(oacc[2*tp+1], pal, &rvh[2]);
            }
        }
        __syncthreads();
    }

    const float inv0 = 1.0f / l0, inv1 = 1.0f / l1;
    const size_t ob0 = ((size_t)b * SS + qrow0) * HID + h * HD;
    const size_t ob1 = ((size_t)b * SS + qrow1) * HID + h * HD;
    #pragma unroll
    for (int t = 0; t < 16; ++t) {
        const int d = t * 8 + (lane & 3) * 2;
        uint32_t hi, lo;
        packhl_h(oacc[t][0] * inv0, oacc[t][1] * inv0, hi, lo);
        *(uint32_t*)(ctxh + ob0 + d) = hi;
        *(uint32_t*)(ctxl + ob0 + d) = lo;
        packhl_h(oacc[t][2] * inv1, oacc[t][3] * inv1, hi, lo);
        *(uint32_t*)(ctxh + ob1 + d) = hi;
        *(uint32_t*)(ctxl + ob1 + d) = lo;
    }
}

// ---------------- launch (dense stream DAG; Wo last) ----------------
extern "C" void kernel_launch(void* const* d_in, const int* in_sizes, int n_in,
                              void* d_out, int out_size) {
    const float* hid   = (const float*)d_in[0];
    const float* ln1g  = (const float*)d_in[1];
    const float* ln1b  = (const float*)d_in[2];
    const float* ln2g  = (const float*)d_in[3];
    const float* ln2b  = (const float*)d_in[4];
    const float* Wqkv  = (const float*)d_in[5];
    const float* bqkv  = (const float*)d_in[6];
    const float* Wo    = (const float*)d_in[7];
    const float* bo    = (const float*)d_in[8];
    const float* Wfc   = (const float*)d_in[9];
    const float* bfc   = (const float*)d_in[10];
    const float* Wproj = (const float*)d_in[11];
    const float* bproj = (const float*)d_in[12];
    float* out = (float*)d_out;

    float *rope;
    hf *ln1h, *ln1l, *ln2h, *ln2l, *ctxh, *ctxl, *fch, *fcl;
    hf *Qh, *Ql, *Kh, *Vh;
    hf *wqkvh, *woh, *wfch, *wprojh;
    cudaGetSymbolAddress((void**)&rope, g_rope);
    cudaGetSymbolAddress((void**)&ln1h, g_ln1h);
    cudaGetSymbolAddress((void**)&ln1l, g_ln1l);
    cudaGetSymbolAddress((void**)&ln2h, g_ln2h);
    cudaGetSymbolAddress((void**)&ln2l, g_ln2l);
    cudaGetSymbolAddress((void**)&ctxh, g_ctxh);
    cudaGetSymbolAddress((void**)&ctxl, g_ctxl);
    cudaGetSymbolAddress((void**)&fch, g_fch);
    cudaGetSymbolAddress((void**)&fcl, g_fcl);
    cudaGetSymbolAddress((void**)&Qh, g_Qh);
    cudaGetSymbolAddress((void**)&Ql, g_Ql);
    cudaGetSymbolAddress((void**)&Kh, g_Kh);
    cudaGetSymbolAddress((void**)&Vh, g_Vh);
    cudaGetSymbolAddress((void**)&wqkvh, g_wqkvh);
    cudaGetSymbolAddress((void**)&woh, g_woh);
    cudaGetSymbolAddress((void**)&wfch, g_wfch);
    cudaGetSymbolAddress((void**)&wprojh, g_wprojh);

    cudaFuncSetAttribute(mma_gemm_h<1>, cudaFuncAttributeMaxDynamicSharedMemorySize, H_SMEM);
    cudaFuncSetAttribute(mma_gemm_h<3>, cudaFuncAttributeMaxDynamicSharedMemorySize, H_SMEM);
    cudaFuncSetAttribute(mma_gemm_h<4>, cudaFuncAttributeMaxDynamicSharedMemorySize, H_SMEM);
    cudaFuncSetAttribute(attn_mma_kernel, cudaFuncAttributeMaxDynamicSharedMemorySize, A_SMEM);

    static cudaStream_t sB = nullptr, sC = nullptr;
    static cudaEvent_t evRoot = nullptr, evLn = nullptr, evWq = nullptr,
                       evWo = nullptr, evWp = nullptr, evPROJ = nullptr;
    if (!sB) {
        cudaStreamCreateWithFlags(&sB, cudaStreamNonBlocking);
        cudaStreamCreateWithFlags(&sC, cudaStreamNonBlocking);
        cudaEventCreateWithFlags(&evRoot, cudaEventDisableTiming);
        cudaEventCreateWithFlags(&evLn,   cudaEventDisableTiming);
        cudaEventCreateWithFlags(&evWq,   cudaEventDisableTiming);
        cudaEventCreateWithFlags(&evWo,   cudaEventDisableTiming);
        cudaEventCreateWithFlags(&evWp,   cudaEventDisableTiming);
        cudaEventCreateWithFlags(&evPROJ, cudaEventDisableTiming);
    }

    cudaEventRecord(evRoot, 0);
    cudaStreamWaitEvent(sB, evRoot, 0);
    cudaStreamWaitEvent(sC, evRoot, 0);

    // --- stream C: Wqkv, Wo, Wproj conversions (fp16 hi) ---
    wconv_h_kernel<<<dim3(3 * HID / 64, HID / 64), 256, 0, sC>>>(Wqkv, wqkvh, HID, 3 * HID);
    cudaEventRecord(evWq, sC);
    wconv_h_kernel<<<dim3(HID / 64, HID / 64), 256, 0, sC>>>(Wo, woh, HID, HID);
    cudaEventRecord(evWo, sC);
    wconv_h_kernel<<<dim3(HID / 64, FF / 64), 256, 0, sC>>>(Wproj, wprojh, FF, HID);
    cudaEventRecord(evWp, sC);

    // --- stream B: Wfc conversion, FC gemm, PROJ gemm ---
    wconv_h_kernel<<<dim3(FF / 64, HID / 64), 256, 0, sB>>>(Wfc, wfch, HID, FF);

    // --- origin: ln (+rope table) ---
    ln_kernel<<<NTOK / 2, 512>>>(hid, ln1g, ln1b, ln2g, ln2b, ln1h, ln1l, ln2h, ln2l, rope);
    cudaEventRecord(evLn, 0);

    // stream B: FC = gelu(ln2 @ W_fc + b_fc)
    cudaStreamWaitEvent(sB, evLn, 0);
    mma_gemm_h<1><<<16 * (FF / 128), 512, H_SMEM, sB>>>(
        ln2h, ln2l, wfch, bfc, nullptr, nullptr,
        nullptr, fch, fcl, nullptr, nullptr, FF, HID);
    // stream B: out = fc @ W_proj + b_proj + hid
    cudaStreamWaitEvent(sB, evWp, 0);
    mma_gemm_h<4><<<16 * (HID / 128), 512, H_SMEM, sB>>>(
        fch, fcl, wprojh, bproj, hid, nullptr,
        out, nullptr, nullptr, nullptr, nullptr, HID, FF);
    cudaEventRecord(evPROJ, sB);

    // origin: QKV gemm + fused bias/RoPE/scale/head-transpose
    cudaStreamWaitEvent(0, evWq, 0);
    mma_gemm_h<3><<<16 * (3 * HID / 128), 512, H_SMEM>>>(
        ln1h, ln1l, wqkvh, bqkv, nullptr, rope,
        nullptr, Qh, Ql, Kh, Vh, 3 * HID, HID);

    // origin: attention (fp16 2-pass)
    attn_mma_kernel<<<dim3(SS / 128, BB * HH), 256, A_SMEM>>>(
        Qh, Ql, Kh, Vh, ctxh, ctxl);

    // origin: out += ctx @ W_o + b_o
    cudaStreamWaitEvent(0, evWo, 0);
    cudaStreamWaitEvent(0, evPROJ, 0);
    mma_gemm_h<4><<<16 * (HID / 128), 512, H_SMEM>>>(
        ctxh, ctxl, woh, bo, out, nullptr,
        out, nullptr, nullptr, nullptr, nullptr, HID, HID);
}

// round 14
// speedup vs baseline: 2.7578x; 1.7588x over previous
#include <cuda_runtime.h>
#include <cuda_fp16.h>
#include <cstdint>

// Problem constants
#define BB 2
#define SS 2048
#define HH 16
#define HD 128
#define HID 2048
#define FF 8192
#define NTOK 4096

typedef __half hf;

// ---------------- scratch (device globals; no allocation allowed) ----------
__device__ float g_rope[SS * 16 * 2];
__device__ hf g_ln1[(size_t)NTOK * HID];
__device__ hf g_ln2[(size_t)NTOK * HID];
__device__ hf g_ctx[(size_t)NTOK * HID];
__device__ hf g_fc[(size_t)NTOK * FF];
__device__ hf g_Q[(size_t)NTOK * HID];
__device__ hf g_K[(size_t)NTOK * HID];
__device__ hf g_V[(size_t)NTOK * HID];
__device__ hf g_wqkv[(size_t)3 * HID * HID];
__device__ hf g_wo[(size_t)HID * HID];
__device__ hf g_wfc[(size_t)FF * HID];
__device__ hf g_wproj[(size_t)HID * FF];

// ---------------- helpers ----------------
__device__ __forceinline__ uint32_t smem_u32(const void* p) {
    uint32_t a;
    asm("{ .reg .u64 t; cvta.to.shared.u64 t, %1; cvt.u32.u64 %0, t; }" : "=r"(a) : "l"(p));
    return a;
}
#define CP16(dst, src) \
    asm volatile("cp.async.cg.shared.global [%0], [%1], 16;" :: "r"(dst), "l"(src) : "memory")
#define CP_COMMIT() asm volatile("cp.async.commit_group;" ::: "memory")
#define CP_WAIT1()  asm volatile("cp.async.wait_group 1;" ::: "memory")
#define CP_WAIT0()  asm volatile("cp.async.wait_group 0;" ::: "memory")

__device__ __forceinline__ void ldm_x4(uint32_t* r, uint32_t addr) {
    asm volatile("ldmatrix.sync.aligned.m8n8.x4.shared.b16 {%0,%1,%2,%3}, [%4];"
                 : "=r"(r[0]), "=r"(r[1]), "=r"(r[2]), "=r"(r[3]) : "r"(addr));
}
__device__ __forceinline__ void ldm_x4_t(uint32_t* r, uint32_t addr) {
    asm volatile("ldmatrix.sync.aligned.m8n8.x4.trans.shared.b16 {%0,%1,%2,%3}, [%4];"
                 : "=r"(r[0]), "=r"(r[1]), "=r"(r[2]), "=r"(r[3]) : "r"(addr));
}
__device__ __forceinline__ void mma_f16(float* c, const uint32_t* a, const uint32_t* b) {
    asm volatile("mma.sync.aligned.m16n8k16.row.col.f32.f16.f16.f32 "
                 "{%0,%1,%2,%3},{%4,%5,%6,%7},{%8,%9},{%0,%1,%2,%3};"
                 : "+f"(c[0]), "+f"(c[1]), "+f"(c[2]), "+f"(c[3])
                 : "r"(a[0]), "r"(a[1]), "r"(a[2]), "r"(a[3]), "r"(b[0]), "r"(b[1]));
}
__device__ __forceinline__ uint32_t pack_h(float a, float b) {
    __half2 hv;
    hv.x = __float2half_rn(a);
    hv.y = __float2half_rn(b);
    return *(uint32_t*)&hv;
}
__device__ __forceinline__ float gelu_exact(float v) {
    return 0.5f * v * (1.0f + erff(v * 0.70710678118654752f));
}

// ------- fused double layernorm (2 rows/block) + RoPE table ----------------
__global__ void ln_kernel(const float* __restrict__ x,
                          const float* __restrict__ g1, const float* __restrict__ b1,
                          const float* __restrict__ g2, const float* __restrict__ b2,
                          hf* __restrict__ o1, hf* __restrict__ o2,
                          float* __restrict__ rtab) {
    __shared__ float redS[16];
    __shared__ float redQ[16];
    const int t = threadIdx.x;             // 512
    const int half_ = t >> 8;
    const int tt = t & 255;
    const int row = blockIdx.x * 2 + half_;

    if (blockIdx.x < 64) {
        const int i = blockIdx.x * 512 + t;
        const int s = i >> 4, fi = i & 15;
        const float inv = powf(10000.0f, -(float)fi * (1.0f / 16.0f));
        float sn, cs;
        sincosf((float)s * inv, &sn, &cs);
        rtab[i * 2]     = cs;
        rtab[i * 2 + 1] = sn;
    }

    const float* xr = x + (size_t)row * HID;
    float4 a = *(const float4*)(xr + tt * 8);
    float4 b = *(const float4*)(xr + tt * 8 + 4);
    float s  = a.x + a.y + a.z + a.w + b.x + b.y + b.z + b.w;
    float ss = a.x*a.x + a.y*a.y + a.z*a.z + a.w*a.w
             + b.x*b.x + b.y*b.y + b.z*b.z + b.w*b.w;
    #pragma unroll
    for (int o = 16; o; o >>= 1) {
        s  += __shfl_xor_sync(0xffffffffu, s,  o);
        ss += __shfl_xor_sync(0xffffffffu, ss, o);
    }
    if ((t & 31) == 0) { redS[t >> 5] = s; redQ[t >> 5] = ss; }
    __syncthreads();
    s = 0.f; ss = 0.f;
    #pragma unroll
    for (int i = 0; i < 8; i++) { s += redS[half_ * 8 + i]; ss += redQ[half_ * 8 + i]; }
    const float mu  = s * (1.0f / HID);
    const float var = ss * (1.0f / HID) - mu * mu;
    const float rs  = rsqrtf(var + 1e-5f);

    float vals[8] = {a.x,a.y,a.z,a.w,b.x,b.y,b.z,b.w};
    __align__(16) hf h1[8], h2[8];
    #pragma unroll
    for (int q = 0; q < 8; q++) {
        const int col = tt * 8 + q;
        const float xn = (vals[q] - mu) * rs;
        h1[q] = __float2half_rn(xn * g1[col] + b1[col]);
        h2[q] = __float2half_rn(xn * g2[col] + b2[col]);
    }
    const size_t off = (size_t)row * HID + tt * 8;
    *(uint4*)(o1 + off) = *(uint4*)h1;
    *(uint4*)(o2 + off) = *(uint4*)h2;
}

// ------- weight convert + transpose (fp16): W[K][N] -> T[N][K] -------------
__global__ void wconv_h_kernel(const float* __restrict__ W, hf* __restrict__ Th,
                               int K, int N) {
    __shared__ float tile[64][65];
    const int n0 = blockIdx.x * 64, k0 = blockIdx.y * 64;
    const int tid = threadIdx.x;           // 256
    {
        const int r = tid >> 4, c = (tid & 15) * 4;
        #pragma unroll
        for (int i = 0; i < 4; i++) {
            const float4 v = *(const float4*)(W + (size_t)(k0 + r + 16 * i) * N + n0 + c);
            tile[r + 16 * i][c]     = v.x;
            tile[r + 16 * i][c + 1] = v.y;
            tile[r + 16 * i][c + 2] = v.z;
            tile[r + 16 * i][c + 3] = v.w;
        }
    }
    __syncthreads();
    #pragma unroll
    for (int it = 0; it < 2; ++it) {
        const int idx = tid + it * 256;
        const int n = idx >> 3, kc = (idx & 7) * 8;
        __align__(16) hf h[8];
        #pragma unroll
        for (int j = 0; j < 8; j++)
            h[j] = __float2half_rn(tile[kc + j][n]);
        const size_t o = (size_t)(n0 + n) * K + k0 + kc;
        *(uint4*)(Th + o) = *(uint4*)h;
    }
}

// ------------ fp16 1-pass GEMM, CTA 256x128, BK=64, 512 thr ----------------
#define ROWP   72
#define A_ARR  36864u
#define B_ARR  18432u
#define H_STG  (A_ARR + B_ARR)          // 55296
#define H_SMEM (2u * H_STG)             // 110592

// EPI: 1 gelu(+bias)->fp16 | 3 qkv fused | 4 +bias+add1->f32
template <int EPI>
__global__ void __launch_bounds__(512, 1) mma_gemm_h(
    const hf* __restrict__ A, const hf* __restrict__ B,
    const float* __restrict__ bias,
    const float* __restrict__ add1,
    const float* __restrict__ rtab,
    float* __restrict__ Cf, hf* __restrict__ Ch,
    hf* __restrict__ Ko, hf* __restrict__ Vo,
    int N, int K) {
    extern __shared__ char sm[];
    const uint32_t smb = smem_u32(sm);
    const int tid = threadIdx.x;
    const int lane = tid & 31;
    const int warp = tid >> 5;
    const int wm = warp >> 2;          // 4 warps along M (64 rows each)
    const int wn = warp & 3;           // 4 warps along N (32 cols each)

    const int Nt = N >> 7;
    const int pid = blockIdx.x;
    const int mt = (pid / (8 * Nt)) * 8 + (pid & 7);
    const int nt = (pid % (8 * Nt)) >> 3;

    const size_t arow0 = (size_t)mt * 256;
    const size_t brow0 = (size_t)nt * 128;
    const hf* pa = A + arow0 * K;
    const hf* pb = B + brow0 * K;
    const int nch = K >> 6;

    const uint32_t aoff = ((wm * 64 + (lane & 15)) * ROWP + (lane >> 4) * 8) * 2;
    const uint32_t boff = ((wn * 32 + (lane & 7) + ((lane >> 4) & 1) * 8) * ROWP
                           + ((lane >> 3) & 1) * 8) * 2;

    float acc[4][4][4];
    #pragma unroll
    for (int m = 0; m < 4; m++)
        #pragma unroll
        for (int n = 0; n < 4; n++)
            #pragma unroll
            for (int q = 0; q < 4; q++) acc[m][n][q] = 0.f;

    auto load_stage = [&](int stg, int k0) {
        const uint32_t sb = smb + (uint32_t)stg * H_STG;
        #pragma unroll
        for (int i = 0; i < 4; ++i) {       // A: 2048 16B chunks
            const int id = tid + i * 512;
            const int row = id >> 3, cc = id & 7;
            CP16(sb + (uint32_t)(row * ROWP + cc * 8) * 2,
                 pa + (size_t)row * K + k0 + cc * 8);
        }
        #pragma unroll
        for (int i = 0; i < 2; ++i) {       // B: 1024 chunks
            const int id = tid + i * 512;
            const int row = id >> 3, cc = id & 7;
            CP16(sb + A_ARR + (uint32_t)(row * ROWP + cc * 8) * 2,
                 pb + (size_t)row * K + k0 + cc * 8);
        }
    };

    load_stage(0, 0);
    CP_COMMIT();

    for (int c = 0; c < nch; ++c) {
        CP_WAIT0();
        __syncthreads();
        if (c + 1 < nch) {
            load_stage((c + 1) & 1, (c + 1) << 6);
            CP_COMMIT();
        }
        const uint32_t sb = smb + (uint32_t)(c & 1) * H_STG;
        #pragma unroll
        for (int ks = 0; ks < 4; ++ks) {
            const uint32_t kb = ks * 32;
            uint32_t ah[4][4], bh[2][4];
            #pragma unroll
            for (int i = 0; i < 4; ++i)
                ldm_x4(ah[i], sb + aoff + kb + i * 16 * ROWP * 2);
            #pragma unroll
            for (int t2 = 0; t2 < 2; ++t2)
                ldm_x4(bh[t2], sb + A_ARR + boff + kb + t2 * 16 * ROWP * 2);
            #pragma unroll
            for (int m = 0; m < 4; ++m)
                #pragma unroll
                for (int n = 0; n < 4; ++n)
                    mma_f16(acc[m][n], ah[m], &bh[n >> 1][(n & 1) * 2]);
        }
    }

    // ---------------- epilogue ----------------
    const int row_base = mt * 256 + wm * 64;
    const int col_base = nt * 128 + wn * 32;

    if (EPI == 3) {
        // qkv: bias, RoPE (d<32 of q/k), q-scale -> head-major fp16
        const int hh2 = col_base / 384;
        const int sub0 = col_base % 384;
        const int sect = sub0 >> 7;            // 0=q 1=k 2=v
        const int dbase = sub0 & 127;
        const bool ropeW = (dbase == 0) && (sect < 2);
        const float qsc = (sect == 0) ? 0.08838834764831845f : 1.0f;
        hf* Oo = (sect == 0) ? Ch : (sect == 1) ? Ko : Vo;
        #pragma unroll
        for (int m = 0; m < 4; ++m) {
            const int r0 = row_base + m * 16 + (lane >> 2);
            const int r1 = r0 + 8;
            const int bb2 = r0 >> 11;
            const int s0 = r0 & (SS - 1), s1 = r1 & (SS - 1);
            float v[4][4];
            #pragma unroll
            for (int n = 0; n < 4; ++n) {
                const int cc = col_base + n * 8 + (lane & 3) * 2;
                const float b0 = bias[cc], b1 = bias[cc + 1];
                v[n][0] = acc[m][n][0] + b0; v[n][1] = acc[m][n][1] + b1;
                v[n][2] = acc[m][n][2] + b0; v[n][3] = acc[m][n][3] + b1;
            }
            if (ropeW) {
                float rp[4][4];
                #pragma unroll
                for (int n = 0; n < 4; ++n) {
                    const int dl = n * 8 + (lane & 3) * 2;   // 0..30 even
                    const bool first = dl < 16;
                    const int np = first ? n + 2 : n - 2;
                    const float sign = first ? -1.0f : 1.0f;
                    const int fi0 = dl & 15, fi1 = (dl + 1) & 15;
                    const float2 c00 = *(const float2*)(rtab + (s0 * 16 + fi0) * 2);
                    const float2 c01 = *(const float2*)(rtab + (s0 * 16 + fi1) * 2);
                    const float2 c10 = *(const float2*)(rtab + (s1 * 16 + fi0) * 2);
                    const float2 c11 = *(const float2*)(rtab + (s1 * 16 + fi1) * 2);
                    rp[n][0] = v[n][0] * c00.x + sign * v[np][0] * c00.y;
                    rp[n][1] = v[n][1] * c01.x + sign * v[np][1] * c01.y;
                    rp[n][2] = v[n][2] * c10.x + sign * v[np][2] * c10.y;
                    rp[n][3] = v[n][3] * c11.x + sign * v[np][3] * c11.y;
                }
                #pragma unroll
                for (int n = 0; n < 4; ++n)
                    #pragma unroll
                    for (int q = 0; q < 4; ++q) v[n][q] = rp[n][q];
            }
            const size_t base0 = (((size_t)bb2 * HH + hh2) * SS + s0) * HD;
            const size_t base1 = (((size_t)bb2 * HH + hh2) * SS + s1) * HD;
            #pragma unroll
            for (int n = 0; n < 4; ++n) {
                const int d = dbase + n * 8 + (lane & 3) * 2;
                *(uint32_t*)(Oo + base0 + d) = pack_h(v[n][0] * qsc, v[n][1] * qsc);
                *(uint32_t*)(Oo + base1 + d) = pack_h(v[n][2] * qsc, v[n][3] * qsc);
            }
        }
        return;
    }

    #pragma unroll
    for (int m = 0; m < 4; ++m) {
        const int r0 = row_base + m * 16 + (lane >> 2);
        #pragma unroll
        for (int n = 0; n < 4; ++n) {
            const int cc = col_base + n * 8 + (lane & 3) * 2;
            const float b0 = bias[cc], b1 = bias[cc + 1];
            float v0 = acc[m][n][0] + b0, v1 = acc[m][n][1] + b1;
            float v2 = acc[m][n][2] + b0, v3 = acc[m][n][3] + b1;
            const size_t off0 = (size_t)r0 * N + cc;
            const size_t off1 = (size_t)(r0 + 8) * N + cc;
            if (EPI == 1) {
                *(uint32_t*)(Ch + off0) = pack_h(gelu_exact(v0), gelu_exact(v1));
                *(uint32_t*)(Ch + off1) = pack_h(gelu_exact(v2), gelu_exact(v3));
            } else {
                const float2 x0 = *(const float2*)(add1 + off0);
                const float2 x1 = *(const float2*)(add1 + off1);
                v0 += x0.x; v1 += x0.y;
                v2 += x1.x; v3 += x1.y;
                *(float2*)(Cf + off0) = make_float2(v0, v1);
                *(float2*)(Cf + off1) = make_float2(v2, v3);
            }
        }
    }
}

// ---------- causal flash attention, pure fp16, BQ=128 ----------------------
#define AST   136
#define ATILE (64 * AST * 2)
#define AQ_0  0
#define ASTAGE0 (2 * ATILE)              // Q is 128 rows = 2*ATILE
#define ASTG_B  (2 * ATILE)              // K, V
#define A_SMEM  (2 * ATILE + 2 * ASTG_B) // 104448

__global__ void __launch_bounds__(256, 1) attn_mma_kernel(
    const hf* __restrict__ Q, const hf* __restrict__ Kg,
    const hf* __restrict__ Vg,
    hf* __restrict__ ctx) {
    extern __shared__ char sm[];
    const uint32_t smb = smem_u32(sm);
    const int qt = gridDim.x - 1 - blockIdx.x;
    const int bhid = blockIdx.y;
    const int b = bhid >> 4, h = bhid & 15;
    const int tid = threadIdx.x;
    const int lane = tid & 31;
    const int w = tid >> 5;

    const size_t headbase = (size_t)bhid * SS * HD;

    auto ldq = [&]() {
        const size_t gb = headbase + (size_t)qt * 128 * HD;
        #pragma unroll
        for (int i = 0; i < 8; i++) {
            const int c = tid + i * 256;           // 2048 chunks
            const int row = c >> 4, ch = c & 15;
            CP16(smb + AQ_0 + row * (AST * 2) + ch * 16,
                 Q + gb + (size_t)row * HD + ch * 8);
        }
    };
    auto ldkv = [&](int kt, int stg) {
        const uint32_t sb = smb + ASTAGE0 + (uint32_t)stg * ASTG_B;
        const size_t gb = headbase + (size_t)kt * 64 * HD;
        #pragma unroll
        for (int i = 0; i < 4; i++) {
            const int c = tid + i * 256;           // 1024 chunks per array
            const int row = c >> 4, ch = c & 15;
            const uint32_t so = row * (AST * 2) + ch * 16;
            const size_t go = gb + (size_t)row * HD + ch * 8;
            CP16(sb + so,         Kg + go);
            CP16(sb + ATILE + so, Vg + go);
        }
    };

    const uint32_t qa_off = ((w * 16 + (lane & 15)) * AST + (lane >> 4) * 8) * 2;
    const int lm = lane >> 3, li = lane & 7;
    const uint32_t kb_off = (((lm >> 1) * 8 + li) * AST + (lm & 1) * 8) * 2;
    const uint32_t vb_off = (((lm & 1) * 8 + li) * AST + (lm >> 1) * 8) * 2;

    float oacc[16][4];
    #pragma unroll
    for (int t = 0; t < 16; t++)
        #pragma unroll
        for (int q = 0; q < 4; q++) oacc[t][q] = 0.f;
    float m0 = -1e30f, m1 = -1e30f, l0 = 0.f, l1 = 0.f;
    const int qrow0 = qt * 128 + w * 16 + (lane >> 2);
    const int qrow1 = qrow0 + 8;
    const int nkt = 2 * qt + 2;

    ldq();
    ldkv(0, 0);
    CP_COMMIT();

    for (int kt = 0; kt < nkt; ++kt) {
        if (kt + 1 < nkt) {
            ldkv(kt + 1, (kt + 1) & 1);
            CP_COMMIT();
            CP_WAIT1();
        } else {
            CP_WAIT0();
        }
        __syncthreads();
        const uint32_t sb = smb + ASTAGE0 + (uint32_t)(kt & 1) * ASTG_B;

        float sacc[8][4];
        #pragma unroll
        for (int j = 0; j < 8; j++)
            #pragma unroll
            for (int q = 0; q < 4; q++) sacc[j][q] = 0.f;

        #pragma unroll
        for (int ks = 0; ks < 8; ++ks) {
            uint32_t ah[4], kfh[8][2];
            ldm_x4(ah, smb + AQ_0 + qa_off + ks * 32);
            #pragma unroll
            for (int jp = 0; jp < 4; ++jp) {
                uint32_t r[4];
                ldm_x4(r, sb + kb_off + (jp * 16 * AST + ks * 16) * 2);
                kfh[2*jp][0] = r[0]; kfh[2*jp][1] = r[1];
                kfh[2*jp+1][0] = r[2]; kfh[2*jp+1][1] = r[3];
            }
            #pragma unroll
            for (int j = 0; j < 8; ++j) mma_f16(sacc[j], ah, kfh[j]);
        }

        if (kt >= 2 * qt) {
            #pragma unroll
            for (int j = 0; j < 8; ++j) {
                const int c0 = kt * 64 + j * 8 + (lane & 3) * 2;
                if (c0     > qrow0) sacc[j][0] = -1e30f;
                if (c0 + 1 > qrow0) sacc[j][1] = -1e30f;
                if (c0     > qrow1) sacc[j][2] = -1e30f;
                if (c0 + 1 > qrow1) sacc[j][3] = -1e30f;
            }
        }

        float mx0 = -1e30f, mx1 = -1e30f;
        #pragma unroll
        for (int j = 0; j < 8; ++j) {
            mx0 = fmaxf(mx0, fmaxf(sacc[j][0], sacc[j][1]));
            mx1 = fmaxf(mx1, fmaxf(sacc[j][2], sacc[j][3]));
        }
        #pragma unroll
        for (int o = 1; o < 4; o <<= 1) {
            mx0 = fmaxf(mx0, __shfl_xor_sync(0xffffffffu, mx0, o));
            mx1 = fmaxf(mx1, __shfl_xor_sync(0xffffffffu, mx1, o));
        }
        const float mn0 = fmaxf(m0, mx0), mn1 = fmaxf(m1, mx1);
        const float e0 = __expf(m0 - mn0), e1 = __expf(m1 - mn1);
        m0 = mn0; m1 = mn1;
        float rs0 = 0.f, rs1 = 0.f;
        #pragma unroll
        for (int j = 0; j < 8; ++j) {
            sacc[j][0] = __expf(sacc[j][0] - mn0); rs0 += sacc[j][0];
            sacc[j][1] = __expf(sacc[j][1] - mn0); rs0 += sacc[j][1];
            sacc[j][2] = __expf(sacc[j][2] - mn1); rs1 += sacc[j][2];
            sacc[j][3] = __expf(sacc[j][3] - mn1); rs1 += sacc[j][3];
        }
        #pragma unroll
        for (int o = 1; o < 4; o <<= 1) {
            rs0 += __shfl_xor_sync(0xffffffffu, rs0, o);
            rs1 += __shfl_xor_sync(0xffffffffu, rs1, o);
        }
        l0 = l0 * e0 + rs0;
        l1 = l1 * e1 + rs1;
        #pragma unroll
        for (int t = 0; t < 16; t++) {
            oacc[t][0] *= e0; oacc[t][1] *= e0;
            oacc[t][2] *= e1; oacc[t][3] *= e1;
        }

        #pragma unroll
        for (int c = 0; c < 4; ++c) {
            uint32_t pah[4];
            pah[0] = pack_h(sacc[2*c][0],   sacc[2*c][1]);
            pah[1] = pack_h(sacc[2*c][2],   sacc[2*c][3]);
            pah[2] = pack_h(sacc[2*c+1][0], sacc[2*c+1][1]);
            pah[3] = pack_h(sacc[2*c+1][2], sacc[2*c+1][3]);
            #pragma unroll
            for (int tp = 0; tp < 8; ++tp) {
                uint32_t rvh[4];
                ldm_x4_t(rvh, sb + ATILE + vb_off + (c * 16 * AST + tp * 16) * 2);
                mma_f16(oacc[2*tp],   pah, &rvh[0]);
                mma_f16(oacc[2*tp+1], pah, &rvh[2]);
            }
        }
        __syncthreads();
    }

    const float inv0 = 1.0f / l0, inv1 = 1.0f / l1;
    const size_t ob0 = ((size_t)b * SS + qrow0) * HID + h * HD;
    const size_t ob1 = ((size_t)b * SS + qrow1) * HID + h * HD;
    #pragma unroll
    for (int t = 0; t < 16; ++t) {
        const int d = t * 8 + (lane & 3) * 2;
        *(uint32_t*)(ctx + ob0 + d) = pack_h(oacc[t][0] * inv0, oacc[t][1] * inv0);
        *(uint32_t*)(ctx + ob1 + d) = pack_h(oacc[t][2] * inv1, oacc[t][3] * inv1);
    }
}

// ---------------- launch (dense stream DAG; Wo last) ----------------
extern "C" void kernel_launch(void* const* d_in, const int* in_sizes, int n_in,
                              void* d_out, int out_size) {
    const float* hid   = (const float*)d_in[0];
    const float* ln1g  = (const float*)d_in[1];
    const float* ln1b  = (const float*)d_in[2];
    const float* ln2g  = (const float*)d_in[3];
    const float* ln2b  = (const float*)d_in[4];
    const float* Wqkv  = (const float*)d_in[5];
    const float* bqkv  = (const float*)d_in[6];
    const float* Wo    = (const float*)d_in[7];
    const float* bo    = (const float*)d_in[8];
    const float* Wfc   = (const float*)d_in[9];
    const float* bfc   = (const float*)d_in[10];
    const float* Wproj = (const float*)d_in[11];
    const float* bproj = (const float*)d_in[12];
    float* out = (float*)d_out;

    float *rope;
    hf *ln1, *ln2, *ctx, *fc, *Q, *K, *V;
    hf *wqkv, *wo, *wfc, *wproj;
    cudaGetSymbolAddress((void**)&rope, g_rope);
    cudaGetSymbolAddress((void**)&ln1, g_ln1);
    cudaGetSymbolAddress((void**)&ln2, g_ln2);
    cudaGetSymbolAddress((void**)&ctx, g_ctx);
    cudaGetSymbolAddress((void**)&fc, g_fc);
    cudaGetSymbolAddress((void**)&Q, g_Q);
    cudaGetSymbolAddress((void**)&K, g_K);
    cudaGetSymbolAddress((void**)&V, g_V);
    cudaGetSymbolAddress((void**)&wqkv, g_wqkv);
    cudaGetSymbolAddress((void**)&wo, g_wo);
    cudaGetSymbolAddress((void**)&wfc, g_wfc);
    cudaGetSymbolAddress((void**)&wproj, g_wproj);

    cudaFuncSetAttribute(mma_gemm_h<1>, cudaFuncAttributeMaxDynamicSharedMemorySize, H_SMEM);
    cudaFuncSetAttribute(mma_gemm_h<3>, cudaFuncAttributeMaxDynamicSharedMemorySize, H_SMEM);
    cudaFuncSetAttribute(mma_gemm_h<4>, cudaFuncAttributeMaxDynamicSharedMemorySize, H_SMEM);
    cudaFuncSetAttribute(attn_mma_kernel, cudaFuncAttributeMaxDynamicSharedMemorySize, A_SMEM);

    static cudaStream_t sB = nullptr, sC = nullptr;
    static cudaEvent_t evRoot = nullptr, evLn = nullptr, evWq = nullptr,
                       evWo = nullptr, evWp = nullptr, evPROJ = nullptr;
    if (!sB) {
        cudaStreamCreateWithFlags(&sB, cudaStreamNonBlocking);
        cudaStreamCreateWithFlags(&sC, cudaStreamNonBlocking);
        cudaEventCreateWithFlags(&evRoot, cudaEventDisableTiming);
        cudaEventCreateWithFlags(&evLn,   cudaEventDisableTiming);
        cudaEventCreateWithFlags(&evWq,   cudaEventDisableTiming);
        cudaEventCreateWithFlags(&evWo,   cudaEventDisableTiming);
        cudaEventCreateWithFlags(&evWp,   cudaEventDisableTiming);
        cudaEventCreateWithFlags(&evPROJ, cudaEventDisableTiming);
    }

    cudaEventRecord(evRoot, 0);
    cudaStreamWaitEvent(sB, evRoot, 0);
    cudaStreamWaitEvent(sC, evRoot, 0);

    // --- stream C: Wqkv, Wo, Wproj conversions ---
    wconv_h_kernel<<<dim3(3 * HID / 64, HID / 64), 256, 0, sC>>>(Wqkv, wqkv, HID, 3 * HID);
    cudaEventRecord(evWq, sC);
    wconv_h_kernel<<<dim3(HID / 64, HID / 64), 256, 0, sC>>>(Wo, wo, HID, HID);
    cudaEventRecord(evWo, sC);
    wconv_h_kernel<<<dim3(HID / 64, FF / 64), 256, 0, sC>>>(Wproj, wproj, FF, HID);
    cudaEventRecord(evWp, sC);

    // --- stream B: Wfc conversion, FC gemm, PROJ gemm ---
    wconv_h_kernel<<<dim3(FF / 64, HID / 64), 256, 0, sB>>>(Wfc, wfc, HID, FF);

    // --- origin: ln (+rope table) ---
    ln_kernel<<<NTOK / 2, 512>>>(hid, ln1g, ln1b, ln2g, ln2b, ln1, ln2, rope);
    cudaEventRecord(evLn, 0);

    // stream B: FC = gelu(ln2 @ W_fc + b_fc)
    cudaStreamWaitEvent(sB, evLn, 0);
    mma_gemm_h<1><<<16 * (FF / 128), 512, H_SMEM, sB>>>(
        ln2, wfc, bfc, nullptr, nullptr,
        nullptr, fc, nullptr, nullptr, FF, HID);
    // stream B: out = fc @ W_proj + b_proj + hid
    cudaStreamWaitEvent(sB, evWp, 0);
    mma_gemm_h<4><<<16 * (HID / 128), 512, H_SMEM, sB>>>(
        fc, wproj, bproj, hid, nullptr,
        out, nullptr, nullptr, nullptr, HID, FF);
    cudaEventRecord(evPROJ, sB);

    // origin: QKV gemm + fused bias/RoPE/scale/head-transpose
    cudaStreamWaitEvent(0, evWq, 0);
    mma_gemm_h<3><<<16 * (3 * HID / 128), 512, H_SMEM>>>(
        ln1, wqkv, bqkv, nullptr, rope,
        nullptr, Q, K, V, 3 * HID, HID);

    // origin: attention (pure fp16)
    attn_mma_kernel<<<dim3(SS / 128, BB * HH), 256, A_SMEM>>>(Q, K, V, ctx);

    // origin: out += ctx @ W_o + b_o
    cudaStreamWaitEvent(0, evWo, 0);
    cudaStreamWaitEvent(0, evPROJ, 0);
    mma_gemm_h<4><<<16 * (HID / 128), 512, H_SMEM>>>(
        ctx, wo, bo, out, nullptr,
        out, nullptr, nullptr, nullptr, HID, HID);
}